// round 1
// baseline (speedup 1.0000x reference)
#include <cuda_runtime.h>
#include <math.h>

#define BATCH   4
#define T_SEQ   2048
#define EMB     1024
#define NHEADS  16
#define HDIM    64
#define WHALF   256
#define MTOT    (BATCH * T_SEQ)      // 8192

// Scratch (static device globals: allowed; cudaMalloc is not)
__device__ float g_q[BATCH * T_SEQ * EMB];
__device__ float g_k[BATCH * T_SEQ * EMB];
__device__ float g_v[BATCH * T_SEQ * EMB];
__device__ float g_att[BATCH * T_SEQ * EMB];

// ---------------------------------------------------------------------------
// SGEMM 128x128x8, 256 threads, 8x8 microtile. Optional fused interleaved
// rotary epilogue (for Q and K projections).
//   A: [M,K] row-major   B: [K,N] row-major   C: [M,N] row-major
//   asel: -1 -> Aexp, 0 -> g_att
//   csel: -1 -> Cexp, 0/1/2 -> g_q/g_k/g_v
// ---------------------------------------------------------------------------
__global__ __launch_bounds__(256) void gemm_kernel(
    const float* __restrict__ Aexp, const float* __restrict__ B,
    float* __restrict__ Cexp, int asel, int csel,
    int M, int N, int K, int rotary)
{
    const float* A = (asel == 0) ? (const float*)g_att : Aexp;
    float* C;
    if (csel == 0) C = g_q;
    else if (csel == 1) C = g_k;
    else if (csel == 2) C = g_v;
    else C = Cexp;

    __shared__ float As[8][128];   // [kk][m]
    __shared__ float Bs[8][132];   // [kk][n] (+pad, keeps 16B row alignment)

    const int t    = threadIdx.x;
    const int m0   = blockIdx.y * 128;
    const int n0   = blockIdx.x * 128;
    const int tr   = t >> 4;
    const int tc   = t & 15;
    const int row0 = tr * 8;
    const int col0 = tc * 8;

    float acc[8][8];
#pragma unroll
    for (int i = 0; i < 8; i++)
#pragma unroll
        for (int j = 0; j < 8; j++) acc[i][j] = 0.0f;

    const int aRow = t >> 1;          // 0..127
    const int aCol = (t & 1) * 4;     // 0 or 4
    const int bRow = t >> 5;          // 0..7
    const int bCol = (t & 31) * 4;    // 0..124

    const float* Aptr = A + (size_t)(m0 + aRow) * K + aCol;
    const float* Bptr = B + (size_t)bRow * N + n0 + bCol;

    for (int k0 = 0; k0 < K; k0 += 8) {
        float4 av = *(const float4*)(Aptr + k0);
        float4 bv = *(const float4*)(Bptr + (size_t)k0 * N);
        __syncthreads();
        As[aCol + 0][aRow] = av.x;
        As[aCol + 1][aRow] = av.y;
        As[aCol + 2][aRow] = av.z;
        As[aCol + 3][aRow] = av.w;
        *(float4*)&Bs[bRow][bCol] = bv;
        __syncthreads();
#pragma unroll
        for (int kk = 0; kk < 8; kk++) {
            float a[8], bb[8];
            float4 a0 = *(const float4*)&As[kk][row0];
            float4 a1 = *(const float4*)&As[kk][row0 + 4];
            float4 b0 = *(const float4*)&Bs[kk][col0];
            float4 b1 = *(const float4*)&Bs[kk][col0 + 4];
            a[0]=a0.x; a[1]=a0.y; a[2]=a0.z; a[3]=a0.w;
            a[4]=a1.x; a[5]=a1.y; a[6]=a1.z; a[7]=a1.w;
            bb[0]=b0.x; bb[1]=b0.y; bb[2]=b0.z; bb[3]=b0.w;
            bb[4]=b1.x; bb[5]=b1.y; bb[6]=b1.z; bb[7]=b1.w;
#pragma unroll
            for (int i = 0; i < 8; i++)
#pragma unroll
                for (int j = 0; j < 8; j++)
                    acc[i][j] = fmaf(a[i], bb[j], acc[i][j]);
        }
    }

    // Epilogue (+ optional rotary on 4 interleaved pairs per row)
    float invf[4];
    if (rotary) {
        const int d0 = col0 & 63;          // even, <= 56; cols d0..d0+7 within one head
        const int p0 = d0 >> 1;
#pragma unroll
        for (int u = 0; u < 4; u++)
            invf[u] = (float)pow(10000.0, -(double)(p0 + u) / 32.0);
    }

#pragma unroll
    for (int i = 0; i < 8; i++) {
        const int gm = m0 + row0 + i;
        float* crow = C + (size_t)gm * N + n0 + col0;
        if (rotary) {
            const float tp = (float)(gm & (T_SEQ - 1));
#pragma unroll
            for (int u = 0; u < 4; u++) {
                float ang = __fmul_rn(tp, invf[u]);   // matches fp32 pos*inv_freq
                // exact-enough range reduction in double, then accurate fp32 sin/cos
                double da = (double)ang;
                double rr = da - floor(da * 0.15915494309189535) * 6.283185307179586;
                float rf = (float)rr;
                float sv = sinf(rf);
                float cv = cosf(rf);
                float x0 = acc[i][2 * u];
                float x1 = acc[i][2 * u + 1];
                acc[i][2 * u]     = x0 * cv - x1 * sv;
                acc[i][2 * u + 1] = x1 * cv + x0 * sv;
            }
        }
        *(float4*)(crow)     = make_float4(acc[i][0], acc[i][1], acc[i][2], acc[i][3]);
        *(float4*)(crow + 4) = make_float4(acc[i][4], acc[i][5], acc[i][6], acc[i][7]);
    }
}

// ---------------------------------------------------------------------------
// Banded flash attention. Block = (qtile of 64, head, batch), 256 threads.
// Each thread: 4 query rows (sq0..sq0+3) x 4 cols (sk0..sk0+3). The same
// 4x4 mapping is used for the score tile (cols = keys) and the output
// accumulator (cols = head dims), so softmax state (m, l, corr) lives
// entirely in registers.
// ---------------------------------------------------------------------------
__global__ __launch_bounds__(256) void attn_kernel()
{
    const int qt = blockIdx.x;   // 0..31
    const int h  = blockIdx.y;   // 0..15
    const int b  = blockIdx.z;   // 0..3
    const int t  = threadIdx.x;
    const int qbase = qt * 64;

    extern __shared__ float sm[];
    float* sQt = sm;               // [64][65], d-major: sQt[d*65 + q]
    float* sKt = sQt + 64 * 65;    // [64][65], d-major: sKt[d*65 + k]
    float* sV  = sKt + 64 * 65;    // [64][64], k-major: sV[k*64 + d]
    float* sP  = sV  + 64 * 64;    // [64][64]: sP[q*64 + k]

    const size_t qoff = ((size_t)(b * T_SEQ + qbase) * NHEADS + h) * HDIM;
    const float* qptr = g_q + qoff;

    // Load + pre-scale Q tile (transposed)
    for (int i = t; i < 64 * 64; i += 256) {
        int qi = i >> 6, d = i & 63;
        sQt[d * 65 + qi] = qptr[(size_t)qi * EMB + d] * 0.125f;
    }

    const int sq0 = (t >> 4) << 2;   // query row group
    const int sk0 = (t & 15) << 2;   // key col group == dim group for output

    float m_run[4], l_run[4], acc[4][4];
#pragma unroll
    for (int i = 0; i < 4; i++) {
        m_run[i] = -3.0e38f;
        l_run[i] = 0.0f;
#pragma unroll
        for (int j = 0; j < 4; j++) acc[i][j] = 0.0f;
    }

    const int kt_lo = (qt - 4 > 0) ? (qt - 4) : 0;
    const int kt_hi = (qt + 4 < 31) ? (qt + 4) : 31;

    for (int kt = kt_lo; kt <= kt_hi; kt++) {
        const int kbase = kt * 64;
        const size_t koff = ((size_t)(b * T_SEQ + kbase) * NHEADS + h) * HDIM;
        const float* kptr = g_k + koff;
        const float* vptr = g_v + koff;

        __syncthreads();   // prev-tile PV done with sKt/sV/sP
        for (int i = t; i < 64 * 64; i += 256) {
            int ki = i >> 6, d = i & 63;
            sKt[d * 65 + ki] = kptr[(size_t)ki * EMB + d];
            sV[ki * 64 + d]  = vptr[(size_t)ki * EMB + d];
        }
        __syncthreads();

        // ---- scores S = Q K^T (pre-scaled) ----
        float s[4][4];
#pragma unroll
        for (int i = 0; i < 4; i++)
#pragma unroll
            for (int j = 0; j < 4; j++) s[i][j] = 0.0f;

#pragma unroll 8
        for (int kk = 0; kk < 64; kk++) {
            float a0 = sQt[kk * 65 + sq0];
            float a1 = sQt[kk * 65 + sq0 + 1];
            float a2 = sQt[kk * 65 + sq0 + 2];
            float a3 = sQt[kk * 65 + sq0 + 3];
            float b0 = sKt[kk * 65 + sk0];
            float b1 = sKt[kk * 65 + sk0 + 1];
            float b2 = sKt[kk * 65 + sk0 + 2];
            float b3 = sKt[kk * 65 + sk0 + 3];
            s[0][0] = fmaf(a0, b0, s[0][0]); s[0][1] = fmaf(a0, b1, s[0][1]);
            s[0][2] = fmaf(a0, b2, s[0][2]); s[0][3] = fmaf(a0, b3, s[0][3]);
            s[1][0] = fmaf(a1, b0, s[1][0]); s[1][1] = fmaf(a1, b1, s[1][1]);
            s[1][2] = fmaf(a1, b2, s[1][2]); s[1][3] = fmaf(a1, b3, s[1][3]);
            s[2][0] = fmaf(a2, b0, s[2][0]); s[2][1] = fmaf(a2, b1, s[2][1]);
            s[2][2] = fmaf(a2, b2, s[2][2]); s[2][3] = fmaf(a2, b3, s[2][3]);
            s[3][0] = fmaf(a3, b0, s[3][0]); s[3][1] = fmaf(a3, b1, s[3][1]);
            s[3][2] = fmaf(a3, b2, s[3][2]); s[3][3] = fmaf(a3, b3, s[3][3]);
        }

        // ---- band mask ----
#pragma unroll
        for (int i = 0; i < 4; i++)
#pragma unroll
            for (int j = 0; j < 4; j++) {
                int dq = (qbase + sq0 + i) - (kbase + sk0 + j);
                if (dq > WHALF || dq < -WHALF) s[i][j] = -3.0e38f;
            }

        // ---- online softmax update (16-lane row groups) ----
        float mnew[4], corr[4], rs[4];
#pragma unroll
        for (int i = 0; i < 4; i++) {
            float rmax = fmaxf(fmaxf(s[i][0], s[i][1]), fmaxf(s[i][2], s[i][3]));
#pragma unroll
            for (int off = 1; off < 16; off <<= 1)
                rmax = fmaxf(rmax, __shfl_xor_sync(0xffffffffu, rmax, off));
            mnew[i] = fmaxf(m_run[i], rmax);
            corr[i] = __expf(m_run[i] - mnew[i]);
            m_run[i] = mnew[i];
        }
#pragma unroll
        for (int i = 0; i < 4; i++) {
#pragma unroll
            for (int j = 0; j < 4; j++) s[i][j] = __expf(s[i][j] - mnew[i]);
            float r = s[i][0] + s[i][1] + s[i][2] + s[i][3];
#pragma unroll
            for (int off = 1; off < 16; off <<= 1)
                r += __shfl_xor_sync(0xffffffffu, r, off);
            rs[i] = r;
            l_run[i] = l_run[i] * corr[i] + rs[i];
            *(float4*)&sP[(sq0 + i) * 64 + sk0] =
                make_float4(s[i][0], s[i][1], s[i][2], s[i][3]);
        }
        __syncthreads();

        // ---- PV accumulate: acc[i][j] over dims d0 = sk0 ----
#pragma unroll
        for (int i = 0; i < 4; i++)
#pragma unroll
            for (int j = 0; j < 4; j++) acc[i][j] *= corr[i];

#pragma unroll 8
        for (int k = 0; k < 64; k++) {
            float p0 = sP[(sq0 + 0) * 64 + k];
            float p1 = sP[(sq0 + 1) * 64 + k];
            float p2 = sP[(sq0 + 2) * 64 + k];
            float p3 = sP[(sq0 + 3) * 64 + k];
            float4 v = *(const float4*)&sV[k * 64 + sk0];
            acc[0][0] = fmaf(p0, v.x, acc[0][0]); acc[0][1] = fmaf(p0, v.y, acc[0][1]);
            acc[0][2] = fmaf(p0, v.z, acc[0][2]); acc[0][3] = fmaf(p0, v.w, acc[0][3]);
            acc[1][0] = fmaf(p1, v.x, acc[1][0]); acc[1][1] = fmaf(p1, v.y, acc[1][1]);
            acc[1][2] = fmaf(p1, v.z, acc[1][2]); acc[1][3] = fmaf(p1, v.w, acc[1][3]);
            acc[2][0] = fmaf(p2, v.x, acc[2][0]); acc[2][1] = fmaf(p2, v.y, acc[2][1]);
            acc[2][2] = fmaf(p2, v.z, acc[2][2]); acc[2][3] = fmaf(p2, v.w, acc[2][3]);
            acc[3][0] = fmaf(p3, v.x, acc[3][0]); acc[3][1] = fmaf(p3, v.y, acc[3][1]);
            acc[3][2] = fmaf(p3, v.z, acc[3][2]); acc[3][3] = fmaf(p3, v.w, acc[3][3]);
        }
    }

    // ---- finalize ----
#pragma unroll
    for (int i = 0; i < 4; i++) {
        float inv_l = 1.0f / l_run[i];
        size_t ooff = ((size_t)(b * T_SEQ + qbase + sq0 + i) * NHEADS + h) * HDIM + sk0;
        *(float4*)&g_att[ooff] = make_float4(acc[i][0] * inv_l, acc[i][1] * inv_l,
                                             acc[i][2] * inv_l, acc[i][3] * inv_l);
    }
}

// ---------------------------------------------------------------------------
// Launch
// ---------------------------------------------------------------------------
extern "C" void kernel_launch(void* const* d_in, const int* in_sizes, int n_in,
                              void* d_out, int out_size)
{
    const float* xq  = (const float*)d_in[0];
    const float* xkv = (const float*)d_in[1];
    const float* Wq  = (const float*)d_in[2];
    const float* Wk  = (const float*)d_in[3];
    const float* Wv  = (const float*)d_in[4];
    const float* Wo  = (const float*)d_in[5];
    float* out = (float*)d_out;

    dim3 ggrid(EMB / 128, MTOT / 128);   // (8, 64)

    gemm_kernel<<<ggrid, 256>>>(xq,  Wq, nullptr, -1, 0, MTOT, EMB, EMB, 1);
    gemm_kernel<<<ggrid, 256>>>(xkv, Wk, nullptr, -1, 1, MTOT, EMB, EMB, 1);
    gemm_kernel<<<ggrid, 256>>>(xkv, Wv, nullptr, -1, 2, MTOT, EMB, EMB, 0);

    const int attn_smem = (64 * 65 * 2 + 64 * 64 * 2) * (int)sizeof(float); // 66048 B
    cudaFuncSetAttribute(attn_kernel, cudaFuncAttributeMaxDynamicSharedMemorySize,
                         attn_smem);
    attn_kernel<<<dim3(T_SEQ / 64, NHEADS, BATCH), 256, attn_smem>>>();

    gemm_kernel<<<ggrid, 256>>>(nullptr, Wo, out, 0, -1, MTOT, EMB, EMB, 0);
}

// round 3
// speedup vs baseline: 1.6163x; 1.6163x over previous
#include <cuda_runtime.h>
#include <cuda_bf16.h>
#include <math.h>
#include <stdint.h>

#define BATCH   4
#define T_SEQ   2048
#define EMB     1024
#define NHEADS  16
#define HDIM    64
#define WHALF   256
#define MTOT    (BATCH * T_SEQ)      // 8192
#define K3      3072                 // 3x split-bf16 K
#define BK      32
#define NCH     (K3 / BK)            // 96
#define AROWB   80                   // padded row: 32 bf16 (64B) + 16B pad
#define ASTG    (128 * AROWB)        // 10240 B per operand per stage
#define STG     (2 * ASTG)           // 20480 B per stage
#define NSTAGE  3

// ---------------------------------------------------------------------------
// Scratch (static device globals; cudaMalloc forbidden)
// ---------------------------------------------------------------------------
__device__ float g_q[MTOT * EMB];
__device__ float g_k[MTOT * EMB];
__device__ float g_v[MTOT * EMB];
__device__ __nv_bfloat16 a_q [(size_t)MTOT * K3];
__device__ __nv_bfloat16 a_kv[(size_t)MTOT * K3];
__device__ __nv_bfloat16 a_at[(size_t)MTOT * K3];
__device__ __nv_bfloat16 w_q[EMB * K3];
__device__ __nv_bfloat16 w_k[EMB * K3];
__device__ __nv_bfloat16 w_v[EMB * K3];
__device__ __nv_bfloat16 w_o[EMB * K3];
__device__ float g_invf[32];

// ---------------------------------------------------------------------------
// PTX helpers (sm_103 base ISA only — no tcgen05!)
// ---------------------------------------------------------------------------
__device__ __forceinline__ uint32_t smem_u32(const void* p) {
    uint32_t a;
    asm("{ .reg .u64 t; cvta.to.shared.u64 t, %1; cvt.u32.u64 %0, t; }"
        : "=r"(a) : "l"(p));
    return a;
}
__device__ __forceinline__ void cp16(uint32_t dst, const void* src) {
    asm volatile("cp.async.cg.shared.global [%0], [%1], 16;"
                 :: "r"(dst), "l"(src) : "memory");
}
__device__ __forceinline__ void cp_commit() {
    asm volatile("cp.async.commit_group;" ::: "memory");
}
__device__ __forceinline__ void ldsm4(uint32_t& r0, uint32_t& r1,
                                      uint32_t& r2, uint32_t& r3, uint32_t addr) {
    asm volatile("ldmatrix.sync.aligned.m8n8.x4.shared.b16 {%0,%1,%2,%3}, [%4];"
                 : "=r"(r0), "=r"(r1), "=r"(r2), "=r"(r3) : "r"(addr));
}
__device__ __forceinline__ void mma16816(float* c, uint32_t a0, uint32_t a1,
                                         uint32_t a2, uint32_t a3,
                                         uint32_t b0, uint32_t b1) {
    asm volatile(
        "mma.sync.aligned.m16n8k16.row.col.f32.bf16.bf16.f32 "
        "{%0,%1,%2,%3}, {%4,%5,%6,%7}, {%8,%9}, {%0,%1,%2,%3};"
        : "+f"(c[0]), "+f"(c[1]), "+f"(c[2]), "+f"(c[3])
        : "r"(a0), "r"(a1), "r"(a2), "r"(a3), "r"(b0), "r"(b1));
}
__device__ __forceinline__ uint32_t pk_bf2(__nv_bfloat16 a, __nv_bfloat16 b) {
    return (uint32_t)__bfloat16_as_ushort(a) |
           ((uint32_t)__bfloat16_as_ushort(b) << 16);
}

// ---------------------------------------------------------------------------
// Conversion kernels
// ---------------------------------------------------------------------------
__global__ void init_invf_kernel() {
    int p = threadIdx.x;
    if (p < 32) g_invf[p] = (float)pow(10000.0, -(double)p / 32.0);
}

// inputs [8192,1024] fp32 -> A' bf16 [8192,3072] = [hi | lo | hi]
__global__ __launch_bounds__(256) void conv_in_kernel(const float* __restrict__ X,
                                                      int which) {
    __nv_bfloat16* A = which ? a_kv : a_q;
    for (size_t i = (size_t)blockIdx.x * blockDim.x + threadIdx.x;
         i < (size_t)MTOT * EMB; i += (size_t)gridDim.x * blockDim.x) {
        size_t m = i >> 10;
        int k = (int)(i & 1023);
        float x = X[i];
        __nv_bfloat16 h = __float2bfloat16(x);
        __nv_bfloat16 l = __float2bfloat16(x - __bfloat162float(h));
        __nv_bfloat16* row = A + m * K3;
        row[k] = h; row[1024 + k] = l; row[2048 + k] = h;
    }
}

// W [1024 K,1024 N] fp32 -> W' bf16 [1024 N, 3072] = [hi | hi | lo] (transposed)
__global__ void conv_w_kernel(const float* __restrict__ W, int which) {
    __nv_bfloat16* O = (which == 0) ? w_q : (which == 1) ? w_k
                       : (which == 2) ? w_v : w_o;
    __shared__ float tile[32][33];
    int tx = threadIdx.x, ty = threadIdx.y;
    int n_in = blockIdx.x * 32 + tx;
    int k_in = blockIdx.y * 32 + ty;
    tile[ty][tx] = W[(size_t)k_in * EMB + n_in];
    __syncthreads();
    int n = blockIdx.x * 32 + ty;
    int k = blockIdx.y * 32 + tx;
    float x = tile[tx][ty];
    __nv_bfloat16 h = __float2bfloat16(x);
    __nv_bfloat16 l = __float2bfloat16(x - __bfloat162float(h));
    __nv_bfloat16* row = O + (size_t)n * K3;
    row[k] = h; row[1024 + k] = h; row[2048 + k] = l;
}

// ---------------------------------------------------------------------------
// mma.sync bf16 GEMM: D[M,N] = A'[M,K3] * W'[N,K3]^T
// CTA tile 128x128, 8 warps (2x4 -> 64x32 warp tiles), BK=32, 3-stage cp.async.
// Epilogue: fp32 store (+ fused rotary for Q/K).
// ---------------------------------------------------------------------------
__global__ __launch_bounds__(256) void mma_gemm(float* __restrict__ Cexp,
                                                int asel, int bsel, int csel,
                                                int rotary) {
    const __nv_bfloat16* Ag = (asel == 0) ? a_q : (asel == 1) ? a_kv : a_at;
    const __nv_bfloat16* Bg = (bsel == 0) ? w_q : (bsel == 1) ? w_k
                              : (bsel == 2) ? w_v : w_o;
    float* C = (csel == 0) ? g_q : (csel == 1) ? g_k : (csel == 2) ? g_v : Cexp;

    extern __shared__ char smraw[];
    const uint32_t sb = smem_u32(smraw);
    const int t = threadIdx.x;
    const int wid = t >> 5, lane = t & 31;
    const int m0 = blockIdx.y * 128, n0 = blockIdx.x * 128;
    const int wm0 = (wid & 1) * 64;     // warp M offset in tile
    const int wn0 = (wid >> 1) * 32;    // warp N offset in tile

    const char* Ab = (const char*)(Ag + (size_t)m0 * K3);
    const char* Bb = (const char*)(Bg + (size_t)n0 * K3);

    // thread's two (row,seg) load slots: idx = 2t, 2t+1 over row*4+seg
    const int r0i = (2 * t) >> 2, s0i = (2 * t) & 3;
    const int r1i = (2 * t + 1) >> 2, s1i = (2 * t + 1) & 3;

#define LOAD_CHUNK(c)                                                          \
    do {                                                                       \
        uint32_t _sa = sb + ((c) % NSTAGE) * STG;                              \
        uint32_t _sb2 = _sa + ASTG;                                            \
        size_t _g0 = (size_t)r0i * (K3 * 2) + (size_t)(c) * 64 + s0i * 16;     \
        size_t _g1 = (size_t)r1i * (K3 * 2) + (size_t)(c) * 64 + s1i * 16;     \
        cp16(_sa + r0i * AROWB + s0i * 16, Ab + _g0);                          \
        cp16(_sa + r1i * AROWB + s1i * 16, Ab + _g1);                          \
        cp16(_sb2 + r0i * AROWB + s0i * 16, Bb + _g0);                         \
        cp16(_sb2 + r1i * AROWB + s1i * 16, Bb + _g1);                         \
        cp_commit();                                                           \
    } while (0)

    float acc[4][4][4];
#pragma unroll
    for (int i = 0; i < 4; i++)
#pragma unroll
        for (int j = 0; j < 4; j++)
#pragma unroll
            for (int u = 0; u < 4; u++) acc[i][j][u] = 0.0f;

    LOAD_CHUNK(0); LOAD_CHUNK(1); LOAD_CHUNK(2);

    // ldmatrix lane address components
    const int lq = lane >> 3, lr = lane & 7;
    const int a_row = (lq & 1) * 8 + lr;          // + i*16 + wm0
    const int a_cb  = (lq >> 1) * 16;             // + ks*32
    const int b_row = (lq >> 1) * 8 + lr;         // + jp*16 + wn0
    const int b_cb  = (lq & 1) * 16;              // + ks*32

    for (int c = 0; c < NCH; c++) {
        int pend = NCH - 1 - c; if (pend > 2) pend = 2;
        if (pend == 2)      asm volatile("cp.async.wait_group 2;" ::: "memory");
        else if (pend == 1) asm volatile("cp.async.wait_group 1;" ::: "memory");
        else                asm volatile("cp.async.wait_group 0;" ::: "memory");
        __syncthreads();

        const uint32_t sa  = sb + (c % NSTAGE) * STG;
        const uint32_t sb2 = sa + ASTG;

#pragma unroll
        for (int ks = 0; ks < 2; ks++) {
            uint32_t af[4][4], bf[2][4];
#pragma unroll
            for (int i = 0; i < 4; i++)
                ldsm4(af[i][0], af[i][1], af[i][2], af[i][3],
                      sa + (uint32_t)((wm0 + i * 16 + a_row) * AROWB
                                      + ks * 32 + a_cb));
#pragma unroll
            for (int jp = 0; jp < 2; jp++)
                ldsm4(bf[jp][0], bf[jp][1], bf[jp][2], bf[jp][3],
                      sb2 + (uint32_t)((wn0 + jp * 16 + b_row) * AROWB
                                       + ks * 32 + b_cb));
#pragma unroll
            for (int i = 0; i < 4; i++)
#pragma unroll
                for (int j = 0; j < 4; j++)
                    mma16816(acc[i][j], af[i][0], af[i][1], af[i][2], af[i][3],
                             bf[j >> 1][(j & 1) * 2], bf[j >> 1][(j & 1) * 2 + 1]);
        }
        __syncthreads();
        if (c + 3 < NCH) LOAD_CHUNK(c + 3);
    }

    // ---- epilogue: each thread owns rows (m, m+8) x col pairs per tile ----
    const int mrow = lane >> 2;            // 0..7
    const int ncol = (lane & 3) * 2;       // even
#pragma unroll
    for (int i = 0; i < 4; i++) {
        const int gmA = m0 + wm0 + i * 16 + mrow;
        const int gmB = gmA + 8;
        const float tpA = (float)(gmA & (T_SEQ - 1));
        const float tpB = (float)(gmB & (T_SEQ - 1));
#pragma unroll
        for (int j = 0; j < 4; j++) {
            const int gc = n0 + wn0 + j * 8 + ncol;
            float x0 = acc[i][j][0], x1 = acc[i][j][1];
            float y0 = acc[i][j][2], y1 = acc[i][j][3];
            if (rotary) {
                const int p = (gc & 63) >> 1;
                const float f = g_invf[p];
                float angA = __fmul_rn(tpA, f);
                float angB = __fmul_rn(tpB, f);
                double dA = (double)angA;
                double rA = dA - floor(dA * 0.15915494309189535) * 6.283185307179586;
                double dB = (double)angB;
                double rB = dB - floor(dB * 0.15915494309189535) * 6.283185307179586;
                float sA = sinf((float)rA), cA = cosf((float)rA);
                float sB = sinf((float)rB), cB = cosf((float)rB);
                float t0 = x0 * cA - x1 * sA;
                float t1 = x1 * cA + x0 * sA;
                float u0 = y0 * cB - y1 * sB;
                float u1 = y1 * cB + y0 * sB;
                x0 = t0; x1 = t1; y0 = u0; y1 = u1;
            }
            *(float2*)(C + (size_t)gmA * EMB + gc) = make_float2(x0, x1);
            *(float2*)(C + (size_t)gmB * EMB + gc) = make_float2(y0, y1);
        }
    }
#undef LOAD_CHUNK
}

// ---------------------------------------------------------------------------
// Banded flash attention (fp32 SIMT), writes bf16 split A' for the O-GEMM.
// ---------------------------------------------------------------------------
__global__ __launch_bounds__(256) void attn_kernel() {
    const int qt = blockIdx.x;
    const int h  = blockIdx.y;
    const int b  = blockIdx.z;
    const int t  = threadIdx.x;
    const int qbase = qt * 64;

    extern __shared__ float sm[];
    float* sQt = sm;
    float* sKt = sQt + 64 * 65;
    float* sV  = sKt + 64 * 65;
    float* sP  = sV  + 64 * 64;

    const size_t qoff = ((size_t)(b * T_SEQ + qbase) * NHEADS + h) * HDIM;
    const float* qptr = g_q + qoff;

    for (int i = t; i < 64 * 64; i += 256) {
        int qi = i >> 6, d = i & 63;
        sQt[d * 65 + qi] = qptr[(size_t)qi * EMB + d] * 0.125f;
    }

    const int sq0 = (t >> 4) << 2;
    const int sk0 = (t & 15) << 2;

    float m_run[4], l_run[4], acc[4][4];
#pragma unroll
    for (int i = 0; i < 4; i++) {
        m_run[i] = -3.0e38f;
        l_run[i] = 0.0f;
#pragma unroll
        for (int j = 0; j < 4; j++) acc[i][j] = 0.0f;
    }

    const int kt_lo = (qt - 4 > 0) ? (qt - 4) : 0;
    const int kt_hi = (qt + 4 < 31) ? (qt + 4) : 31;

    for (int kt = kt_lo; kt <= kt_hi; kt++) {
        const int kbase = kt * 64;
        const size_t koff = ((size_t)(b * T_SEQ + kbase) * NHEADS + h) * HDIM;
        const float* kptr = g_k + koff;
        const float* vptr = g_v + koff;

        __syncthreads();
        for (int i = t; i < 64 * 64; i += 256) {
            int ki = i >> 6, d = i & 63;
            sKt[d * 65 + ki] = kptr[(size_t)ki * EMB + d];
            sV[ki * 64 + d]  = vptr[(size_t)ki * EMB + d];
        }
        __syncthreads();

        float s[4][4];
#pragma unroll
        for (int i = 0; i < 4; i++)
#pragma unroll
            for (int j = 0; j < 4; j++) s[i][j] = 0.0f;

#pragma unroll 8
        for (int kk = 0; kk < 64; kk++) {
            float a0 = sQt[kk * 65 + sq0];
            float a1 = sQt[kk * 65 + sq0 + 1];
            float a2 = sQt[kk * 65 + sq0 + 2];
            float a3 = sQt[kk * 65 + sq0 + 3];
            float b0 = sKt[kk * 65 + sk0];
            float b1 = sKt[kk * 65 + sk0 + 1];
            float b2 = sKt[kk * 65 + sk0 + 2];
            float b3 = sKt[kk * 65 + sk0 + 3];
            s[0][0] = fmaf(a0, b0, s[0][0]); s[0][1] = fmaf(a0, b1, s[0][1]);
            s[0][2] = fmaf(a0, b2, s[0][2]); s[0][3] = fmaf(a0, b3, s[0][3]);
            s[1][0] = fmaf(a1, b0, s[1][0]); s[1][1] = fmaf(a1, b1, s[1][1]);
            s[1][2] = fmaf(a1, b2, s[1][2]); s[1][3] = fmaf(a1, b3, s[1][3]);
            s[2][0] = fmaf(a2, b0, s[2][0]); s[2][1] = fmaf(a2, b1, s[2][1]);
            s[2][2] = fmaf(a2, b2, s[2][2]); s[2][3] = fmaf(a2, b3, s[2][3]);
            s[3][0] = fmaf(a3, b0, s[3][0]); s[3][1] = fmaf(a3, b1, s[3][1]);
            s[3][2] = fmaf(a3, b2, s[3][2]); s[3][3] = fmaf(a3, b3, s[3][3]);
        }

#pragma unroll
        for (int i = 0; i < 4; i++)
#pragma unroll
            for (int j = 0; j < 4; j++) {
                int dq = (qbase + sq0 + i) - (kbase + sk0 + j);
                if (dq > WHALF || dq < -WHALF) s[i][j] = -3.0e38f;
            }

        float mnew[4], corr[4];
#pragma unroll
        for (int i = 0; i < 4; i++) {
            float rmax = fmaxf(fmaxf(s[i][0], s[i][1]), fmaxf(s[i][2], s[i][3]));
#pragma unroll
            for (int off = 1; off < 16; off <<= 1)
                rmax = fmaxf(rmax, __shfl_xor_sync(0xffffffffu, rmax, off));
            mnew[i] = fmaxf(m_run[i], rmax);
            corr[i] = __expf(m_run[i] - mnew[i]);
            m_run[i] = mnew[i];
        }
#pragma unroll
        for (int i = 0; i < 4; i++) {
#pragma unroll
            for (int j = 0; j < 4; j++) s[i][j] = __expf(s[i][j] - mnew[i]);
            float r = s[i][0] + s[i][1] + s[i][2] + s[i][3];
#pragma unroll
            for (int off = 1; off < 16; off <<= 1)
                r += __shfl_xor_sync(0xffffffffu, r, off);
            l_run[i] = l_run[i] * corr[i] + r;
            *(float4*)&sP[(sq0 + i) * 64 + sk0] =
                make_float4(s[i][0], s[i][1], s[i][2], s[i][3]);
        }
        __syncthreads();

#pragma unroll
        for (int i = 0; i < 4; i++)
#pragma unroll
            for (int j = 0; j < 4; j++) acc[i][j] *= corr[i];

#pragma unroll 8
        for (int k = 0; k < 64; k++) {
            float p0 = sP[(sq0 + 0) * 64 + k];
            float p1 = sP[(sq0 + 1) * 64 + k];
            float p2 = sP[(sq0 + 2) * 64 + k];
            float p3 = sP[(sq0 + 3) * 64 + k];
            float4 v = *(const float4*)&sV[k * 64 + sk0];
            acc[0][0] = fmaf(p0, v.x, acc[0][0]); acc[0][1] = fmaf(p0, v.y, acc[0][1]);
            acc[0][2] = fmaf(p0, v.z, acc[0][2]); acc[0][3] = fmaf(p0, v.w, acc[0][3]);
            acc[1][0] = fmaf(p1, v.x, acc[1][0]); acc[1][1] = fmaf(p1, v.y, acc[1][1]);
            acc[1][2] = fmaf(p1, v.z, acc[1][2]); acc[1][3] = fmaf(p1, v.w, acc[1][3]);
            acc[2][0] = fmaf(p2, v.x, acc[2][0]); acc[2][1] = fmaf(p2, v.y, acc[2][1]);
            acc[2][2] = fmaf(p2, v.z, acc[2][2]); acc[2][3] = fmaf(p2, v.w, acc[2][3]);
            acc[3][0] = fmaf(p3, v.x, acc[3][0]); acc[3][1] = fmaf(p3, v.y, acc[3][1]);
            acc[3][2] = fmaf(p3, v.z, acc[3][2]); acc[3][3] = fmaf(p3, v.w, acc[3][3]);
        }
    }

    // ---- finalize: write bf16 split [hi | lo | hi] rows of a_at ----
#pragma unroll
    for (int i = 0; i < 4; i++) {
        float inv_l = 1.0f / l_run[i];
        size_t m = (size_t)(b * T_SEQ + qbase + sq0 + i);
        int n = h * HDIM + sk0;
        __nv_bfloat16* dst = a_at + m * (size_t)K3;
        uint32_t hp[2], lp[2];
#pragma unroll
        for (int j2 = 0; j2 < 2; j2++) {
            float x0 = acc[i][2 * j2]     * inv_l;
            float x1 = acc[i][2 * j2 + 1] * inv_l;
            __nv_bfloat16 h0 = __float2bfloat16(x0);
            __nv_bfloat16 h1 = __float2bfloat16(x1);
            __nv_bfloat16 l0 = __float2bfloat16(x0 - __bfloat162float(h0));
            __nv_bfloat16 l1 = __float2bfloat16(x1 - __bfloat162float(h1));
            hp[j2] = pk_bf2(h0, h1);
            lp[j2] = pk_bf2(l0, l1);
        }
        *(uint2*)(dst + n)        = make_uint2(hp[0], hp[1]);
        *(uint2*)(dst + 1024 + n) = make_uint2(lp[0], lp[1]);
        *(uint2*)(dst + 2048 + n) = make_uint2(hp[0], hp[1]);
    }
}

// ---------------------------------------------------------------------------
// Launch
// ---------------------------------------------------------------------------
extern "C" void kernel_launch(void* const* d_in, const int* in_sizes, int n_in,
                              void* d_out, int out_size)
{
    const float* xq  = (const float*)d_in[0];
    const float* xkv = (const float*)d_in[1];
    const float* Wq  = (const float*)d_in[2];
    const float* Wk  = (const float*)d_in[3];
    const float* Wv  = (const float*)d_in[4];
    const float* Wo  = (const float*)d_in[5];
    float* out = (float*)d_out;

    init_invf_kernel<<<1, 32>>>();
    conv_in_kernel<<<4096, 256>>>(xq, 0);
    conv_in_kernel<<<4096, 256>>>(xkv, 1);
    dim3 wtb(32, 32);
    conv_w_kernel<<<dim3(32, 32), wtb>>>(Wq, 0);
    conv_w_kernel<<<dim3(32, 32), wtb>>>(Wk, 1);
    conv_w_kernel<<<dim3(32, 32), wtb>>>(Wv, 2);
    conv_w_kernel<<<dim3(32, 32), wtb>>>(Wo, 3);

    const int gemm_smem = NSTAGE * STG;   // 61440
    cudaFuncSetAttribute(mma_gemm, cudaFuncAttributeMaxDynamicSharedMemorySize,
                         gemm_smem);
    dim3 gg(EMB / 128, MTOT / 128);       // (8, 64)

    mma_gemm<<<gg, 256, gemm_smem>>>(nullptr, 0, 0, 0, 1);   // Q (+rotary)
    mma_gemm<<<gg, 256, gemm_smem>>>(nullptr, 1, 1, 1, 1);   // K (+rotary)
    mma_gemm<<<gg, 256, gemm_smem>>>(nullptr, 1, 2, 2, 0);   // V

    const int attn_smem = (64 * 65 * 2 + 64 * 64 * 2) * (int)sizeof(float);
    cudaFuncSetAttribute(attn_kernel, cudaFuncAttributeMaxDynamicSharedMemorySize,
                         attn_smem);
    attn_kernel<<<dim3(T_SEQ / 64, NHEADS, BATCH), 256, attn_smem>>>();

    mma_gemm<<<gg, 256, gemm_smem>>>(out, 2, 3, 3, 0);       // O-proj
}

// round 4
// speedup vs baseline: 1.8215x; 1.1270x over previous
#include <cuda_runtime.h>
#include <cuda_bf16.h>
#include <math.h>
#include <stdint.h>

#define BATCH   4
#define T_SEQ   2048
#define EMB     1024
#define NHEADS  16
#define HDIM    64
#define WHALF   256
#define MTOT    (BATCH * T_SEQ)      // 8192
#define K3      3072                 // 3x split-bf16 K
#define BK      32
#define NCH     (K3 / BK)            // 96
#define AROWB   80                   // padded row: 32 bf16 (64B) + 16B pad
#define ASTG    (128 * AROWB)
#define STG     (2 * ASTG)
#define NSTAGE  3

// ---------------------------------------------------------------------------
// Scratch (static device globals; cudaMalloc forbidden)
// ---------------------------------------------------------------------------
__device__ __nv_bfloat16 a_q [(size_t)MTOT * K3];
__device__ __nv_bfloat16 a_kv[(size_t)MTOT * K3];
__device__ __nv_bfloat16 a_at[(size_t)MTOT * K3];
__device__ __nv_bfloat16 w_q[EMB * K3];
__device__ __nv_bfloat16 w_k[EMB * K3];
__device__ __nv_bfloat16 w_v[EMB * K3];
__device__ __nv_bfloat16 w_o[EMB * K3];
// attention operands (split-bf16, written by projection GEMM epilogues)
__device__ __nv_bfloat16 q2 [(size_t)MTOT * NHEADS * 192];  // [m][h][hi|lo|hi]
__device__ __nv_bfloat16 k2 [(size_t)MTOT * NHEADS * 192];  // [m][h][hi|hi|lo]
__device__ __nv_bfloat16 v2h[(size_t)MTOT * EMB];           // [m][h*64+d] hi
__device__ __nv_bfloat16 v2l[(size_t)MTOT * EMB];           // lo
__device__ float g_invf[32];

// ---------------------------------------------------------------------------
// PTX helpers (sm_103 base ISA only — no tcgen05)
// ---------------------------------------------------------------------------
__device__ __forceinline__ uint32_t smem_u32(const void* p) {
    uint32_t a;
    asm("{ .reg .u64 t; cvta.to.shared.u64 t, %1; cvt.u32.u64 %0, t; }"
        : "=r"(a) : "l"(p));
    return a;
}
__device__ __forceinline__ void cp16(uint32_t dst, const void* src) {
    asm volatile("cp.async.cg.shared.global [%0], [%1], 16;"
                 :: "r"(dst), "l"(src) : "memory");
}
__device__ __forceinline__ void cp_commit() {
    asm volatile("cp.async.commit_group;" ::: "memory");
}
__device__ __forceinline__ void ldsm4(uint32_t& r0, uint32_t& r1,
                                      uint32_t& r2, uint32_t& r3, uint32_t addr) {
    asm volatile("ldmatrix.sync.aligned.m8n8.x4.shared.b16 {%0,%1,%2,%3}, [%4];"
                 : "=r"(r0), "=r"(r1), "=r"(r2), "=r"(r3) : "r"(addr));
}
__device__ __forceinline__ void ldsm4t(uint32_t& r0, uint32_t& r1,
                                       uint32_t& r2, uint32_t& r3, uint32_t addr) {
    asm volatile("ldmatrix.sync.aligned.m8n8.x4.trans.shared.b16 {%0,%1,%2,%3}, [%4];"
                 : "=r"(r0), "=r"(r1), "=r"(r2), "=r"(r3) : "r"(addr));
}
__device__ __forceinline__ void mma16816(float* c, uint32_t a0, uint32_t a1,
                                         uint32_t a2, uint32_t a3,
                                         uint32_t b0, uint32_t b1) {
    asm volatile(
        "mma.sync.aligned.m16n8k16.row.col.f32.bf16.bf16.f32 "
        "{%0,%1,%2,%3}, {%4,%5,%6,%7}, {%8,%9}, {%0,%1,%2,%3};"
        : "+f"(c[0]), "+f"(c[1]), "+f"(c[2]), "+f"(c[3])
        : "r"(a0), "r"(a1), "r"(a2), "r"(a3), "r"(b0), "r"(b1));
}
__device__ __forceinline__ uint32_t pk_bf2(__nv_bfloat16 a, __nv_bfloat16 b) {
    return (uint32_t)__bfloat16_as_ushort(a) |
           ((uint32_t)__bfloat16_as_ushort(b) << 16);
}
__device__ __forceinline__ void split2(float x0, float x1,
                                       uint32_t& hp, uint32_t& lp) {
    __nv_bfloat16 h0 = __float2bfloat16(x0);
    __nv_bfloat16 h1 = __float2bfloat16(x1);
    __nv_bfloat16 l0 = __float2bfloat16(x0 - __bfloat162float(h0));
    __nv_bfloat16 l1 = __float2bfloat16(x1 - __bfloat162float(h1));
    hp = pk_bf2(h0, h1);
    lp = pk_bf2(l0, l1);
}

// ---------------------------------------------------------------------------
// Conversion kernels
// ---------------------------------------------------------------------------
__global__ void init_invf_kernel() {
    int p = threadIdx.x;
    if (p < 32) g_invf[p] = (float)pow(10000.0, -(double)p / 32.0);
}

__global__ __launch_bounds__(256) void conv_in_kernel(const float* __restrict__ X,
                                                      int which) {
    __nv_bfloat16* A = which ? a_kv : a_q;
    for (size_t i = (size_t)blockIdx.x * blockDim.x + threadIdx.x;
         i < (size_t)MTOT * EMB; i += (size_t)gridDim.x * blockDim.x) {
        size_t m = i >> 10;
        int k = (int)(i & 1023);
        float x = X[i];
        __nv_bfloat16 h = __float2bfloat16(x);
        __nv_bfloat16 l = __float2bfloat16(x - __bfloat162float(h));
        __nv_bfloat16* row = A + m * K3;
        row[k] = h; row[1024 + k] = l; row[2048 + k] = h;
    }
}

__global__ void conv_w_kernel(const float* __restrict__ W, int which) {
    __nv_bfloat16* O = (which == 0) ? w_q : (which == 1) ? w_k
                       : (which == 2) ? w_v : w_o;
    __shared__ float tile[32][33];
    int tx = threadIdx.x, ty = threadIdx.y;
    int n_in = blockIdx.x * 32 + tx;
    int k_in = blockIdx.y * 32 + ty;
    tile[ty][tx] = W[(size_t)k_in * EMB + n_in];
    __syncthreads();
    int n = blockIdx.x * 32 + ty;
    int k = blockIdx.y * 32 + tx;
    float x = tile[tx][ty];
    __nv_bfloat16 h = __float2bfloat16(x);
    __nv_bfloat16 l = __float2bfloat16(x - __bfloat162float(h));
    __nv_bfloat16* row = O + (size_t)n * K3;
    row[k] = h; row[1024 + k] = h; row[2048 + k] = l;
}

// ---------------------------------------------------------------------------
// mma.sync bf16 GEMM: 128x128 CTA tile, 8 warps, BK=32, 3-stage cp.async.
// Epilogues: csel 0/1 -> q2/k2 split rows (+rotary, Q pre-scaled by 1/8)
//            csel 2   -> v2h/v2l
//            csel 3   -> fp32 to Cexp (final output)
// ---------------------------------------------------------------------------
__global__ __launch_bounds__(256) void mma_gemm(float* __restrict__ Cexp,
                                                int asel, int bsel, int csel,
                                                int rotary) {
    const __nv_bfloat16* Ag = (asel == 0) ? a_q : (asel == 1) ? a_kv : a_at;
    const __nv_bfloat16* Bg = (bsel == 0) ? w_q : (bsel == 1) ? w_k
                              : (bsel == 2) ? w_v : w_o;

    extern __shared__ char smraw[];
    const uint32_t sb = smem_u32(smraw);
    const int t = threadIdx.x;
    const int wid = t >> 5, lane = t & 31;
    const int m0 = blockIdx.y * 128, n0 = blockIdx.x * 128;
    const int wm0 = (wid & 1) * 64;
    const int wn0 = (wid >> 1) * 32;

    const char* Ab = (const char*)(Ag + (size_t)m0 * K3);
    const char* Bb = (const char*)(Bg + (size_t)n0 * K3);

    const int r0i = (2 * t) >> 2, s0i = (2 * t) & 3;
    const int r1i = (2 * t + 1) >> 2, s1i = (2 * t + 1) & 3;

#define LOAD_CHUNK(c)                                                          \
    do {                                                                       \
        uint32_t _sa = sb + ((c) % NSTAGE) * STG;                              \
        uint32_t _sb2 = _sa + ASTG;                                            \
        size_t _g0 = (size_t)r0i * (K3 * 2) + (size_t)(c) * 64 + s0i * 16;     \
        size_t _g1 = (size_t)r1i * (K3 * 2) + (size_t)(c) * 64 + s1i * 16;     \
        cp16(_sa + r0i * AROWB + s0i * 16, Ab + _g0);                          \
        cp16(_sa + r1i * AROWB + s1i * 16, Ab + _g1);                          \
        cp16(_sb2 + r0i * AROWB + s0i * 16, Bb + _g0);                         \
        cp16(_sb2 + r1i * AROWB + s1i * 16, Bb + _g1);                         \
        cp_commit();                                                           \
    } while (0)

    float acc[4][4][4];
#pragma unroll
    for (int i = 0; i < 4; i++)
#pragma unroll
        for (int j = 0; j < 4; j++)
#pragma unroll
            for (int u = 0; u < 4; u++) acc[i][j][u] = 0.0f;

    LOAD_CHUNK(0); LOAD_CHUNK(1); LOAD_CHUNK(2);

    const int lq = lane >> 3, lr = lane & 7;
    const int a_row = (lq & 1) * 8 + lr;
    const int a_cb  = (lq >> 1) * 16;
    const int b_row = (lq >> 1) * 8 + lr;
    const int b_cb  = (lq & 1) * 16;

    for (int c = 0; c < NCH; c++) {
        int pend = NCH - 1 - c; if (pend > 2) pend = 2;
        if (pend == 2)      asm volatile("cp.async.wait_group 2;" ::: "memory");
        else if (pend == 1) asm volatile("cp.async.wait_group 1;" ::: "memory");
        else                asm volatile("cp.async.wait_group 0;" ::: "memory");
        __syncthreads();

        const uint32_t sa  = sb + (c % NSTAGE) * STG;
        const uint32_t sb2 = sa + ASTG;

#pragma unroll
        for (int ks = 0; ks < 2; ks++) {
            uint32_t af[4][4], bf[2][4];
#pragma unroll
            for (int i = 0; i < 4; i++)
                ldsm4(af[i][0], af[i][1], af[i][2], af[i][3],
                      sa + (uint32_t)((wm0 + i * 16 + a_row) * AROWB
                                      + ks * 32 + a_cb));
#pragma unroll
            for (int jp = 0; jp < 2; jp++)
                ldsm4(bf[jp][0], bf[jp][1], bf[jp][2], bf[jp][3],
                      sb2 + (uint32_t)((wn0 + jp * 16 + b_row) * AROWB
                                       + ks * 32 + b_cb));
#pragma unroll
            for (int i = 0; i < 4; i++)
#pragma unroll
                for (int j = 0; j < 4; j++)
                    mma16816(acc[i][j], af[i][0], af[i][1], af[i][2], af[i][3],
                             bf[j >> 1][(j & 1) * 2], bf[j >> 1][(j & 1) * 2 + 1]);
        }
        __syncthreads();
        if (c + 3 < NCH) LOAD_CHUNK(c + 3);
    }

    // ---- epilogue ----
    const int mrow = lane >> 2;
    const int ncol = (lane & 3) * 2;
#pragma unroll
    for (int i = 0; i < 4; i++) {
        const int gmA = m0 + wm0 + i * 16 + mrow;
        const int gmB = gmA + 8;
        const float tpA = (float)(gmA & (T_SEQ - 1));
        const float tpB = (float)(gmB & (T_SEQ - 1));
#pragma unroll
        for (int j = 0; j < 4; j++) {
            const int gc = n0 + wn0 + j * 8 + ncol;
            float x0 = acc[i][j][0], x1 = acc[i][j][1];
            float y0 = acc[i][j][2], y1 = acc[i][j][3];
            if (rotary) {
                const int p = (gc & 63) >> 1;
                const float f = g_invf[p];
                float angA = __fmul_rn(tpA, f);
                float angB = __fmul_rn(tpB, f);
                double dA = (double)angA;
                double rA = dA - floor(dA * 0.15915494309189535) * 6.283185307179586;
                double dB = (double)angB;
                double rB = dB - floor(dB * 0.15915494309189535) * 6.283185307179586;
                float sA = sinf((float)rA), cA = cosf((float)rA);
                float sB = sinf((float)rB), cB = cosf((float)rB);
                float t0 = x0 * cA - x1 * sA;
                float t1 = x1 * cA + x0 * sA;
                float u0 = y0 * cB - y1 * sB;
                float u1 = y1 * cB + y0 * sB;
                x0 = t0; x1 = t1; y0 = u0; y1 = u1;
            }
            if (csel <= 1) {                       // Q or K -> split rows
                if (csel == 0) { x0 *= 0.125f; x1 *= 0.125f;
                                 y0 *= 0.125f; y1 *= 0.125f; }
                __nv_bfloat16* dst = (csel == 0) ? q2 : k2;
                const int hh = gc >> 6, d = gc & 63;
                uint32_t hA, lA, hB, lB;
                split2(x0, x1, hA, lA);
                split2(y0, y1, hB, lB);
                __nv_bfloat16* rA2 = dst + ((size_t)gmA * NHEADS + hh) * 192 + d;
                __nv_bfloat16* rB2 = dst + ((size_t)gmB * NHEADS + hh) * 192 + d;
                if (csel == 0) {   // Q: [hi | lo | hi]
                    *(uint32_t*)(rA2)       = hA;
                    *(uint32_t*)(rA2 + 64)  = lA;
                    *(uint32_t*)(rA2 + 128) = hA;
                    *(uint32_t*)(rB2)       = hB;
                    *(uint32_t*)(rB2 + 64)  = lB;
                    *(uint32_t*)(rB2 + 128) = hB;
                } else {           // K: [hi | hi | lo]
                    *(uint32_t*)(rA2)       = hA;
                    *(uint32_t*)(rA2 + 64)  = hA;
                    *(uint32_t*)(rA2 + 128) = lA;
                    *(uint32_t*)(rB2)       = hB;
                    *(uint32_t*)(rB2 + 64)  = hB;
                    *(uint32_t*)(rB2 + 128) = lB;
                }
            } else if (csel == 2) {                // V -> hi/lo planes
                uint32_t hA, lA, hB, lB;
                split2(x0, x1, hA, lA);
                split2(y0, y1, hB, lB);
                *(uint32_t*)(v2h + (size_t)gmA * EMB + gc) = hA;
                *(uint32_t*)(v2l + (size_t)gmA * EMB + gc) = lA;
                *(uint32_t*)(v2h + (size_t)gmB * EMB + gc) = hB;
                *(uint32_t*)(v2l + (size_t)gmB * EMB + gc) = lB;
            } else {                               // final fp32 output
                *(float2*)(Cexp + (size_t)gmA * EMB + gc) = make_float2(x0, x1);
                *(float2*)(Cexp + (size_t)gmB * EMB + gc) = make_float2(y0, y1);
            }
        }
    }
#undef LOAD_CHUNK
}

// ---------------------------------------------------------------------------
// Banded flash attention with mma.sync. Block = (64 queries, head, batch),
// 4 warps. QK^T: 64x64x192 split-bf16. Softmax in accumulator layout.
// PV: 3 register terms Ph*Vh + Pl*Vh + Ph*Vl, V frags via ldmatrix.trans.
// Output written as split-bf16 rows [hi|lo|hi] of a_at for the O-GEMM.
// ---------------------------------------------------------------------------
#define QPITCH 400   // bytes per Q/K smem row (192 bf16 + pad, 16B-mult)
#define VPITCH 144   // bytes per V smem row (64 bf16 + pad, 16B-mult)
#define SM_Q   0
#define SM_K   (64 * QPITCH)             // 25600
#define SM_VH  (SM_K + 64 * QPITCH)      // 51200
#define SM_VL  (SM_VH + 64 * VPITCH)     // 60416
#define SM_ATT (SM_VL + 64 * VPITCH)     // 69632 bytes total

__global__ __launch_bounds__(128) void attn_mma() {
    const int qt = blockIdx.x, h = blockIdx.y, b = blockIdx.z;
    const int t = threadIdx.x;
    const int wid = t >> 5, lane = t & 31;
    const int qbase = qt * 64;

    extern __shared__ char smraw[];
    char* smp = smraw;
    const uint32_t sb = smem_u32(smraw);

    // ---- load Q' tile (64 x 192) once ----
    for (int i = t; i < 64 * 24; i += 128) {
        int r = i / 24, c = i % 24;
        const uint4* src = (const uint4*)(q2 +
            ((size_t)(b * T_SEQ + qbase + r) * NHEADS + h) * 192);
        *(uint4*)(smp + SM_Q + r * QPITCH + c * 16) = src[c];
    }

    float m0r = -3.0e38f, m1r = -3.0e38f, l0r = 0.0f, l1r = 0.0f;
    float o[8][4];
#pragma unroll
    for (int j = 0; j < 8; j++)
#pragma unroll
        for (int u = 0; u < 4; u++) o[j][u] = 0.0f;

    const int kt_lo = (qt - 4 > 0) ? (qt - 4) : 0;
    const int kt_hi = (qt + 4 < 31) ? (qt + 4) : 31;

    const int r0g = qbase + 16 * wid + (lane >> 2);   // global q row (and +8)
    const int coff = 2 * (lane & 3);

    for (int kt = kt_lo; kt <= kt_hi; kt++) {
        const int kbase = kt * 64;
        __syncthreads();   // previous tile's smem fully consumed
        // ---- load K' (64x192) and Vh/Vl (64x64) ----
        for (int i = t; i < 64 * 24; i += 128) {
            int r = i / 24, c = i % 24;
            const uint4* src = (const uint4*)(k2 +
                ((size_t)(b * T_SEQ + kbase + r) * NHEADS + h) * 192);
            *(uint4*)(smp + SM_K + r * QPITCH + c * 16) = src[c];
        }
        for (int i = t; i < 64 * 8; i += 128) {
            int r = i / 8, c = i % 8;
            size_t g = (size_t)(b * T_SEQ + kbase + r) * EMB + h * 64;
            *(uint4*)(smp + SM_VH + r * VPITCH + c * 16) =
                ((const uint4*)(v2h + g))[c];
            *(uint4*)(smp + SM_VL + r * VPITCH + c * 16) =
                ((const uint4*)(v2l + g))[c];
        }
        __syncthreads();

        // ---- S = Q' K'^T (k = 192) ----
        float s[8][4];
#pragma unroll
        for (int j = 0; j < 8; j++)
#pragma unroll
            for (int u = 0; u < 4; u++) s[j][u] = 0.0f;

        const uint32_t aAddrBase = sb + SM_Q
            + (uint32_t)((16 * wid + (lane & 15)) * QPITCH + (lane >> 4) * 16);
        const int bRow = (lane & 7) + ((lane >> 4) << 3);
        const uint32_t bAddrBase = sb + SM_K
            + (uint32_t)(bRow * QPITCH + (((lane >> 3) & 1) << 4));

#pragma unroll
        for (int ks = 0; ks < 12; ks++) {
            uint32_t a0, a1, a2, a3;
            ldsm4(a0, a1, a2, a3, aAddrBase + ks * 32);
#pragma unroll
            for (int g = 0; g < 4; g++) {
                uint32_t b0, b1, b2, b3;
                ldsm4(b0, b1, b2, b3,
                      bAddrBase + (uint32_t)(g * 16 * QPITCH + ks * 32));
                mma16816(s[2 * g],     a0, a1, a2, a3, b0, b1);
                mma16816(s[2 * g + 1], a0, a1, a2, a3, b2, b3);
            }
        }

        // ---- band mask ----
#pragma unroll
        for (int j = 0; j < 8; j++) {
            int c0 = kbase + 8 * j + coff;
            int d00 = r0g - c0, d01 = r0g - (c0 + 1);
            if (d00 > WHALF || d00 < -WHALF) s[j][0] = -1.0e30f;
            if (d01 > WHALF || d01 < -WHALF) s[j][1] = -1.0e30f;
            int d10 = d00 + 8, d11 = d01 + 8;
            if (d10 > WHALF || d10 < -WHALF) s[j][2] = -1.0e30f;
            if (d11 > WHALF || d11 < -WHALF) s[j][3] = -1.0e30f;
        }

        // ---- online softmax (row group = 4 lanes) ----
        float mx0 = -1.0e30f, mx1 = -1.0e30f;
#pragma unroll
        for (int j = 0; j < 8; j++) {
            mx0 = fmaxf(mx0, fmaxf(s[j][0], s[j][1]));
            mx1 = fmaxf(mx1, fmaxf(s[j][2], s[j][3]));
        }
        mx0 = fmaxf(mx0, __shfl_xor_sync(0xffffffffu, mx0, 1));
        mx0 = fmaxf(mx0, __shfl_xor_sync(0xffffffffu, mx0, 2));
        mx1 = fmaxf(mx1, __shfl_xor_sync(0xffffffffu, mx1, 1));
        mx1 = fmaxf(mx1, __shfl_xor_sync(0xffffffffu, mx1, 2));
        float mn0 = fmaxf(m0r, mx0), mn1 = fmaxf(m1r, mx1);
        float cor0 = __expf(m0r - mn0), cor1 = __expf(m1r - mn1);
        m0r = mn0; m1r = mn1;

        float rs0 = 0.0f, rs1 = 0.0f;
#pragma unroll
        for (int j = 0; j < 8; j++) {
            s[j][0] = __expf(s[j][0] - mn0);
            s[j][1] = __expf(s[j][1] - mn0);
            s[j][2] = __expf(s[j][2] - mn1);
            s[j][3] = __expf(s[j][3] - mn1);
            rs0 += s[j][0] + s[j][1];
            rs1 += s[j][2] + s[j][3];
        }
        rs0 += __shfl_xor_sync(0xffffffffu, rs0, 1);
        rs0 += __shfl_xor_sync(0xffffffffu, rs0, 2);
        rs1 += __shfl_xor_sync(0xffffffffu, rs1, 1);
        rs1 += __shfl_xor_sync(0xffffffffu, rs1, 2);
        l0r = l0r * cor0 + rs0;
        l1r = l1r * cor1 + rs1;

#pragma unroll
        for (int j = 0; j < 8; j++) {
            o[j][0] *= cor0; o[j][1] *= cor0;
            o[j][2] *= cor1; o[j][3] *= cor1;
        }

        // ---- P -> register A-fragments (hi/lo) ----
        uint32_t ph[4][4], pl[4][4];
#pragma unroll
        for (int ks2 = 0; ks2 < 4; ks2++) {
            int j0 = 2 * ks2, j1 = j0 + 1;
            split2(s[j0][0], s[j0][1], ph[ks2][0], pl[ks2][0]);
            split2(s[j0][2], s[j0][3], ph[ks2][1], pl[ks2][1]);
            split2(s[j1][0], s[j1][1], ph[ks2][2], pl[ks2][2]);
            split2(s[j1][2], s[j1][3], ph[ks2][3], pl[ks2][3]);
        }

        // ---- PV: out += Ph*Vh + Pl*Vh + Ph*Vl ----
        const uint32_t vAddrBase =
            (uint32_t)((lane & 15) * VPITCH + (lane >> 4) * 16);
#pragma unroll
        for (int ks2 = 0; ks2 < 4; ks2++) {
            uint32_t voff = vAddrBase + (uint32_t)(ks2 * 16 * VPITCH);
#pragma unroll
            for (int g = 0; g < 4; g++) {
                uint32_t h0, h1, h2, h3, e0, e1, e2, e3;
                ldsm4t(h0, h1, h2, h3, sb + SM_VH + voff + g * 32);
                ldsm4t(e0, e1, e2, e3, sb + SM_VL + voff + g * 32);
                mma16816(o[2 * g],     ph[ks2][0], ph[ks2][1], ph[ks2][2],
                         ph[ks2][3], h0, h1);
                mma16816(o[2 * g + 1], ph[ks2][0], ph[ks2][1], ph[ks2][2],
                         ph[ks2][3], h2, h3);
                mma16816(o[2 * g],     pl[ks2][0], pl[ks2][1], pl[ks2][2],
                         pl[ks2][3], h0, h1);
                mma16816(o[2 * g + 1], pl[ks2][0], pl[ks2][1], pl[ks2][2],
                         pl[ks2][3], h2, h3);
                mma16816(o[2 * g],     ph[ks2][0], ph[ks2][1], ph[ks2][2],
                         ph[ks2][3], e0, e1);
                mma16816(o[2 * g + 1], ph[ks2][0], ph[ks2][1], ph[ks2][2],
                         ph[ks2][3], e2, e3);
            }
        }
    }

    // ---- finalize: scale by 1/l, write split rows [hi|lo|hi] of a_at ----
    const float inv0 = 1.0f / l0r, inv1 = 1.0f / l1r;
    const size_t mA = (size_t)(b * T_SEQ) + qbase + 16 * wid + (lane >> 2);
    const size_t mB = mA + 8;
    __nv_bfloat16* rowA = a_at + mA * K3 + h * 64 + coff;
    __nv_bfloat16* rowB = a_at + mB * K3 + h * 64 + coff;
#pragma unroll
    for (int j = 0; j < 8; j++) {
        uint32_t hA, lA, hB, lB;
        split2(o[j][0] * inv0, o[j][1] * inv0, hA, lA);
        split2(o[j][2] * inv1, o[j][3] * inv1, hB, lB);
        *(uint32_t*)(rowA + 8 * j)        = hA;
        *(uint32_t*)(rowA + 8 * j + 1024) = lA;
        *(uint32_t*)(rowA + 8 * j + 2048) = hA;
        *(uint32_t*)(rowB + 8 * j)        = hB;
        *(uint32_t*)(rowB + 8 * j + 1024) = lB;
        *(uint32_t*)(rowB + 8 * j + 2048) = hB;
    }
}

// ---------------------------------------------------------------------------
// Launch
// ---------------------------------------------------------------------------
extern "C" void kernel_launch(void* const* d_in, const int* in_sizes, int n_in,
                              void* d_out, int out_size)
{
    const float* xq  = (const float*)d_in[0];
    const float* xkv = (const float*)d_in[1];
    const float* Wq  = (const float*)d_in[2];
    const float* Wk  = (const float*)d_in[3];
    const float* Wv  = (const float*)d_in[4];
    const float* Wo  = (const float*)d_in[5];
    float* out = (float*)d_out;

    init_invf_kernel<<<1, 32>>>();
    conv_in_kernel<<<4096, 256>>>(xq, 0);
    conv_in_kernel<<<4096, 256>>>(xkv, 1);
    dim3 wtb(32, 32);
    conv_w_kernel<<<dim3(32, 32), wtb>>>(Wq, 0);
    conv_w_kernel<<<dim3(32, 32), wtb>>>(Wk, 1);
    conv_w_kernel<<<dim3(32, 32), wtb>>>(Wv, 2);
    conv_w_kernel<<<dim3(32, 32), wtb>>>(Wo, 3);

    const int gemm_smem = NSTAGE * STG;   // 61440
    cudaFuncSetAttribute(mma_gemm, cudaFuncAttributeMaxDynamicSharedMemorySize,
                         gemm_smem);
    dim3 gg(EMB / 128, MTOT / 128);       // (8, 64)

    mma_gemm<<<gg, 256, gemm_smem>>>(nullptr, 0, 0, 0, 1);   // Q (+rotary, x1/8)
    mma_gemm<<<gg, 256, gemm_smem>>>(nullptr, 1, 1, 1, 1);   // K (+rotary)
    mma_gemm<<<gg, 256, gemm_smem>>>(nullptr, 1, 2, 2, 0);   // V

    cudaFuncSetAttribute(attn_mma, cudaFuncAttributeMaxDynamicSharedMemorySize,
                         SM_ATT);
    attn_mma<<<dim3(T_SEQ / 64, NHEADS, BATCH), 128, SM_ATT>>>();

    mma_gemm<<<gg, 256, gemm_smem>>>(out, 2, 3, 3, 0);       // O-proj
}

// round 5
// speedup vs baseline: 2.7802x; 1.5263x over previous
#include <cuda_runtime.h>
#include <cuda_fp16.h>
#include <math.h>
#include <stdint.h>

#define BATCH   4
#define T_SEQ   2048
#define EMB     1024
#define NHEADS  16
#define HDIM    64
#define WHALF   256
#define MTOT    (BATCH * T_SEQ)      // 8192
#define K2      2048                 // 2x split-fp16 K
#define BK      32
#define NCH     (K2 / BK)            // 64
#define AROWB   80                   // padded row: 32 fp16 (64B) + 16B pad
#define ASTG    (128 * AROWB)
#define STG     (2 * ASTG)
#define NSTAGE  3

// ---------------------------------------------------------------------------
// Scratch (static device globals; cudaMalloc forbidden)
// ---------------------------------------------------------------------------
__device__ __half a_q [(size_t)MTOT * K2];    // [Xh | Xl]
__device__ __half a_kv[(size_t)MTOT * K2];
__device__ __half a_at[(size_t)MTOT * K2];    // attn out [Oh | Ol]
__device__ __half w_q[EMB * EMB];             // Wh only, [N][K] K-major
__device__ __half w_k[EMB * EMB];
__device__ __half w_v[EMB * EMB];
__device__ __half w_o[EMB * EMB];
// attention operands
__device__ __half q2[(size_t)MTOT * NHEADS * 128];  // [m][h][Qh|Ql] (x 1/8)
__device__ __half k2[(size_t)MTOT * NHEADS * 64];   // [m][h][Kh]
__device__ __half v2[(size_t)MTOT * EMB];           // [m][h*64+d] Vh
__device__ float g_invf[32];

// ---------------------------------------------------------------------------
// PTX helpers (sm_103 base ISA only)
// ---------------------------------------------------------------------------
__device__ __forceinline__ uint32_t smem_u32(const void* p) {
    uint32_t a;
    asm("{ .reg .u64 t; cvta.to.shared.u64 t, %1; cvt.u32.u64 %0, t; }"
        : "=r"(a) : "l"(p));
    return a;
}
__device__ __forceinline__ void cp16(uint32_t dst, const void* src) {
    asm volatile("cp.async.cg.shared.global [%0], [%1], 16;"
                 :: "r"(dst), "l"(src) : "memory");
}
__device__ __forceinline__ void cp_commit() {
    asm volatile("cp.async.commit_group;" ::: "memory");
}
__device__ __forceinline__ void ldsm4(uint32_t& r0, uint32_t& r1,
                                      uint32_t& r2, uint32_t& r3, uint32_t addr) {
    asm volatile("ldmatrix.sync.aligned.m8n8.x4.shared.b16 {%0,%1,%2,%3}, [%4];"
                 : "=r"(r0), "=r"(r1), "=r"(r2), "=r"(r3) : "r"(addr));
}
__device__ __forceinline__ void ldsm4t(uint32_t& r0, uint32_t& r1,
                                       uint32_t& r2, uint32_t& r3, uint32_t addr) {
    asm volatile("ldmatrix.sync.aligned.m8n8.x4.trans.shared.b16 {%0,%1,%2,%3}, [%4];"
                 : "=r"(r0), "=r"(r1), "=r"(r2), "=r"(r3) : "r"(addr));
}
__device__ __forceinline__ void mma16816(float* c, uint32_t a0, uint32_t a1,
                                         uint32_t a2, uint32_t a3,
                                         uint32_t b0, uint32_t b1) {
    asm volatile(
        "mma.sync.aligned.m16n8k16.row.col.f32.f16.f16.f32 "
        "{%0,%1,%2,%3}, {%4,%5,%6,%7}, {%8,%9}, {%0,%1,%2,%3};"
        : "+f"(c[0]), "+f"(c[1]), "+f"(c[2]), "+f"(c[3])
        : "r"(a0), "r"(a1), "r"(a2), "r"(a3), "r"(b0), "r"(b1));
}
__device__ __forceinline__ uint32_t pk_h2(__half a, __half b) {
    return (uint32_t)__half_as_ushort(a) |
           ((uint32_t)__half_as_ushort(b) << 16);
}
__device__ __forceinline__ void splitH(float x0, float x1,
                                       uint32_t& hp, uint32_t& lp) {
    __half h0 = __float2half_rn(x0);
    __half h1 = __float2half_rn(x1);
    __half l0 = __float2half_rn(x0 - __half2float(h0));
    __half l1 = __float2half_rn(x1 - __half2float(h1));
    hp = pk_h2(h0, h1);
    lp = pk_h2(l0, l1);
}

// ---------------------------------------------------------------------------
// Conversion kernels
// ---------------------------------------------------------------------------
__global__ void init_invf_kernel() {
    int p = threadIdx.x;
    if (p < 32) g_invf[p] = (float)pow(10000.0, -(double)p / 32.0);
}

// inputs [8192,1024] fp32 -> [Xh | Xl] fp16 [8192,2048]
__global__ __launch_bounds__(256) void conv_in_kernel(const float* __restrict__ X,
                                                      int which) {
    __half* A = which ? a_kv : a_q;
    for (size_t i = (size_t)blockIdx.x * blockDim.x + threadIdx.x;
         i < (size_t)MTOT * EMB; i += (size_t)gridDim.x * blockDim.x) {
        size_t m = i >> 10;
        int k = (int)(i & 1023);
        float x = X[i];
        __half h = __float2half_rn(x);
        __half l = __float2half_rn(x - __half2float(h));
        __half* row = A + m * K2;
        row[k] = h; row[1024 + k] = l;
    }
}

// W [1024 K,1024 N] fp32 -> Wh fp16 [1024 N][1024 K] (transposed)
__global__ void conv_w_kernel(const float* __restrict__ W, int which) {
    __half* O = (which == 0) ? w_q : (which == 1) ? w_k
                : (which == 2) ? w_v : w_o;
    __shared__ float tile[32][33];
    int tx = threadIdx.x, ty = threadIdx.y;
    tile[ty][tx] = W[(size_t)(blockIdx.y * 32 + ty) * EMB + blockIdx.x * 32 + tx];
    __syncthreads();
    int n = blockIdx.x * 32 + ty;
    int k = blockIdx.y * 32 + tx;
    O[(size_t)n * EMB + k] = __float2half_rn(tile[tx][ty]);
}

// ---------------------------------------------------------------------------
// mma.sync fp16 GEMM: D = A'[M,2048] * (Wh[N,1024] dup)^T
// 128x128 CTA tile, 8 warps, BK=32, 3-stage cp.async. B chunk = c & 31.
// ---------------------------------------------------------------------------
__global__ __launch_bounds__(256) void mma_gemm(float* __restrict__ Cexp,
                                                int asel, int bsel, int csel,
                                                int rotary) {
    const __half* Ag = (asel == 0) ? a_q : (asel == 1) ? a_kv : a_at;
    const __half* Bg = (bsel == 0) ? w_q : (bsel == 1) ? w_k
                       : (bsel == 2) ? w_v : w_o;

    extern __shared__ char smraw[];
    const uint32_t sb = smem_u32(smraw);
    const int t = threadIdx.x;
    const int wid = t >> 5, lane = t & 31;
    const int m0 = blockIdx.y * 128, n0 = blockIdx.x * 128;
    const int wm0 = (wid & 1) * 64;
    const int wn0 = (wid >> 1) * 32;

    const char* Ab = (const char*)(Ag + (size_t)m0 * K2);
    const char* Bb = (const char*)(Bg + (size_t)n0 * EMB);

    const int r0i = (2 * t) >> 2, s0i = (2 * t) & 3;
    const int r1i = (2 * t + 1) >> 2, s1i = (2 * t + 1) & 3;

#define LOAD_CHUNK(c)                                                          \
    do {                                                                       \
        uint32_t _sa = sb + ((c) % NSTAGE) * STG;                              \
        uint32_t _sb2 = _sa + ASTG;                                            \
        size_t _ga0 = (size_t)r0i * (K2 * 2) + (size_t)(c) * 64 + s0i * 16;    \
        size_t _ga1 = (size_t)r1i * (K2 * 2) + (size_t)(c) * 64 + s1i * 16;    \
        size_t _gb0 = (size_t)r0i * (EMB * 2) + (size_t)((c) & 31) * 64        \
                      + s0i * 16;                                              \
        size_t _gb1 = (size_t)r1i * (EMB * 2) + (size_t)((c) & 31) * 64        \
                      + s1i * 16;                                              \
        cp16(_sa + r0i * AROWB + s0i * 16, Ab + _ga0);                         \
        cp16(_sa + r1i * AROWB + s1i * 16, Ab + _ga1);                         \
        cp16(_sb2 + r0i * AROWB + s0i * 16, Bb + _gb0);                        \
        cp16(_sb2 + r1i * AROWB + s1i * 16, Bb + _gb1);                        \
        cp_commit();                                                           \
    } while (0)

    float acc[4][4][4];
#pragma unroll
    for (int i = 0; i < 4; i++)
#pragma unroll
        for (int j = 0; j < 4; j++)
#pragma unroll
            for (int u = 0; u < 4; u++) acc[i][j][u] = 0.0f;

    LOAD_CHUNK(0); LOAD_CHUNK(1); LOAD_CHUNK(2);

    const int lq = lane >> 3, lr = lane & 7;
    const int a_row = (lq & 1) * 8 + lr;
    const int a_cb  = (lq >> 1) * 16;
    const int b_row = (lq >> 1) * 8 + lr;
    const int b_cb  = (lq & 1) * 16;

    for (int c = 0; c < NCH; c++) {
        int pend = NCH - 1 - c; if (pend > 2) pend = 2;
        if (pend == 2)      asm volatile("cp.async.wait_group 2;" ::: "memory");
        else if (pend == 1) asm volatile("cp.async.wait_group 1;" ::: "memory");
        else                asm volatile("cp.async.wait_group 0;" ::: "memory");
        __syncthreads();

        const uint32_t sa  = sb + (c % NSTAGE) * STG;
        const uint32_t sb2 = sa + ASTG;

#pragma unroll
        for (int ks = 0; ks < 2; ks++) {
            uint32_t af[4][4], bf[2][4];
#pragma unroll
            for (int i = 0; i < 4; i++)
                ldsm4(af[i][0], af[i][1], af[i][2], af[i][3],
                      sa + (uint32_t)((wm0 + i * 16 + a_row) * AROWB
                                      + ks * 32 + a_cb));
#pragma unroll
            for (int jp = 0; jp < 2; jp++)
                ldsm4(bf[jp][0], bf[jp][1], bf[jp][2], bf[jp][3],
                      sb2 + (uint32_t)((wn0 + jp * 16 + b_row) * AROWB
                                       + ks * 32 + b_cb));
#pragma unroll
            for (int i = 0; i < 4; i++)
#pragma unroll
                for (int j = 0; j < 4; j++)
                    mma16816(acc[i][j], af[i][0], af[i][1], af[i][2], af[i][3],
                             bf[j >> 1][(j & 1) * 2], bf[j >> 1][(j & 1) * 2 + 1]);
        }
        __syncthreads();
        if (c + 3 < NCH) LOAD_CHUNK(c + 3);
    }

    // ---- epilogue ----
    const int mrow = lane >> 2;
    const int ncol = (lane & 3) * 2;
#pragma unroll
    for (int i = 0; i < 4; i++) {
        const int gmA = m0 + wm0 + i * 16 + mrow;
        const int gmB = gmA + 8;
        const float tpA = (float)(gmA & (T_SEQ - 1));
        const float tpB = (float)(gmB & (T_SEQ - 1));
#pragma unroll
        for (int j = 0; j < 4; j++) {
            const int gc = n0 + wn0 + j * 8 + ncol;
            float x0 = acc[i][j][0], x1 = acc[i][j][1];
            float y0 = acc[i][j][2], y1 = acc[i][j][3];
            if (rotary) {
                const int p = (gc & 63) >> 1;
                const float f = g_invf[p];
                float angA = __fmul_rn(tpA, f);
                float angB = __fmul_rn(tpB, f);
                double dA = (double)angA;
                double rA = dA - floor(dA * 0.15915494309189535) * 6.283185307179586;
                double dB = (double)angB;
                double rB = dB - floor(dB * 0.15915494309189535) * 6.283185307179586;
                float sA = sinf((float)rA), cA = cosf((float)rA);
                float sB = sinf((float)rB), cB = cosf((float)rB);
                float t0 = x0 * cA - x1 * sA;
                float t1 = x1 * cA + x0 * sA;
                float u0 = y0 * cB - y1 * sB;
                float u1 = y1 * cB + y0 * sB;
                x0 = t0; x1 = t1; y0 = u0; y1 = u1;
            }
            const int hh = gc >> 6, d = gc & 63;
            if (csel == 0) {            // Q: [Qh | Ql], pre-scaled 1/8
                x0 *= 0.125f; x1 *= 0.125f; y0 *= 0.125f; y1 *= 0.125f;
                uint32_t hA, lA, hB, lB;
                splitH(x0, x1, hA, lA);
                splitH(y0, y1, hB, lB);
                __half* rA2 = q2 + ((size_t)gmA * NHEADS + hh) * 128 + d;
                __half* rB2 = q2 + ((size_t)gmB * NHEADS + hh) * 128 + d;
                *(uint32_t*)(rA2)      = hA;
                *(uint32_t*)(rA2 + 64) = lA;
                *(uint32_t*)(rB2)      = hB;
                *(uint32_t*)(rB2 + 64) = lB;
            } else if (csel == 1) {     // K: Kh only
                *(uint32_t*)(k2 + ((size_t)gmA * NHEADS + hh) * 64 + d) =
                    pk_h2(__float2half_rn(x0), __float2half_rn(x1));
                *(uint32_t*)(k2 + ((size_t)gmB * NHEADS + hh) * 64 + d) =
                    pk_h2(__float2half_rn(y0), __float2half_rn(y1));
            } else if (csel == 2) {     // V: Vh only
                *(uint32_t*)(v2 + (size_t)gmA * EMB + gc) =
                    pk_h2(__float2half_rn(x0), __float2half_rn(x1));
                *(uint32_t*)(v2 + (size_t)gmB * EMB + gc) =
                    pk_h2(__float2half_rn(y0), __float2half_rn(y1));
            } else {                    // final fp32 output
                *(float2*)(Cexp + (size_t)gmA * EMB + gc) = make_float2(x0, x1);
                *(float2*)(Cexp + (size_t)gmB * EMB + gc) = make_float2(y0, y1);
            }
        }
    }
#undef LOAD_CHUNK
}

// ---------------------------------------------------------------------------
// Banded flash attention, fp16 mma. Block = (64 queries, head, batch), 4 warps.
// QK^T: 64x64 over logical k=128 ([Qh|Ql] vs [Kh|Kh], Kh smem reused).
// PV: [Ph|Pl] x Vh (V smem reused for both terms).
// Output written as [Oh | Ol] fp16 rows of a_at.
// ---------------------------------------------------------------------------
#define QPITCH 272   // 128 fp16 (256B) + 16B pad
#define KPITCH 144   // 64 fp16 (128B) + 16B pad
#define SM_Q   0
#define SM_K   (64 * QPITCH)             // 17408
#define SM_V   (SM_K + 64 * KPITCH)      // 26624
#define SM_ATT (SM_V + 64 * KPITCH)      // 35840 bytes

__global__ __launch_bounds__(128) void attn_mma() {
    const int qt = blockIdx.x, h = blockIdx.y, b = blockIdx.z;
    const int t = threadIdx.x;
    const int wid = t >> 5, lane = t & 31;
    const int qbase = qt * 64;

    extern __shared__ char smraw[];
    char* smp = smraw;
    const uint32_t sb = smem_u32(smraw);

    // ---- load Q' tile (64 x 128 fp16) once ----
    for (int i = t; i < 64 * 16; i += 128) {
        int r = i >> 4, c = i & 15;
        const uint4* src = (const uint4*)(q2 +
            ((size_t)(b * T_SEQ + qbase + r) * NHEADS + h) * 128);
        *(uint4*)(smp + SM_Q + r * QPITCH + c * 16) = src[c];
    }

    float m0r = -3.0e38f, m1r = -3.0e38f, l0r = 0.0f, l1r = 0.0f;
    float o[8][4];
#pragma unroll
    for (int j = 0; j < 8; j++)
#pragma unroll
        for (int u = 0; u < 4; u++) o[j][u] = 0.0f;

    const int kt_lo = (qt - 4 > 0) ? (qt - 4) : 0;
    const int kt_hi = (qt + 4 < 31) ? (qt + 4) : 31;

    const int r0g = qbase + 16 * wid + (lane >> 2);
    const int coff = 2 * (lane & 3);

    for (int kt = kt_lo; kt <= kt_hi; kt++) {
        const int kbase = kt * 64;
        __syncthreads();
        // ---- load Kh (64x64) and Vh (64x64) ----
        for (int i = t; i < 64 * 8; i += 128) {
            int r = i >> 3, c = i & 7;
            const uint4* srck = (const uint4*)(k2 +
                ((size_t)(b * T_SEQ + kbase + r) * NHEADS + h) * 64);
            *(uint4*)(smp + SM_K + r * KPITCH + c * 16) = srck[c];
            size_t g = (size_t)(b * T_SEQ + kbase + r) * EMB + h * 64;
            *(uint4*)(smp + SM_V + r * KPITCH + c * 16) =
                ((const uint4*)(v2 + g))[c];
        }
        __syncthreads();

        // ---- S = Q' K'^T: Qh.Kh + Ql.Kh ----
        float s[8][4];
#pragma unroll
        for (int j = 0; j < 8; j++)
#pragma unroll
            for (int u = 0; u < 4; u++) s[j][u] = 0.0f;

        const uint32_t aAddrBase = sb + SM_Q
            + (uint32_t)((16 * wid + (lane & 15)) * QPITCH + (lane >> 4) * 16);
        const int bRow = (lane & 7) + ((lane >> 4) << 3);
        const uint32_t bAddrBase = sb + SM_K
            + (uint32_t)(bRow * KPITCH + (((lane >> 3) & 1) << 4));

#pragma unroll
        for (int ks = 0; ks < 4; ks++) {
            uint32_t ah0, ah1, ah2, ah3, al0, al1, al2, al3;
            ldsm4(ah0, ah1, ah2, ah3, aAddrBase + ks * 32);
            ldsm4(al0, al1, al2, al3, aAddrBase + 128 + ks * 32);
#pragma unroll
            for (int g = 0; g < 4; g++) {
                uint32_t b0, b1, b2, b3;
                ldsm4(b0, b1, b2, b3,
                      bAddrBase + (uint32_t)(g * 16 * KPITCH + ks * 32));
                mma16816(s[2 * g],     ah0, ah1, ah2, ah3, b0, b1);
                mma16816(s[2 * g + 1], ah0, ah1, ah2, ah3, b2, b3);
                mma16816(s[2 * g],     al0, al1, al2, al3, b0, b1);
                mma16816(s[2 * g + 1], al0, al1, al2, al3, b2, b3);
            }
        }

        // ---- band mask ----
#pragma unroll
        for (int j = 0; j < 8; j++) {
            int c0 = kbase + 8 * j + coff;
            int d00 = r0g - c0, d01 = r0g - (c0 + 1);
            if (d00 > WHALF || d00 < -WHALF) s[j][0] = -1.0e30f;
            if (d01 > WHALF || d01 < -WHALF) s[j][1] = -1.0e30f;
            int d10 = d00 + 8, d11 = d01 + 8;
            if (d10 > WHALF || d10 < -WHALF) s[j][2] = -1.0e30f;
            if (d11 > WHALF || d11 < -WHALF) s[j][3] = -1.0e30f;
        }

        // ---- online softmax ----
        float mx0 = -1.0e30f, mx1 = -1.0e30f;
#pragma unroll
        for (int j = 0; j < 8; j++) {
            mx0 = fmaxf(mx0, fmaxf(s[j][0], s[j][1]));
            mx1 = fmaxf(mx1, fmaxf(s[j][2], s[j][3]));
        }
        mx0 = fmaxf(mx0, __shfl_xor_sync(0xffffffffu, mx0, 1));
        mx0 = fmaxf(mx0, __shfl_xor_sync(0xffffffffu, mx0, 2));
        mx1 = fmaxf(mx1, __shfl_xor_sync(0xffffffffu, mx1, 1));
        mx1 = fmaxf(mx1, __shfl_xor_sync(0xffffffffu, mx1, 2));
        float mn0 = fmaxf(m0r, mx0), mn1 = fmaxf(m1r, mx1);
        float cor0 = __expf(m0r - mn0), cor1 = __expf(m1r - mn1);
        m0r = mn0; m1r = mn1;

        float rs0 = 0.0f, rs1 = 0.0f;
#pragma unroll
        for (int j = 0; j < 8; j++) {
            s[j][0] = __expf(s[j][0] - mn0);
            s[j][1] = __expf(s[j][1] - mn0);
            s[j][2] = __expf(s[j][2] - mn1);
            s[j][3] = __expf(s[j][3] - mn1);
            rs0 += s[j][0] + s[j][1];
            rs1 += s[j][2] + s[j][3];
        }
        rs0 += __shfl_xor_sync(0xffffffffu, rs0, 1);
        rs0 += __shfl_xor_sync(0xffffffffu, rs0, 2);
        rs1 += __shfl_xor_sync(0xffffffffu, rs1, 1);
        rs1 += __shfl_xor_sync(0xffffffffu, rs1, 2);
        l0r = l0r * cor0 + rs0;
        l1r = l1r * cor1 + rs1;

#pragma unroll
        for (int j = 0; j < 8; j++) {
            o[j][0] *= cor0; o[j][1] *= cor0;
            o[j][2] *= cor1; o[j][3] *= cor1;
        }

        // ---- P -> fp16 hi/lo A-fragments ----
        uint32_t ph[4][4], pl[4][4];
#pragma unroll
        for (int ks2 = 0; ks2 < 4; ks2++) {
            int j0 = 2 * ks2, j1 = j0 + 1;
            splitH(s[j0][0], s[j0][1], ph[ks2][0], pl[ks2][0]);
            splitH(s[j0][2], s[j0][3], ph[ks2][1], pl[ks2][1]);
            splitH(s[j1][0], s[j1][1], ph[ks2][2], pl[ks2][2]);
            splitH(s[j1][2], s[j1][3], ph[ks2][3], pl[ks2][3]);
        }

        // ---- PV: out += Ph*Vh + Pl*Vh ----
        const uint32_t vAddrBase =
            (uint32_t)((lane & 15) * KPITCH + (lane >> 4) * 16);
#pragma unroll
        for (int ks2 = 0; ks2 < 4; ks2++) {
            uint32_t voff = vAddrBase + (uint32_t)(ks2 * 16 * KPITCH);
#pragma unroll
            for (int g = 0; g < 4; g++) {
                uint32_t v0, v1, v2r, v3;
                ldsm4t(v0, v1, v2r, v3, sb + SM_V + voff + g * 32);
                mma16816(o[2 * g],     ph[ks2][0], ph[ks2][1], ph[ks2][2],
                         ph[ks2][3], v0, v1);
                mma16816(o[2 * g + 1], ph[ks2][0], ph[ks2][1], ph[ks2][2],
                         ph[ks2][3], v2r, v3);
                mma16816(o[2 * g],     pl[ks2][0], pl[ks2][1], pl[ks2][2],
                         pl[ks2][3], v0, v1);
                mma16816(o[2 * g + 1], pl[ks2][0], pl[ks2][1], pl[ks2][2],
                         pl[ks2][3], v2r, v3);
            }
        }
    }

    // ---- finalize: write [Oh | Ol] rows of a_at ----
    const float inv0 = 1.0f / l0r, inv1 = 1.0f / l1r;
    const size_t mA = (size_t)(b * T_SEQ) + qbase + 16 * wid + (lane >> 2);
    const size_t mB = mA + 8;
    __half* rowA = a_at + mA * K2 + h * 64 + coff;
    __half* rowB = a_at + mB * K2 + h * 64 + coff;
#pragma unroll
    for (int j = 0; j < 8; j++) {
        uint32_t hA, lA, hB, lB;
        splitH(o[j][0] * inv0, o[j][1] * inv0, hA, lA);
        splitH(o[j][2] * inv1, o[j][3] * inv1, hB, lB);
        *(uint32_t*)(rowA + 8 * j)        = hA;
        *(uint32_t*)(rowA + 8 * j + 1024) = lA;
        *(uint32_t*)(rowB + 8 * j)        = hB;
        *(uint32_t*)(rowB + 8 * j + 1024) = lB;
    }
}

// ---------------------------------------------------------------------------
// Launch
// ---------------------------------------------------------------------------
extern "C" void kernel_launch(void* const* d_in, const int* in_sizes, int n_in,
                              void* d_out, int out_size)
{
    const float* xq  = (const float*)d_in[0];
    const float* xkv = (const float*)d_in[1];
    const float* Wq  = (const float*)d_in[2];
    const float* Wk  = (const float*)d_in[3];
    const float* Wv  = (const float*)d_in[4];
    const float* Wo  = (const float*)d_in[5];
    float* out = (float*)d_out;

    init_invf_kernel<<<1, 32>>>();
    conv_in_kernel<<<4096, 256>>>(xq, 0);
    conv_in_kernel<<<4096, 256>>>(xkv, 1);
    dim3 wtb(32, 32);
    conv_w_kernel<<<dim3(32, 32), wtb>>>(Wq, 0);
    conv_w_kernel<<<dim3(32, 32), wtb>>>(Wk, 1);
    conv_w_kernel<<<dim3(32, 32), wtb>>>(Wv, 2);
    conv_w_kernel<<<dim3(32, 32), wtb>>>(Wo, 3);

    const int gemm_smem = NSTAGE * STG;   // 61440
    cudaFuncSetAttribute(mma_gemm, cudaFuncAttributeMaxDynamicSharedMemorySize,
                         gemm_smem);
    dim3 gg(EMB / 128, MTOT / 128);       // (8, 64)

    mma_gemm<<<gg, 256, gemm_smem>>>(nullptr, 0, 0, 0, 1);   // Q (+rotary, x1/8)
    mma_gemm<<<gg, 256, gemm_smem>>>(nullptr, 1, 1, 1, 1);   // K (+rotary)
    mma_gemm<<<gg, 256, gemm_smem>>>(nullptr, 1, 2, 2, 0);   // V

    cudaFuncSetAttribute(attn_mma, cudaFuncAttributeMaxDynamicSharedMemorySize,
                         SM_ATT);
    attn_mma<<<dim3(T_SEQ / 64, NHEADS, BATCH), 128, SM_ATT>>>();

    mma_gemm<<<gg, 256, gemm_smem>>>(out, 2, 3, 3, 0);       // O-proj
}

// round 6
// speedup vs baseline: 3.7712x; 1.3565x over previous
#include <cuda_runtime.h>
#include <cuda_fp16.h>
#include <math.h>
#include <stdint.h>

#define BATCH   4
#define T_SEQ   2048
#define EMB     1024
#define NHEADS  16
#define HDIM    64
#define WHALF   256
#define MTOT    (BATCH * T_SEQ)      // 8192
#define K2      2048                 // O-GEMM split K ([Oh|Ol])
#define BK      32
#define AROWB   80                   // padded row: 32 fp16 (64B) + 16B pad
#define ASTG    (128 * AROWB)
#define STG     (2 * ASTG)
#define NSTAGE  3

// ---------------------------------------------------------------------------
// Scratch (static device globals; cudaMalloc forbidden)
// ---------------------------------------------------------------------------
__device__ __half a_q [(size_t)MTOT * EMB];   // Xh (single plane)
__device__ __half a_kv[(size_t)MTOT * EMB];
__device__ __half a_at[(size_t)MTOT * K2];    // attn out [Oh | Ol]
__device__ __half w_q[EMB * EMB];             // Wh, [N][K] K-major
__device__ __half w_k[EMB * EMB];
__device__ __half w_v[EMB * EMB];
__device__ __half w_o[EMB * EMB];
// attention operands (single fp16)
__device__ __half q2[(size_t)MTOT * NHEADS * 64];   // [m][h][Qh] (x 1/8)
__device__ __half k2[(size_t)MTOT * NHEADS * 64];   // [m][h][Kh]
__device__ __half v2[(size_t)MTOT * EMB];           // [m][h*64+d] Vh
__device__ float g_invf[32];

// ---------------------------------------------------------------------------
// PTX helpers (sm_103 base ISA only)
// ---------------------------------------------------------------------------
__device__ __forceinline__ uint32_t smem_u32(const void* p) {
    uint32_t a;
    asm("{ .reg .u64 t; cvta.to.shared.u64 t, %1; cvt.u32.u64 %0, t; }"
        : "=r"(a) : "l"(p));
    return a;
}
__device__ __forceinline__ void cp16(uint32_t dst, const void* src) {
    asm volatile("cp.async.cg.shared.global [%0], [%1], 16;"
                 :: "r"(dst), "l"(src) : "memory");
}
__device__ __forceinline__ void cp_commit() {
    asm volatile("cp.async.commit_group;" ::: "memory");
}
__device__ __forceinline__ void ldsm4(uint32_t& r0, uint32_t& r1,
                                      uint32_t& r2, uint32_t& r3, uint32_t addr) {
    asm volatile("ldmatrix.sync.aligned.m8n8.x4.shared.b16 {%0,%1,%2,%3}, [%4];"
                 : "=r"(r0), "=r"(r1), "=r"(r2), "=r"(r3) : "r"(addr));
}
__device__ __forceinline__ void ldsm4t(uint32_t& r0, uint32_t& r1,
                                       uint32_t& r2, uint32_t& r3, uint32_t addr) {
    asm volatile("ldmatrix.sync.aligned.m8n8.x4.trans.shared.b16 {%0,%1,%2,%3}, [%4];"
                 : "=r"(r0), "=r"(r1), "=r"(r2), "=r"(r3) : "r"(addr));
}
__device__ __forceinline__ void mma16816(float* c, uint32_t a0, uint32_t a1,
                                         uint32_t a2, uint32_t a3,
                                         uint32_t b0, uint32_t b1) {
    asm volatile(
        "mma.sync.aligned.m16n8k16.row.col.f32.f16.f16.f32 "
        "{%0,%1,%2,%3}, {%4,%5,%6,%7}, {%8,%9}, {%0,%1,%2,%3};"
        : "+f"(c[0]), "+f"(c[1]), "+f"(c[2]), "+f"(c[3])
        : "r"(a0), "r"(a1), "r"(a2), "r"(a3), "r"(b0), "r"(b1));
}
__device__ __forceinline__ uint32_t pk_h2(__half a, __half b) {
    return (uint32_t)__half_as_ushort(a) |
           ((uint32_t)__half_as_ushort(b) << 16);
}
__device__ __forceinline__ void splitH(float x0, float x1,
                                       uint32_t& hp, uint32_t& lp) {
    __half h0 = __float2half_rn(x0);
    __half h1 = __float2half_rn(x1);
    __half l0 = __float2half_rn(x0 - __half2float(h0));
    __half l1 = __float2half_rn(x1 - __half2float(h1));
    hp = pk_h2(h0, h1);
    lp = pk_h2(l0, l1);
}

// ---------------------------------------------------------------------------
// Conversion kernels
// ---------------------------------------------------------------------------
__global__ void init_invf_kernel() {
    int p = threadIdx.x;
    if (p < 32) g_invf[p] = (float)pow(10000.0, -(double)p / 32.0);
}

// inputs [8192,1024] fp32 -> Xh fp16 (single plane)
__global__ __launch_bounds__(256) void conv_in_kernel(const float* __restrict__ X,
                                                      int which) {
    __half* A = which ? a_kv : a_q;
    for (size_t i = (size_t)blockIdx.x * blockDim.x + threadIdx.x;
         i < (size_t)MTOT * EMB; i += (size_t)gridDim.x * blockDim.x) {
        A[i] = __float2half_rn(X[i]);
    }
}

// W [1024 K,1024 N] fp32 -> Wh fp16 [1024 N][1024 K] (transposed)
__global__ void conv_w_kernel(const float* __restrict__ W, int which) {
    __half* O = (which == 0) ? w_q : (which == 1) ? w_k
                : (which == 2) ? w_v : w_o;
    __shared__ float tile[32][33];
    int tx = threadIdx.x, ty = threadIdx.y;
    tile[ty][tx] = W[(size_t)(blockIdx.y * 32 + ty) * EMB + blockIdx.x * 32 + tx];
    __syncthreads();
    int n = blockIdx.x * 32 + ty;
    int k = blockIdx.y * 32 + tx;
    O[(size_t)n * EMB + k] = __float2half_rn(tile[tx][ty]);
}

// ---------------------------------------------------------------------------
// mma.sync fp16 GEMM, 128x128 CTA tile, 8 warps, BK=32, 3-stage cp.async.
//   nch:  number of K chunks (32 for proj, 64 for O-GEMM)
//   krow: A row length in elements (1024 proj, 2048 O)
//   bdup: B chunk index = c & 31 (for the duplicated-B split K extension)
// Epilogues: csel 0 -> q2 (x1/8, rotary), 1 -> k2 (rotary), 2 -> v2,
//            3 -> fp32 Cexp
// ---------------------------------------------------------------------------
__global__ __launch_bounds__(256) void mma_gemm(float* __restrict__ Cexp,
                                                int asel, int bsel, int csel,
                                                int rotary, int nch, int krow,
                                                int bdup) {
    const __half* Ag = (asel == 0) ? a_q : (asel == 1) ? a_kv : a_at;
    const __half* Bg = (bsel == 0) ? w_q : (bsel == 1) ? w_k
                       : (bsel == 2) ? w_v : w_o;

    extern __shared__ char smraw[];
    const uint32_t sb = smem_u32(smraw);
    const int t = threadIdx.x;
    const int wid = t >> 5, lane = t & 31;
    const int m0 = blockIdx.y * 128, n0 = blockIdx.x * 128;
    const int wm0 = (wid & 1) * 64;
    const int wn0 = (wid >> 1) * 32;

    const char* Ab = (const char*)(Ag + (size_t)m0 * krow);
    const char* Bb = (const char*)(Bg + (size_t)n0 * EMB);

    const int r0i = (2 * t) >> 2, s0i = (2 * t) & 3;
    const int r1i = (2 * t + 1) >> 2, s1i = (2 * t + 1) & 3;

#define LOAD_CHUNK(c)                                                          \
    do {                                                                       \
        int _bc = bdup ? ((c) & 31) : (c);                                     \
        uint32_t _sa = sb + ((c) % NSTAGE) * STG;                              \
        uint32_t _sb2 = _sa + ASTG;                                            \
        size_t _ga0 = (size_t)r0i * (krow * 2) + (size_t)(c) * 64 + s0i * 16;  \
        size_t _ga1 = (size_t)r1i * (krow * 2) + (size_t)(c) * 64 + s1i * 16;  \
        size_t _gb0 = (size_t)r0i * (EMB * 2) + (size_t)_bc * 64 + s0i * 16;   \
        size_t _gb1 = (size_t)r1i * (EMB * 2) + (size_t)_bc * 64 + s1i * 16;   \
        cp16(_sa + r0i * AROWB + s0i * 16, Ab + _ga0);                         \
        cp16(_sa + r1i * AROWB + s1i * 16, Ab + _ga1);                         \
        cp16(_sb2 + r0i * AROWB + s0i * 16, Bb + _gb0);                        \
        cp16(_sb2 + r1i * AROWB + s1i * 16, Bb + _gb1);                        \
        cp_commit();                                                           \
    } while (0)

    float acc[4][4][4];
#pragma unroll
    for (int i = 0; i < 4; i++)
#pragma unroll
        for (int j = 0; j < 4; j++)
#pragma unroll
            for (int u = 0; u < 4; u++) acc[i][j][u] = 0.0f;

    LOAD_CHUNK(0); LOAD_CHUNK(1); LOAD_CHUNK(2);

    const int lq = lane >> 3, lr = lane & 7;
    const int a_row = (lq & 1) * 8 + lr;
    const int a_cb  = (lq >> 1) * 16;
    const int b_row = (lq >> 1) * 8 + lr;
    const int b_cb  = (lq & 1) * 16;

    for (int c = 0; c < nch; c++) {
        int pend = nch - 1 - c; if (pend > 2) pend = 2;
        if (pend == 2)      asm volatile("cp.async.wait_group 2;" ::: "memory");
        else if (pend == 1) asm volatile("cp.async.wait_group 1;" ::: "memory");
        else                asm volatile("cp.async.wait_group 0;" ::: "memory");
        __syncthreads();

        const uint32_t sa  = sb + (c % NSTAGE) * STG;
        const uint32_t sb2 = sa + ASTG;

#pragma unroll
        for (int ks = 0; ks < 2; ks++) {
            uint32_t af[4][4], bf[2][4];
#pragma unroll
            for (int i = 0; i < 4; i++)
                ldsm4(af[i][0], af[i][1], af[i][2], af[i][3],
                      sa + (uint32_t)((wm0 + i * 16 + a_row) * AROWB
                                      + ks * 32 + a_cb));
#pragma unroll
            for (int jp = 0; jp < 2; jp++)
                ldsm4(bf[jp][0], bf[jp][1], bf[jp][2], bf[jp][3],
                      sb2 + (uint32_t)((wn0 + jp * 16 + b_row) * AROWB
                                       + ks * 32 + b_cb));
#pragma unroll
            for (int i = 0; i < 4; i++)
#pragma unroll
                for (int j = 0; j < 4; j++)
                    mma16816(acc[i][j], af[i][0], af[i][1], af[i][2], af[i][3],
                             bf[j >> 1][(j & 1) * 2], bf[j >> 1][(j & 1) * 2 + 1]);
        }
        __syncthreads();
        if (c + 3 < nch) LOAD_CHUNK(c + 3);
    }

    // ---- epilogue ----
    const int mrow = lane >> 2;
    const int ncol = (lane & 3) * 2;
#pragma unroll
    for (int i = 0; i < 4; i++) {
        const int gmA = m0 + wm0 + i * 16 + mrow;
        const int gmB = gmA + 8;
        const float tpA = (float)(gmA & (T_SEQ - 1));
        const float tpB = (float)(gmB & (T_SEQ - 1));
#pragma unroll
        for (int j = 0; j < 4; j++) {
            const int gc = n0 + wn0 + j * 8 + ncol;
            float x0 = acc[i][j][0], x1 = acc[i][j][1];
            float y0 = acc[i][j][2], y1 = acc[i][j][3];
            if (rotary) {
                const int p = (gc & 63) >> 1;
                const float f = g_invf[p];
                float angA = __fmul_rn(tpA, f);
                float angB = __fmul_rn(tpB, f);
                double dA = (double)angA;
                double rA = dA - floor(dA * 0.15915494309189535) * 6.283185307179586;
                double dB = (double)angB;
                double rB = dB - floor(dB * 0.15915494309189535) * 6.283185307179586;
                float sA = sinf((float)rA), cA = cosf((float)rA);
                float sB = sinf((float)rB), cB = cosf((float)rB);
                float t0 = x0 * cA - x1 * sA;
                float t1 = x1 * cA + x0 * sA;
                float u0 = y0 * cB - y1 * sB;
                float u1 = y1 * cB + y0 * sB;
                x0 = t0; x1 = t1; y0 = u0; y1 = u1;
            }
            const int hh = gc >> 6, d = gc & 63;
            if (csel == 0 || csel == 1) {   // Q or K -> single fp16
                if (csel == 0) { x0 *= 0.125f; x1 *= 0.125f;
                                 y0 *= 0.125f; y1 *= 0.125f; }
                __half* dst = (csel == 0) ? q2 : k2;
                *(uint32_t*)(dst + ((size_t)gmA * NHEADS + hh) * 64 + d) =
                    pk_h2(__float2half_rn(x0), __float2half_rn(x1));
                *(uint32_t*)(dst + ((size_t)gmB * NHEADS + hh) * 64 + d) =
                    pk_h2(__float2half_rn(y0), __float2half_rn(y1));
            } else if (csel == 2) {         // V -> single fp16
                *(uint32_t*)(v2 + (size_t)gmA * EMB + gc) =
                    pk_h2(__float2half_rn(x0), __float2half_rn(x1));
                *(uint32_t*)(v2 + (size_t)gmB * EMB + gc) =
                    pk_h2(__float2half_rn(y0), __float2half_rn(y1));
            } else {                        // final fp32 output
                *(float2*)(Cexp + (size_t)gmA * EMB + gc) = make_float2(x0, x1);
                *(float2*)(Cexp + (size_t)gmB * EMB + gc) = make_float2(y0, y1);
            }
        }
    }
#undef LOAD_CHUNK
}

// ---------------------------------------------------------------------------
// Banded flash attention, fp16 mma. Block = (64 queries, head, batch), 4 warps.
// QK^T: single term Qh.Kh (k=64). PV: [Ph|Pl] x Vh.
// Output written as [Oh | Ol] fp16 rows of a_at.
// ---------------------------------------------------------------------------
#define KPITCH 144   // 64 fp16 (128B) + 16B pad
#define SM_Q   0
#define SM_K   (64 * KPITCH)             // 9216
#define SM_V   (SM_K + 64 * KPITCH)      // 18432
#define SM_ATT (SM_V + 64 * KPITCH)      // 27648 bytes

__global__ __launch_bounds__(128) void attn_mma() {
    const int qt = blockIdx.x, h = blockIdx.y, b = blockIdx.z;
    const int t = threadIdx.x;
    const int wid = t >> 5, lane = t & 31;
    const int qbase = qt * 64;

    extern __shared__ char smraw[];
    char* smp = smraw;
    const uint32_t sb = smem_u32(smraw);

    // ---- load Qh tile (64 x 64 fp16) once ----
    for (int i = t; i < 64 * 8; i += 128) {
        int r = i >> 3, c = i & 7;
        const uint4* src = (const uint4*)(q2 +
            ((size_t)(b * T_SEQ + qbase + r) * NHEADS + h) * 64);
        *(uint4*)(smp + SM_Q + r * KPITCH + c * 16) = src[c];
    }

    float m0r = -3.0e38f, m1r = -3.0e38f, l0r = 0.0f, l1r = 0.0f;
    float o[8][4];
#pragma unroll
    for (int j = 0; j < 8; j++)
#pragma unroll
        for (int u = 0; u < 4; u++) o[j][u] = 0.0f;

    const int kt_lo = (qt - 4 > 0) ? (qt - 4) : 0;
    const int kt_hi = (qt + 4 < 31) ? (qt + 4) : 31;

    const int r0g = qbase + 16 * wid + (lane >> 2);
    const int coff = 2 * (lane & 3);

    for (int kt = kt_lo; kt <= kt_hi; kt++) {
        const int kbase = kt * 64;
        __syncthreads();
        // ---- load Kh (64x64) and Vh (64x64) ----
        for (int i = t; i < 64 * 8; i += 128) {
            int r = i >> 3, c = i & 7;
            const uint4* srck = (const uint4*)(k2 +
                ((size_t)(b * T_SEQ + kbase + r) * NHEADS + h) * 64);
            *(uint4*)(smp + SM_K + r * KPITCH + c * 16) = srck[c];
            size_t g = (size_t)(b * T_SEQ + kbase + r) * EMB + h * 64;
            *(uint4*)(smp + SM_V + r * KPITCH + c * 16) =
                ((const uint4*)(v2 + g))[c];
        }
        __syncthreads();

        // ---- S = Qh Kh^T (k = 64) ----
        float s[8][4];
#pragma unroll
        for (int j = 0; j < 8; j++)
#pragma unroll
            for (int u = 0; u < 4; u++) s[j][u] = 0.0f;

        const uint32_t aAddrBase = sb + SM_Q
            + (uint32_t)((16 * wid + (lane & 15)) * KPITCH + (lane >> 4) * 16);
        const int bRow = (lane & 7) + ((lane >> 4) << 3);
        const uint32_t bAddrBase = sb + SM_K
            + (uint32_t)(bRow * KPITCH + (((lane >> 3) & 1) << 4));

#pragma unroll
        for (int ks = 0; ks < 4; ks++) {
            uint32_t a0, a1, a2, a3;
            ldsm4(a0, a1, a2, a3, aAddrBase + ks * 32);
#pragma unroll
            for (int g = 0; g < 4; g++) {
                uint32_t b0, b1, b2, b3;
                ldsm4(b0, b1, b2, b3,
                      bAddrBase + (uint32_t)(g * 16 * KPITCH + ks * 32));
                mma16816(s[2 * g],     a0, a1, a2, a3, b0, b1);
                mma16816(s[2 * g + 1], a0, a1, a2, a3, b2, b3);
            }
        }

        // ---- band mask ----
#pragma unroll
        for (int j = 0; j < 8; j++) {
            int c0 = kbase + 8 * j + coff;
            int d00 = r0g - c0, d01 = r0g - (c0 + 1);
            if (d00 > WHALF || d00 < -WHALF) s[j][0] = -1.0e30f;
            if (d01 > WHALF || d01 < -WHALF) s[j][1] = -1.0e30f;
            int d10 = d00 + 8, d11 = d01 + 8;
            if (d10 > WHALF || d10 < -WHALF) s[j][2] = -1.0e30f;
            if (d11 > WHALF || d11 < -WHALF) s[j][3] = -1.0e30f;
        }

        // ---- online softmax ----
        float mx0 = -1.0e30f, mx1 = -1.0e30f;
#pragma unroll
        for (int j = 0; j < 8; j++) {
            mx0 = fmaxf(mx0, fmaxf(s[j][0], s[j][1]));
            mx1 = fmaxf(mx1, fmaxf(s[j][2], s[j][3]));
        }
        mx0 = fmaxf(mx0, __shfl_xor_sync(0xffffffffu, mx0, 1));
        mx0 = fmaxf(mx0, __shfl_xor_sync(0xffffffffu, mx0, 2));
        mx1 = fmaxf(mx1, __shfl_xor_sync(0xffffffffu, mx1, 1));
        mx1 = fmaxf(mx1, __shfl_xor_sync(0xffffffffu, mx1, 2));
        float mn0 = fmaxf(m0r, mx0), mn1 = fmaxf(m1r, mx1);
        float cor0 = __expf(m0r - mn0), cor1 = __expf(m1r - mn1);
        m0r = mn0; m1r = mn1;

        float rs0 = 0.0f, rs1 = 0.0f;
#pragma unroll
        for (int j = 0; j < 8; j++) {
            s[j][0] = __expf(s[j][0] - mn0);
            s[j][1] = __expf(s[j][1] - mn0);
            s[j][2] = __expf(s[j][2] - mn1);
            s[j][3] = __expf(s[j][3] - mn1);
            rs0 += s[j][0] + s[j][1];
            rs1 += s[j][2] + s[j][3];
        }
        rs0 += __shfl_xor_sync(0xffffffffu, rs0, 1);
        rs0 += __shfl_xor_sync(0xffffffffu, rs0, 2);
        rs1 += __shfl_xor_sync(0xffffffffu, rs1, 1);
        rs1 += __shfl_xor_sync(0xffffffffu, rs1, 2);
        l0r = l0r * cor0 + rs0;
        l1r = l1r * cor1 + rs1;

#pragma unroll
        for (int j = 0; j < 8; j++) {
            o[j][0] *= cor0; o[j][1] *= cor0;
            o[j][2] *= cor1; o[j][3] *= cor1;
        }

        // ---- P -> fp16 hi/lo A-fragments ----
        uint32_t ph[4][4], pl[4][4];
#pragma unroll
        for (int ks2 = 0; ks2 < 4; ks2++) {
            int j0 = 2 * ks2, j1 = j0 + 1;
            splitH(s[j0][0], s[j0][1], ph[ks2][0], pl[ks2][0]);
            splitH(s[j0][2], s[j0][3], ph[ks2][1], pl[ks2][1]);
            splitH(s[j1][0], s[j1][1], ph[ks2][2], pl[ks2][2]);
            splitH(s[j1][2], s[j1][3], ph[ks2][3], pl[ks2][3]);
        }

        // ---- PV: out += Ph*Vh + Pl*Vh ----
        const uint32_t vAddrBase =
            (uint32_t)((lane & 15) * KPITCH + (lane >> 4) * 16);
#pragma unroll
        for (int ks2 = 0; ks2 < 4; ks2++) {
            uint32_t voff = vAddrBase + (uint32_t)(ks2 * 16 * KPITCH);
#pragma unroll
            for (int g = 0; g < 4; g++) {
                uint32_t v0, v1, v2r, v3;
                ldsm4t(v0, v1, v2r, v3, sb + SM_V + voff + g * 32);
                mma16816(o[2 * g],     ph[ks2][0], ph[ks2][1], ph[ks2][2],
                         ph[ks2][3], v0, v1);
                mma16816(o[2 * g + 1], ph[ks2][0], ph[ks2][1], ph[ks2][2],
                         ph[ks2][3], v2r, v3);
                mma16816(o[2 * g],     pl[ks2][0], pl[ks2][1], pl[ks2][2],
                         pl[ks2][3], v0, v1);
                mma16816(o[2 * g + 1], pl[ks2][0], pl[ks2][1], pl[ks2][2],
                         pl[ks2][3], v2r, v3);
            }
        }
    }

    // ---- finalize: write [Oh | Ol] rows of a_at ----
    const float inv0 = 1.0f / l0r, inv1 = 1.0f / l1r;
    const size_t mA = (size_t)(b * T_SEQ) + qbase + 16 * wid + (lane >> 2);
    const size_t mB = mA + 8;
    __half* rowA = a_at + mA * K2 + h * 64 + coff;
    __half* rowB = a_at + mB * K2 + h * 64 + coff;
#pragma unroll
    for (int j = 0; j < 8; j++) {
        uint32_t hA, lA, hB, lB;
        splitH(o[j][0] * inv0, o[j][1] * inv0, hA, lA);
        splitH(o[j][2] * inv1, o[j][3] * inv1, hB, lB);
        *(uint32_t*)(rowA + 8 * j)        = hA;
        *(uint32_t*)(rowA + 8 * j + 1024) = lA;
        *(uint32_t*)(rowB + 8 * j)        = hB;
        *(uint32_t*)(rowB + 8 * j + 1024) = lB;
    }
}

// ---------------------------------------------------------------------------
// Launch
// ---------------------------------------------------------------------------
extern "C" void kernel_launch(void* const* d_in, const int* in_sizes, int n_in,
                              void* d_out, int out_size)
{
    const float* xq  = (const float*)d_in[0];
    const float* xkv = (const float*)d_in[1];
    const float* Wq  = (const float*)d_in[2];
    const float* Wk  = (const float*)d_in[3];
    const float* Wv  = (const float*)d_in[4];
    const float* Wo  = (const float*)d_in[5];
    float* out = (float*)d_out;

    init_invf_kernel<<<1, 32>>>();
    conv_in_kernel<<<2048, 256>>>(xq, 0);
    conv_in_kernel<<<2048, 256>>>(xkv, 1);
    dim3 wtb(32, 32);
    conv_w_kernel<<<dim3(32, 32), wtb>>>(Wq, 0);
    conv_w_kernel<<<dim3(32, 32), wtb>>>(Wk, 1);
    conv_w_kernel<<<dim3(32, 32), wtb>>>(Wv, 2);
    conv_w_kernel<<<dim3(32, 32), wtb>>>(Wo, 3);

    const int gemm_smem = NSTAGE * STG;   // 61440
    cudaFuncSetAttribute(mma_gemm, cudaFuncAttributeMaxDynamicSharedMemorySize,
                         gemm_smem);
    dim3 gg(EMB / 128, MTOT / 128);       // (8, 64)

    // projections: single-pass K=1024 (32 chunks)
    mma_gemm<<<gg, 256, gemm_smem>>>(nullptr, 0, 0, 0, 1, 32, EMB, 0);  // Q
    mma_gemm<<<gg, 256, gemm_smem>>>(nullptr, 1, 1, 1, 1, 32, EMB, 0);  // K
    mma_gemm<<<gg, 256, gemm_smem>>>(nullptr, 1, 2, 2, 0, 32, EMB, 0);  // V

    cudaFuncSetAttribute(attn_mma, cudaFuncAttributeMaxDynamicSharedMemorySize,
                         SM_ATT);
    attn_mma<<<dim3(T_SEQ / 64, NHEADS, BATCH), 128, SM_ATT>>>();

    // O-projection: 2-term split K=2048 (64 chunks, duplicated B)
    mma_gemm<<<gg, 256, gemm_smem>>>(out, 2, 3, 3, 0, 64, K2, 1);
}

// round 7
// speedup vs baseline: 4.7464x; 1.2586x over previous
#include <cuda_runtime.h>
#include <cuda_fp16.h>
#include <math.h>
#include <stdint.h>

#define BATCH   4
#define T_SEQ   2048
#define EMB     1024
#define NHEADS  16
#define HDIM    64
#define WHALF   256
#define MTOT    (BATCH * T_SEQ)      // 8192
#define BK      32
#define AROWB   80                   // padded row: 32 fp16 (64B) + 16B pad
#define ASTG    (128 * AROWB)
#define STG     (2 * ASTG)
#define NSTAGE  3

// ---------------------------------------------------------------------------
// Scratch (static device globals; cudaMalloc forbidden)
// ---------------------------------------------------------------------------
__device__ __half a_q [(size_t)MTOT * EMB];   // Xh
__device__ __half a_kv[(size_t)MTOT * EMB];
__device__ __half a_at[(size_t)MTOT * EMB];   // attn out Oh (single plane)
__device__ __half w_q[EMB * EMB];             // Wh, [N][K] K-major
__device__ __half w_k[EMB * EMB];
__device__ __half w_v[EMB * EMB];
__device__ __half w_o[EMB * EMB];
// attention operands (single fp16)
__device__ __half q2[(size_t)MTOT * NHEADS * 64];   // [m][h][Qh] (x 1/8)
__device__ __half k2[(size_t)MTOT * NHEADS * 64];   // [m][h][Kh]
__device__ __half v2[(size_t)MTOT * EMB];           // [m][h*64+d] Vh
__device__ float g_invf[32];

// ---------------------------------------------------------------------------
// PTX helpers (sm_103 base ISA only)
// ---------------------------------------------------------------------------
__device__ __forceinline__ uint32_t smem_u32(const void* p) {
    uint32_t a;
    asm("{ .reg .u64 t; cvta.to.shared.u64 t, %1; cvt.u32.u64 %0, t; }"
        : "=r"(a) : "l"(p));
    return a;
}
__device__ __forceinline__ void cp16(uint32_t dst, const void* src) {
    asm volatile("cp.async.cg.shared.global [%0], [%1], 16;"
                 :: "r"(dst), "l"(src) : "memory");
}
__device__ __forceinline__ void cp_commit() {
    asm volatile("cp.async.commit_group;" ::: "memory");
}
__device__ __forceinline__ void ldsm4(uint32_t& r0, uint32_t& r1,
                                      uint32_t& r2, uint32_t& r3, uint32_t addr) {
    asm volatile("ldmatrix.sync.aligned.m8n8.x4.shared.b16 {%0,%1,%2,%3}, [%4];"
                 : "=r"(r0), "=r"(r1), "=r"(r2), "=r"(r3) : "r"(addr));
}
__device__ __forceinline__ void ldsm4t(uint32_t& r0, uint32_t& r1,
                                       uint32_t& r2, uint32_t& r3, uint32_t addr) {
    asm volatile("ldmatrix.sync.aligned.m8n8.x4.trans.shared.b16 {%0,%1,%2,%3}, [%4];"
                 : "=r"(r0), "=r"(r1), "=r"(r2), "=r"(r3) : "r"(addr));
}
__device__ __forceinline__ void mma16816(float* c, uint32_t a0, uint32_t a1,
                                         uint32_t a2, uint32_t a3,
                                         uint32_t b0, uint32_t b1) {
    asm volatile(
        "mma.sync.aligned.m16n8k16.row.col.f32.f16.f16.f32 "
        "{%0,%1,%2,%3}, {%4,%5,%6,%7}, {%8,%9}, {%0,%1,%2,%3};"
        : "+f"(c[0]), "+f"(c[1]), "+f"(c[2]), "+f"(c[3])
        : "r"(a0), "r"(a1), "r"(a2), "r"(a3), "r"(b0), "r"(b1));
}
__device__ __forceinline__ uint32_t pk_h2(__half a, __half b) {
    return (uint32_t)__half_as_ushort(a) |
           ((uint32_t)__half_as_ushort(b) << 16);
}
__device__ __forceinline__ uint32_t cvt_h2(float x0, float x1) {
    return pk_h2(__float2half_rn(x0), __float2half_rn(x1));
}

// ---------------------------------------------------------------------------
// Conversion kernels
// ---------------------------------------------------------------------------
__global__ void init_invf_kernel() {
    int p = threadIdx.x;
    if (p < 32) g_invf[p] = (float)pow(10000.0, -(double)p / 32.0);
}

// inputs [8192,1024] fp32 -> Xh fp16, vectorized float4 -> half4
__global__ __launch_bounds__(256) void conv_in_kernel(const float* __restrict__ X,
                                                      int which) {
    __half* A = which ? a_kv : a_q;
    const size_t n4 = (size_t)MTOT * EMB / 4;
    for (size_t i = (size_t)blockIdx.x * blockDim.x + threadIdx.x;
         i < n4; i += (size_t)gridDim.x * blockDim.x) {
        float4 v = ((const float4*)X)[i];
        uint2 o;
        o.x = cvt_h2(v.x, v.y);
        o.y = cvt_h2(v.z, v.w);
        ((uint2*)A)[i] = o;
    }
}

// W [1024 K,1024 N] fp32 -> Wh fp16 [1024 N][1024 K] (transposed)
__global__ void conv_w_kernel(const float* __restrict__ W, int which) {
    __half* O = (which == 0) ? w_q : (which == 1) ? w_k
                : (which == 2) ? w_v : w_o;
    __shared__ float tile[32][33];
    int tx = threadIdx.x, ty = threadIdx.y;
    tile[ty][tx] = W[(size_t)(blockIdx.y * 32 + ty) * EMB + blockIdx.x * 32 + tx];
    __syncthreads();
    int n = blockIdx.x * 32 + ty;
    int k = blockIdx.y * 32 + tx;
    O[(size_t)n * EMB + k] = __float2half_rn(tile[tx][ty]);
}

// ---------------------------------------------------------------------------
// mma.sync fp16 GEMM, 128x128 CTA tile, 8 warps, BK=32 (32 chunks), 3-stage.
// Epilogues: csel 0 -> q2 (x1/8, rotary), 1 -> k2 (rotary), 2 -> v2,
//            3 -> fp32 Cexp
// ---------------------------------------------------------------------------
__global__ __launch_bounds__(256) void mma_gemm(float* __restrict__ Cexp,
                                                int asel, int bsel, int csel,
                                                int rotary) {
    const __half* Ag = (asel == 0) ? a_q : (asel == 1) ? a_kv : a_at;
    const __half* Bg = (bsel == 0) ? w_q : (bsel == 1) ? w_k
                       : (bsel == 2) ? w_v : w_o;
    const int nch = 32;

    extern __shared__ char smraw[];
    const uint32_t sb = smem_u32(smraw);
    const int t = threadIdx.x;
    const int wid = t >> 5, lane = t & 31;
    const int m0 = blockIdx.y * 128, n0 = blockIdx.x * 128;
    const int wm0 = (wid & 1) * 64;
    const int wn0 = (wid >> 1) * 32;

    const char* Ab = (const char*)(Ag + (size_t)m0 * EMB);
    const char* Bb = (const char*)(Bg + (size_t)n0 * EMB);

    const int r0i = (2 * t) >> 2, s0i = (2 * t) & 3;
    const int r1i = (2 * t + 1) >> 2, s1i = (2 * t + 1) & 3;

#define LOAD_CHUNK(c)                                                          \
    do {                                                                       \
        uint32_t _sa = sb + ((c) % NSTAGE) * STG;                              \
        uint32_t _sb2 = _sa + ASTG;                                            \
        size_t _ga0 = (size_t)r0i * (EMB * 2) + (size_t)(c) * 64 + s0i * 16;   \
        size_t _ga1 = (size_t)r1i * (EMB * 2) + (size_t)(c) * 64 + s1i * 16;   \
        cp16(_sa + r0i * AROWB + s0i * 16, Ab + _ga0);                         \
        cp16(_sa + r1i * AROWB + s1i * 16, Ab + _ga1);                         \
        cp16(_sb2 + r0i * AROWB + s0i * 16, Bb + _ga0);                        \
        cp16(_sb2 + r1i * AROWB + s1i * 16, Bb + _ga1);                        \
        cp_commit();                                                           \
    } while (0)

    float acc[4][4][4];
#pragma unroll
    for (int i = 0; i < 4; i++)
#pragma unroll
        for (int j = 0; j < 4; j++)
#pragma unroll
            for (int u = 0; u < 4; u++) acc[i][j][u] = 0.0f;

    LOAD_CHUNK(0); LOAD_CHUNK(1); LOAD_CHUNK(2);

    const int lq = lane >> 3, lr = lane & 7;
    const int a_row = (lq & 1) * 8 + lr;
    const int a_cb  = (lq >> 1) * 16;
    const int b_row = (lq >> 1) * 8 + lr;
    const int b_cb  = (lq & 1) * 16;

    for (int c = 0; c < nch; c++) {
        int pend = nch - 1 - c; if (pend > 2) pend = 2;
        if (pend == 2)      asm volatile("cp.async.wait_group 2;" ::: "memory");
        else if (pend == 1) asm volatile("cp.async.wait_group 1;" ::: "memory");
        else                asm volatile("cp.async.wait_group 0;" ::: "memory");
        __syncthreads();

        const uint32_t sa  = sb + (c % NSTAGE) * STG;
        const uint32_t sb2 = sa + ASTG;

#pragma unroll
        for (int ks = 0; ks < 2; ks++) {
            uint32_t af[4][4], bf[2][4];
#pragma unroll
            for (int i = 0; i < 4; i++)
                ldsm4(af[i][0], af[i][1], af[i][2], af[i][3],
                      sa + (uint32_t)((wm0 + i * 16 + a_row) * AROWB
                                      + ks * 32 + a_cb));
#pragma unroll
            for (int jp = 0; jp < 2; jp++)
                ldsm4(bf[jp][0], bf[jp][1], bf[jp][2], bf[jp][3],
                      sb2 + (uint32_t)((wn0 + jp * 16 + b_row) * AROWB
                                       + ks * 32 + b_cb));
#pragma unroll
            for (int i = 0; i < 4; i++)
#pragma unroll
                for (int j = 0; j < 4; j++)
                    mma16816(acc[i][j], af[i][0], af[i][1], af[i][2], af[i][3],
                             bf[j >> 1][(j & 1) * 2], bf[j >> 1][(j & 1) * 2 + 1]);
        }
        __syncthreads();
        if (c + 3 < nch) LOAD_CHUNK(c + 3);
    }

    // ---- epilogue ----
    const int mrow = lane >> 2;
    const int ncol = (lane & 3) * 2;
#pragma unroll
    for (int i = 0; i < 4; i++) {
        const int gmA = m0 + wm0 + i * 16 + mrow;
        const int gmB = gmA + 8;
        const float tpA = (float)(gmA & (T_SEQ - 1));
        const float tpB = (float)(gmB & (T_SEQ - 1));
#pragma unroll
        for (int j = 0; j < 4; j++) {
            const int gc = n0 + wn0 + j * 8 + ncol;
            float x0 = acc[i][j][0], x1 = acc[i][j][1];
            float y0 = acc[i][j][2], y1 = acc[i][j][3];
            if (rotary) {
                const int p = (gc & 63) >> 1;
                const float f = g_invf[p];
                float angA = __fmul_rn(tpA, f);
                float angB = __fmul_rn(tpB, f);
                double dA = (double)angA;
                double rA = dA - floor(dA * 0.15915494309189535) * 6.283185307179586;
                double dB = (double)angB;
                double rB = dB - floor(dB * 0.15915494309189535) * 6.283185307179586;
                float sA = sinf((float)rA), cA = cosf((float)rA);
                float sB = sinf((float)rB), cB = cosf((float)rB);
                float t0 = x0 * cA - x1 * sA;
                float t1 = x1 * cA + x0 * sA;
                float u0 = y0 * cB - y1 * sB;
                float u1 = y1 * cB + y0 * sB;
                x0 = t0; x1 = t1; y0 = u0; y1 = u1;
            }
            const int hh = gc >> 6, d = gc & 63;
            if (csel == 0 || csel == 1) {   // Q or K -> single fp16
                if (csel == 0) { x0 *= 0.125f; x1 *= 0.125f;
                                 y0 *= 0.125f; y1 *= 0.125f; }
                __half* dst = (csel == 0) ? q2 : k2;
                *(uint32_t*)(dst + ((size_t)gmA * NHEADS + hh) * 64 + d) =
                    cvt_h2(x0, x1);
                *(uint32_t*)(dst + ((size_t)gmB * NHEADS + hh) * 64 + d) =
                    cvt_h2(y0, y1);
            } else if (csel == 2) {         // V -> single fp16
                *(uint32_t*)(v2 + (size_t)gmA * EMB + gc) = cvt_h2(x0, x1);
                *(uint32_t*)(v2 + (size_t)gmB * EMB + gc) = cvt_h2(y0, y1);
            } else {                        // final fp32 output
                *(float2*)(Cexp + (size_t)gmA * EMB + gc) = make_float2(x0, x1);
                *(float2*)(Cexp + (size_t)gmB * EMB + gc) = make_float2(y0, y1);
            }
        }
    }
#undef LOAD_CHUNK
}

// ---------------------------------------------------------------------------
// Banded flash attention, fp16 mma. Block = (64 queries, head, batch), 4 warps.
// QK^T: Qh.Kh (k=64). PV: Ph x Vh (single term).
// Output written as Oh fp16 rows of a_at.
// ---------------------------------------------------------------------------
#define KPITCH 144   // 64 fp16 (128B) + 16B pad
#define SM_Q   0
#define SM_K   (64 * KPITCH)             // 9216
#define SM_V   (SM_K + 64 * KPITCH)      // 18432
#define SM_ATT (SM_V + 64 * KPITCH)      // 27648 bytes

__global__ __launch_bounds__(128) void attn_mma() {
    const int qt = blockIdx.x, h = blockIdx.y, b = blockIdx.z;
    const int t = threadIdx.x;
    const int wid = t >> 5, lane = t & 31;
    const int qbase = qt * 64;

    extern __shared__ char smraw[];
    char* smp = smraw;
    const uint32_t sb = smem_u32(smraw);

    // ---- load Qh tile (64 x 64 fp16) once ----
    for (int i = t; i < 64 * 8; i += 128) {
        int r = i >> 3, c = i & 7;
        const uint4* src = (const uint4*)(q2 +
            ((size_t)(b * T_SEQ + qbase + r) * NHEADS + h) * 64);
        *(uint4*)(smp + SM_Q + r * KPITCH + c * 16) = src[c];
    }

    float m0r = -3.0e38f, m1r = -3.0e38f, l0r = 0.0f, l1r = 0.0f;
    float o[8][4];
#pragma unroll
    for (int j = 0; j < 8; j++)
#pragma unroll
        for (int u = 0; u < 4; u++) o[j][u] = 0.0f;

    const int kt_lo = (qt - 4 > 0) ? (qt - 4) : 0;
    const int kt_hi = (qt + 4 < 31) ? (qt + 4) : 31;

    const int r0g = qbase + 16 * wid + (lane >> 2);
    const int coff = 2 * (lane & 3);

    for (int kt = kt_lo; kt <= kt_hi; kt++) {
        const int kbase = kt * 64;
        __syncthreads();
        // ---- load Kh (64x64) and Vh (64x64) ----
        for (int i = t; i < 64 * 8; i += 128) {
            int r = i >> 3, c = i & 7;
            const uint4* srck = (const uint4*)(k2 +
                ((size_t)(b * T_SEQ + kbase + r) * NHEADS + h) * 64);
            *(uint4*)(smp + SM_K + r * KPITCH + c * 16) = srck[c];
            size_t g = (size_t)(b * T_SEQ + kbase + r) * EMB + h * 64;
            *(uint4*)(smp + SM_V + r * KPITCH + c * 16) =
                ((const uint4*)(v2 + g))[c];
        }
        __syncthreads();

        // ---- S = Qh Kh^T (k = 64) ----
        float s[8][4];
#pragma unroll
        for (int j = 0; j < 8; j++)
#pragma unroll
            for (int u = 0; u < 4; u++) s[j][u] = 0.0f;

        const uint32_t aAddrBase = sb + SM_Q
            + (uint32_t)((16 * wid + (lane & 15)) * KPITCH + (lane >> 4) * 16);
        const int bRow = (lane & 7) + ((lane >> 4) << 3);
        const uint32_t bAddrBase = sb + SM_K
            + (uint32_t)(bRow * KPITCH + (((lane >> 3) & 1) << 4));

#pragma unroll
        for (int ks = 0; ks < 4; ks++) {
            uint32_t a0, a1, a2, a3;
            ldsm4(a0, a1, a2, a3, aAddrBase + ks * 32);
#pragma unroll
            for (int g = 0; g < 4; g++) {
                uint32_t b0, b1, b2, b3;
                ldsm4(b0, b1, b2, b3,
                      bAddrBase + (uint32_t)(g * 16 * KPITCH + ks * 32));
                mma16816(s[2 * g],     a0, a1, a2, a3, b0, b1);
                mma16816(s[2 * g + 1], a0, a1, a2, a3, b2, b3);
            }
        }

        // ---- band mask ----
#pragma unroll
        for (int j = 0; j < 8; j++) {
            int c0 = kbase + 8 * j + coff;
            int d00 = r0g - c0, d01 = r0g - (c0 + 1);
            if (d00 > WHALF || d00 < -WHALF) s[j][0] = -1.0e30f;
            if (d01 > WHALF || d01 < -WHALF) s[j][1] = -1.0e30f;
            int d10 = d00 + 8, d11 = d01 + 8;
            if (d10 > WHALF || d10 < -WHALF) s[j][2] = -1.0e30f;
            if (d11 > WHALF || d11 < -WHALF) s[j][3] = -1.0e30f;
        }

        // ---- online softmax ----
        float mx0 = -1.0e30f, mx1 = -1.0e30f;
#pragma unroll
        for (int j = 0; j < 8; j++) {
            mx0 = fmaxf(mx0, fmaxf(s[j][0], s[j][1]));
            mx1 = fmaxf(mx1, fmaxf(s[j][2], s[j][3]));
        }
        mx0 = fmaxf(mx0, __shfl_xor_sync(0xffffffffu, mx0, 1));
        mx0 = fmaxf(mx0, __shfl_xor_sync(0xffffffffu, mx0, 2));
        mx1 = fmaxf(mx1, __shfl_xor_sync(0xffffffffu, mx1, 1));
        mx1 = fmaxf(mx1, __shfl_xor_sync(0xffffffffu, mx1, 2));
        float mn0 = fmaxf(m0r, mx0), mn1 = fmaxf(m1r, mx1);
        float cor0 = __expf(m0r - mn0), cor1 = __expf(m1r - mn1);
        m0r = mn0; m1r = mn1;

        float rs0 = 0.0f, rs1 = 0.0f;
#pragma unroll
        for (int j = 0; j < 8; j++) {
            s[j][0] = __expf(s[j][0] - mn0);
            s[j][1] = __expf(s[j][1] - mn0);
            s[j][2] = __expf(s[j][2] - mn1);
            s[j][3] = __expf(s[j][3] - mn1);
            rs0 += s[j][0] + s[j][1];
            rs1 += s[j][2] + s[j][3];
        }
        rs0 += __shfl_xor_sync(0xffffffffu, rs0, 1);
        rs0 += __shfl_xor_sync(0xffffffffu, rs0, 2);
        rs1 += __shfl_xor_sync(0xffffffffu, rs1, 1);
        rs1 += __shfl_xor_sync(0xffffffffu, rs1, 2);
        l0r = l0r * cor0 + rs0;
        l1r = l1r * cor1 + rs1;

#pragma unroll
        for (int j = 0; j < 8; j++) {
            o[j][0] *= cor0; o[j][1] *= cor0;
            o[j][2] *= cor1; o[j][3] *= cor1;
        }

        // ---- P -> fp16 A-fragments (single term) ----
        uint32_t ph[4][4];
#pragma unroll
        for (int ks2 = 0; ks2 < 4; ks2++) {
            int j0 = 2 * ks2, j1 = j0 + 1;
            ph[ks2][0] = cvt_h2(s[j0][0], s[j0][1]);
            ph[ks2][1] = cvt_h2(s[j0][2], s[j0][3]);
            ph[ks2][2] = cvt_h2(s[j1][0], s[j1][1]);
            ph[ks2][3] = cvt_h2(s[j1][2], s[j1][3]);
        }

        // ---- PV: out += Ph*Vh ----
        const uint32_t vAddrBase =
            (uint32_t)((lane & 15) * KPITCH + (lane >> 4) * 16);
#pragma unroll
        for (int ks2 = 0; ks2 < 4; ks2++) {
            uint32_t voff = vAddrBase + (uint32_t)(ks2 * 16 * KPITCH);
#pragma unroll
            for (int g = 0; g < 4; g++) {
                uint32_t v0, v1, v2r, v3;
                ldsm4t(v0, v1, v2r, v3, sb + SM_V + voff + g * 32);
                mma16816(o[2 * g],     ph[ks2][0], ph[ks2][1], ph[ks2][2],
                         ph[ks2][3], v0, v1);
                mma16816(o[2 * g + 1], ph[ks2][0], ph[ks2][1], ph[ks2][2],
                         ph[ks2][3], v2r, v3);
            }
        }
    }

    // ---- finalize: write Oh rows of a_at ----
    const float inv0 = 1.0f / l0r, inv1 = 1.0f / l1r;
    const size_t mA = (size_t)(b * T_SEQ) + qbase + 16 * wid + (lane >> 2);
    const size_t mB = mA + 8;
    __half* rowA = a_at + mA * EMB + h * 64 + coff;
    __half* rowB = a_at + mB * EMB + h * 64 + coff;
#pragma unroll
    for (int j = 0; j < 8; j++) {
        *(uint32_t*)(rowA + 8 * j) = cvt_h2(o[j][0] * inv0, o[j][1] * inv0);
        *(uint32_t*)(rowB + 8 * j) = cvt_h2(o[j][2] * inv1, o[j][3] * inv1);
    }
}

// ---------------------------------------------------------------------------
// Launch
// ---------------------------------------------------------------------------
extern "C" void kernel_launch(void* const* d_in, const int* in_sizes, int n_in,
                              void* d_out, int out_size)
{
    const float* xq  = (const float*)d_in[0];
    const float* xkv = (const float*)d_in[1];
    const float* Wq  = (const float*)d_in[2];
    const float* Wk  = (const float*)d_in[3];
    const float* Wv  = (const float*)d_in[4];
    const float* Wo  = (const float*)d_in[5];
    float* out = (float*)d_out;

    init_invf_kernel<<<1, 32>>>();
    conv_in_kernel<<<1024, 256>>>(xq, 0);
    conv_in_kernel<<<1024, 256>>>(xkv, 1);
    dim3 wtb(32, 32);
    conv_w_kernel<<<dim3(32, 32), wtb>>>(Wq, 0);
    conv_w_kernel<<<dim3(32, 32), wtb>>>(Wk, 1);
    conv_w_kernel<<<dim3(32, 32), wtb>>>(Wv, 2);
    conv_w_kernel<<<dim3(32, 32), wtb>>>(Wo, 3);

    const int gemm_smem = NSTAGE * STG;   // 61440
    cudaFuncSetAttribute(mma_gemm, cudaFuncAttributeMaxDynamicSharedMemorySize,
                         gemm_smem);
    dim3 gg(EMB / 128, MTOT / 128);       // (8, 64)

    mma_gemm<<<gg, 256, gemm_smem>>>(nullptr, 0, 0, 0, 1);   // Q (+rotary, x1/8)
    mma_gemm<<<gg, 256, gemm_smem>>>(nullptr, 1, 1, 1, 1);   // K (+rotary)
    mma_gemm<<<gg, 256, gemm_smem>>>(nullptr, 1, 2, 2, 0);   // V

    cudaFuncSetAttribute(attn_mma, cudaFuncAttributeMaxDynamicSharedMemorySize,
                         SM_ATT);
    attn_mma<<<dim3(T_SEQ / 64, NHEADS, BATCH), 128, SM_ATT>>>();

    mma_gemm<<<gg, 256, gemm_smem>>>(out, 2, 3, 3, 0);       // O-proj
}

// round 8
// speedup vs baseline: 4.7469x; 1.0001x over previous
#include <cuda_runtime.h>
#include <cuda_fp16.h>
#include <math.h>
#include <stdint.h>

#define BATCH   4
#define T_SEQ   2048
#define EMB     1024
#define NHEADS  16
#define HDIM    64
#define WHALF   256
#define MTOT    (BATCH * T_SEQ)      // 8192
#define BK      32
#define AROWB   80                   // padded row: 32 fp16 (64B) + 16B pad
#define ASTG    (128 * AROWB)        // 10240 B per operand per stage
#define STG     (2 * ASTG)           // 20480 B per stage
#define NSTAGE  3

// ---------------------------------------------------------------------------
// Scratch (static device globals; cudaMalloc forbidden)
// ---------------------------------------------------------------------------
__device__ __half a_q [(size_t)MTOT * EMB];   // Xh
__device__ __half a_kv[(size_t)MTOT * EMB];
__device__ __half a_at[(size_t)MTOT * EMB];   // attn out Oh
__device__ __half w_q[EMB * EMB];             // Wh, [N][K] K-major
__device__ __half w_k[EMB * EMB];
__device__ __half w_v[EMB * EMB];
__device__ __half w_o[EMB * EMB];
// attention operands (single fp16)
__device__ __half q2[(size_t)MTOT * NHEADS * 64];   // [m][h][Qh] (x 1/8)
__device__ __half k2[(size_t)MTOT * NHEADS * 64];   // [m][h][Kh]
__device__ __half v2[(size_t)MTOT * EMB];           // [m][h*64+d] Vh
__device__ float g_invf[32];

// ---------------------------------------------------------------------------
// PTX helpers (sm_103 base ISA only)
// ---------------------------------------------------------------------------
__device__ __forceinline__ uint32_t smem_u32(const void* p) {
    uint32_t a;
    asm("{ .reg .u64 t; cvta.to.shared.u64 t, %1; cvt.u32.u64 %0, t; }"
        : "=r"(a) : "l"(p));
    return a;
}
__device__ __forceinline__ void cp16(uint32_t dst, const void* src) {
    asm volatile("cp.async.cg.shared.global [%0], [%1], 16;"
                 :: "r"(dst), "l"(src) : "memory");
}
__device__ __forceinline__ void cp_commit() {
    asm volatile("cp.async.commit_group;" ::: "memory");
}
__device__ __forceinline__ void ldsm4(uint32_t& r0, uint32_t& r1,
                                      uint32_t& r2, uint32_t& r3, uint32_t addr) {
    asm volatile("ldmatrix.sync.aligned.m8n8.x4.shared.b16 {%0,%1,%2,%3}, [%4];"
                 : "=r"(r0), "=r"(r1), "=r"(r2), "=r"(r3) : "r"(addr));
}
__device__ __forceinline__ void ldsm4t(uint32_t& r0, uint32_t& r1,
                                       uint32_t& r2, uint32_t& r3, uint32_t addr) {
    asm volatile("ldmatrix.sync.aligned.m8n8.x4.trans.shared.b16 {%0,%1,%2,%3}, [%4];"
                 : "=r"(r0), "=r"(r1), "=r"(r2), "=r"(r3) : "r"(addr));
}
__device__ __forceinline__ void mma16816(float* c, uint32_t a0, uint32_t a1,
                                         uint32_t a2, uint32_t a3,
                                         uint32_t b0, uint32_t b1) {
    asm volatile(
        "mma.sync.aligned.m16n8k16.row.col.f32.f16.f16.f32 "
        "{%0,%1,%2,%3}, {%4,%5,%6,%7}, {%8,%9}, {%0,%1,%2,%3};"
        : "+f"(c[0]), "+f"(c[1]), "+f"(c[2]), "+f"(c[3])
        : "r"(a0), "r"(a1), "r"(a2), "r"(a3), "r"(b0), "r"(b1));
}
__device__ __forceinline__ uint32_t pk_h2(__half a, __half b) {
    return (uint32_t)__half_as_ushort(a) |
           ((uint32_t)__half_as_ushort(b) << 16);
}
__device__ __forceinline__ uint32_t cvt_h2(float x0, float x1) {
    return pk_h2(__float2half_rn(x0), __float2half_rn(x1));
}

// ---------------------------------------------------------------------------
// Conversion kernels (fused across operands via blockIdx.z)
// ---------------------------------------------------------------------------
__global__ void init_invf_kernel() {
    int p = threadIdx.x;
    if (p < 32) g_invf[p] = (float)pow(10000.0, -(double)p / 32.0);
}

__global__ __launch_bounds__(256) void conv_in_kernel(
    const float* __restrict__ Xq, const float* __restrict__ Xkv) {
    const float* X = blockIdx.z ? Xkv : Xq;
    __half* A = blockIdx.z ? a_kv : a_q;
    const size_t n4 = (size_t)MTOT * EMB / 4;
    for (size_t i = (size_t)blockIdx.x * blockDim.x + threadIdx.x;
         i < n4; i += (size_t)gridDim.x * blockDim.x) {
        float4 v = ((const float4*)X)[i];
        uint2 o;
        o.x = cvt_h2(v.x, v.y);
        o.y = cvt_h2(v.z, v.w);
        ((uint2*)A)[i] = o;
    }
}

__global__ void conv_w_kernel(const float* __restrict__ Wq,
                              const float* __restrict__ Wk,
                              const float* __restrict__ Wv,
                              const float* __restrict__ Wo) {
    const int z = blockIdx.z;
    const float* W = (z == 0) ? Wq : (z == 1) ? Wk : (z == 2) ? Wv : Wo;
    __half* O = (z == 0) ? w_q : (z == 1) ? w_k : (z == 2) ? w_v : w_o;
    __shared__ float tile[32][33];
    int tx = threadIdx.x, ty = threadIdx.y;
    tile[ty][tx] = W[(size_t)(blockIdx.y * 32 + ty) * EMB + blockIdx.x * 32 + tx];
    __syncthreads();
    int n = blockIdx.x * 32 + ty;
    int k = blockIdx.y * 32 + tx;
    O[(size_t)n * EMB + k] = __float2half_rn(tile[tx][ty]);
}

// ---------------------------------------------------------------------------
// mma.sync fp16 GEMM, 128x128 CTA tile, 4 warps (64x64 warp tiles), BK=32,
// 3-stage cp.async, single barrier per chunk.
// csel: <0 -> use blockIdx.z (merged QKV projections); else explicit.
//   0 -> q2 (x1/8, rotary), 1 -> k2 (rotary), 2 -> v2, 3 -> fp32 Cexp (A=a_at)
// ---------------------------------------------------------------------------
__global__ __launch_bounds__(128) void mma_gemm(float* __restrict__ Cexp,
                                                int csel_in) {
    const int csel = (csel_in < 0) ? (int)blockIdx.z : csel_in;
    const int rotary = (csel <= 1);
    const __half* Ag = (csel == 0) ? a_q : (csel == 3) ? a_at : a_kv;
    const __half* Bg = (csel == 0) ? w_q : (csel == 1) ? w_k
                       : (csel == 2) ? w_v : w_o;
    const int nch = 32;

    extern __shared__ char smraw[];
    const uint32_t sb = smem_u32(smraw);
    const int t = threadIdx.x;
    const int wid = t >> 5, lane = t & 31;
    const int m0 = blockIdx.y * 128, n0 = blockIdx.x * 128;
    const int wm0 = (wid & 1) * 64;
    const int wn0 = (wid >> 1) * 64;

    const char* Ab = (const char*)(Ag + (size_t)m0 * EMB);
    const char* Bb = (const char*)(Bg + (size_t)n0 * EMB);

    // loader: 128 threads x 4 slots per operand cover 128 rows x 4 segs
#define LOAD_CHUNK(c)                                                          \
    do {                                                                       \
        uint32_t _sa = sb + ((c) % NSTAGE) * STG;                              \
        uint32_t _sb2 = _sa + ASTG;                                            \
        _Pragma("unroll")                                                      \
        for (int _i = 0; _i < 4; _i++) {                                       \
            int _idx = t + _i * 128;                                           \
            int _row = _idx >> 2, _seg = _idx & 3;                             \
            size_t _g = (size_t)_row * (EMB * 2) + (size_t)(c) * 64            \
                        + _seg * 16;                                           \
            uint32_t _so = (uint32_t)(_row * AROWB + _seg * 16);               \
            cp16(_sa + _so, Ab + _g);                                          \
            cp16(_sb2 + _so, Bb + _g);                                         \
        }                                                                      \
        cp_commit();                                                           \
    } while (0)

    float acc[4][8][4];
#pragma unroll
    for (int i = 0; i < 4; i++)
#pragma unroll
        for (int j = 0; j < 8; j++)
#pragma unroll
            for (int u = 0; u < 4; u++) acc[i][j][u] = 0.0f;

    LOAD_CHUNK(0);
    LOAD_CHUNK(1);

    const int lq = lane >> 3, lr = lane & 7;
    const int a_row = (lq & 1) * 8 + lr;
    const int a_cb  = (lq >> 1) * 16;
    const int b_row = (lq >> 1) * 8 + lr;
    const int b_cb  = (lq & 1) * 16;

    for (int c = 0; c < nch; c++) {
        if (c >= nch - 1) asm volatile("cp.async.wait_group 0;" ::: "memory");
        else              asm volatile("cp.async.wait_group 1;" ::: "memory");
        __syncthreads();
        if (c + 2 < nch) LOAD_CHUNK(c + 2);

        const uint32_t sa  = sb + (c % NSTAGE) * STG;
        const uint32_t sb2 = sa + ASTG;

#pragma unroll
        for (int ks = 0; ks < 2; ks++) {
            uint32_t af[4][4], bf[4][4];
#pragma unroll
            for (int i = 0; i < 4; i++)
                ldsm4(af[i][0], af[i][1], af[i][2], af[i][3],
                      sa + (uint32_t)((wm0 + i * 16 + a_row) * AROWB
                                      + ks * 32 + a_cb));
#pragma unroll
            for (int jp = 0; jp < 4; jp++)
                ldsm4(bf[jp][0], bf[jp][1], bf[jp][2], bf[jp][3],
                      sb2 + (uint32_t)((wn0 + jp * 16 + b_row) * AROWB
                                       + ks * 32 + b_cb));
#pragma unroll
            for (int i = 0; i < 4; i++)
#pragma unroll
                for (int jp = 0; jp < 4; jp++) {
                    mma16816(acc[i][2 * jp], af[i][0], af[i][1], af[i][2],
                             af[i][3], bf[jp][0], bf[jp][1]);
                    mma16816(acc[i][2 * jp + 1], af[i][0], af[i][1], af[i][2],
                             af[i][3], bf[jp][2], bf[jp][3]);
                }
        }
    }

    // ---- epilogue ----
    const int mrow = lane >> 2;
    const int ncol = (lane & 3) * 2;
#pragma unroll
    for (int i = 0; i < 4; i++) {
        const int gmA = m0 + wm0 + i * 16 + mrow;
        const int gmB = gmA + 8;
        const float tpA = (float)(gmA & (T_SEQ - 1));
        const float tpB = (float)(gmB & (T_SEQ - 1));
#pragma unroll
        for (int j = 0; j < 8; j++) {
            const int gc = n0 + wn0 + j * 8 + ncol;
            float x0 = acc[i][j][0], x1 = acc[i][j][1];
            float y0 = acc[i][j][2], y1 = acc[i][j][3];
            if (rotary) {
                const int p = (gc & 63) >> 1;
                const float f = g_invf[p];
                float angA = __fmul_rn(tpA, f);
                float angB = __fmul_rn(tpB, f);
                double dA = (double)angA;
                double rA = dA - floor(dA * 0.15915494309189535) * 6.283185307179586;
                double dB = (double)angB;
                double rB = dB - floor(dB * 0.15915494309189535) * 6.283185307179586;
                float sA = sinf((float)rA), cA = cosf((float)rA);
                float sB = sinf((float)rB), cB = cosf((float)rB);
                float t0 = x0 * cA - x1 * sA;
                float t1 = x1 * cA + x0 * sA;
                float u0 = y0 * cB - y1 * sB;
                float u1 = y1 * cB + y0 * sB;
                x0 = t0; x1 = t1; y0 = u0; y1 = u1;
            }
            const int hh = gc >> 6, d = gc & 63;
            if (csel == 0 || csel == 1) {   // Q or K -> single fp16
                if (csel == 0) { x0 *= 0.125f; x1 *= 0.125f;
                                 y0 *= 0.125f; y1 *= 0.125f; }
                __half* dst = (csel == 0) ? q2 : k2;
                *(uint32_t*)(dst + ((size_t)gmA * NHEADS + hh) * 64 + d) =
                    cvt_h2(x0, x1);
                *(uint32_t*)(dst + ((size_t)gmB * NHEADS + hh) * 64 + d) =
                    cvt_h2(y0, y1);
            } else if (csel == 2) {         // V -> single fp16
                *(uint32_t*)(v2 + (size_t)gmA * EMB + gc) = cvt_h2(x0, x1);
                *(uint32_t*)(v2 + (size_t)gmB * EMB + gc) = cvt_h2(y0, y1);
            } else {                        // final fp32 output
                *(float2*)(Cexp + (size_t)gmA * EMB + gc) = make_float2(x0, x1);
                *(float2*)(Cexp + (size_t)gmB * EMB + gc) = make_float2(y0, y1);
            }
        }
    }
#undef LOAD_CHUNK
}

// ---------------------------------------------------------------------------
// Banded flash attention, fp16 mma. Block = (64 queries, head, batch), 4 warps.
// QK^T: Qh.Kh (k=64). PV: Ph x Vh. Output -> Oh fp16 rows of a_at.
// ---------------------------------------------------------------------------
#define KPITCH 144   // 64 fp16 (128B) + 16B pad
#define SM_Q   0
#define SM_K   (64 * KPITCH)             // 9216
#define SM_V   (SM_K + 64 * KPITCH)      // 18432
#define SM_ATT (SM_V + 64 * KPITCH)      // 27648 bytes

__global__ __launch_bounds__(128) void attn_mma() {
    const int qt = blockIdx.x, h = blockIdx.y, b = blockIdx.z;
    const int t = threadIdx.x;
    const int wid = t >> 5, lane = t & 31;
    const int qbase = qt * 64;

    extern __shared__ char smraw[];
    char* smp = smraw;
    const uint32_t sb = smem_u32(smraw);

    // ---- load Qh tile (64 x 64 fp16) once ----
    for (int i = t; i < 64 * 8; i += 128) {
        int r = i >> 3, c = i & 7;
        const uint4* src = (const uint4*)(q2 +
            ((size_t)(b * T_SEQ + qbase + r) * NHEADS + h) * 64);
        *(uint4*)(smp + SM_Q + r * KPITCH + c * 16) = src[c];
    }

    float m0r = -3.0e38f, m1r = -3.0e38f, l0r = 0.0f, l1r = 0.0f;
    float o[8][4];
#pragma unroll
    for (int j = 0; j < 8; j++)
#pragma unroll
        for (int u = 0; u < 4; u++) o[j][u] = 0.0f;

    const int kt_lo = (qt - 4 > 0) ? (qt - 4) : 0;
    const int kt_hi = (qt + 4 < 31) ? (qt + 4) : 31;

    const int r0g = qbase + 16 * wid + (lane >> 2);
    const int coff = 2 * (lane & 3);

    for (int kt = kt_lo; kt <= kt_hi; kt++) {
        const int kbase = kt * 64;
        __syncthreads();
        // ---- load Kh (64x64) and Vh (64x64) ----
        for (int i = t; i < 64 * 8; i += 128) {
            int r = i >> 3, c = i & 7;
            const uint4* srck = (const uint4*)(k2 +
                ((size_t)(b * T_SEQ + kbase + r) * NHEADS + h) * 64);
            *(uint4*)(smp + SM_K + r * KPITCH + c * 16) = srck[c];
            size_t g = (size_t)(b * T_SEQ + kbase + r) * EMB + h * 64;
            *(uint4*)(smp + SM_V + r * KPITCH + c * 16) =
                ((const uint4*)(v2 + g))[c];
        }
        __syncthreads();

        // ---- S = Qh Kh^T (k = 64) ----
        float s[8][4];
#pragma unroll
        for (int j = 0; j < 8; j++)
#pragma unroll
            for (int u = 0; u < 4; u++) s[j][u] = 0.0f;

        const uint32_t aAddrBase = sb + SM_Q
            + (uint32_t)((16 * wid + (lane & 15)) * KPITCH + (lane >> 4) * 16);
        const int bRow = (lane & 7) + ((lane >> 4) << 3);
        const uint32_t bAddrBase = sb + SM_K
            + (uint32_t)(bRow * KPITCH + (((lane >> 3) & 1) << 4));

#pragma unroll
        for (int ks = 0; ks < 4; ks++) {
            uint32_t a0, a1, a2, a3;
            ldsm4(a0, a1, a2, a3, aAddrBase + ks * 32);
#pragma unroll
            for (int g = 0; g < 4; g++) {
                uint32_t b0, b1, b2, b3;
                ldsm4(b0, b1, b2, b3,
                      bAddrBase + (uint32_t)(g * 16 * KPITCH + ks * 32));
                mma16816(s[2 * g],     a0, a1, a2, a3, b0, b1);
                mma16816(s[2 * g + 1], a0, a1, a2, a3, b2, b3);
            }
        }

        // ---- band mask ----
#pragma unroll
        for (int j = 0; j < 8; j++) {
            int c0 = kbase + 8 * j + coff;
            int d00 = r0g - c0, d01 = r0g - (c0 + 1);
            if (d00 > WHALF || d00 < -WHALF) s[j][0] = -1.0e30f;
            if (d01 > WHALF || d01 < -WHALF) s[j][1] = -1.0e30f;
            int d10 = d00 + 8, d11 = d01 + 8;
            if (d10 > WHALF || d10 < -WHALF) s[j][2] = -1.0e30f;
            if (d11 > WHALF || d11 < -WHALF) s[j][3] = -1.0e30f;
        }

        // ---- online softmax ----
        float mx0 = -1.0e30f, mx1 = -1.0e30f;
#pragma unroll
        for (int j = 0; j < 8; j++) {
            mx0 = fmaxf(mx0, fmaxf(s[j][0], s[j][1]));
            mx1 = fmaxf(mx1, fmaxf(s[j][2], s[j][3]));
        }
        mx0 = fmaxf(mx0, __shfl_xor_sync(0xffffffffu, mx0, 1));
        mx0 = fmaxf(mx0, __shfl_xor_sync(0xffffffffu, mx0, 2));
        mx1 = fmaxf(mx1, __shfl_xor_sync(0xffffffffu, mx1, 1));
        mx1 = fmaxf(mx1, __shfl_xor_sync(0xffffffffu, mx1, 2));
        float mn0 = fmaxf(m0r, mx0), mn1 = fmaxf(m1r, mx1);
        float cor0 = __expf(m0r - mn0), cor1 = __expf(m1r - mn1);
        m0r = mn0; m1r = mn1;

        float rs0 = 0.0f, rs1 = 0.0f;
#pragma unroll
        for (int j = 0; j < 8; j++) {
            s[j][0] = __expf(s[j][0] - mn0);
            s[j][1] = __expf(s[j][1] - mn0);
            s[j][2] = __expf(s[j][2] - mn1);
            s[j][3] = __expf(s[j][3] - mn1);
            rs0 += s[j][0] + s[j][1];
            rs1 += s[j][2] + s[j][3];
        }
        rs0 += __shfl_xor_sync(0xffffffffu, rs0, 1);
        rs0 += __shfl_xor_sync(0xffffffffu, rs0, 2);
        rs1 += __shfl_xor_sync(0xffffffffu, rs1, 1);
        rs1 += __shfl_xor_sync(0xffffffffu, rs1, 2);
        l0r = l0r * cor0 + rs0;
        l1r = l1r * cor1 + rs1;

#pragma unroll
        for (int j = 0; j < 8; j++) {
            o[j][0] *= cor0; o[j][1] *= cor0;
            o[j][2] *= cor1; o[j][3] *= cor1;
        }

        // ---- P -> fp16 A-fragments ----
        uint32_t ph[4][4];
#pragma unroll
        for (int ks2 = 0; ks2 < 4; ks2++) {
            int j0 = 2 * ks2, j1 = j0 + 1;
            ph[ks2][0] = cvt_h2(s[j0][0], s[j0][1]);
            ph[ks2][1] = cvt_h2(s[j0][2], s[j0][3]);
            ph[ks2][2] = cvt_h2(s[j1][0], s[j1][1]);
            ph[ks2][3] = cvt_h2(s[j1][2], s[j1][3]);
        }

        // ---- PV: out += Ph*Vh ----
        const uint32_t vAddrBase =
            (uint32_t)((lane & 15) * KPITCH + (lane >> 4) * 16);
#pragma unroll
        for (int ks2 = 0; ks2 < 4; ks2++) {
            uint32_t voff = vAddrBase + (uint32_t)(ks2 * 16 * KPITCH);
#pragma unroll
            for (int g = 0; g < 4; g++) {
                uint32_t v0, v1, v2r, v3;
                ldsm4t(v0, v1, v2r, v3, sb + SM_V + voff + g * 32);
                mma16816(o[2 * g],     ph[ks2][0], ph[ks2][1], ph[ks2][2],
                         ph[ks2][3], v0, v1);
                mma16816(o[2 * g + 1], ph[ks2][0], ph[ks2][1], ph[ks2][2],
                         ph[ks2][3], v2r, v3);
            }
        }
    }

    // ---- finalize: write Oh rows of a_at ----
    const float inv0 = 1.0f / l0r, inv1 = 1.0f / l1r;
    const size_t mA = (size_t)(b * T_SEQ) + qbase + 16 * wid + (lane >> 2);
    const size_t mB = mA + 8;
    __half* rowA = a_at + mA * EMB + h * 64 + coff;
    __half* rowB = a_at + mB * EMB + h * 64 + coff;
#pragma unroll
    for (int j = 0; j < 8; j++) {
        *(uint32_t*)(rowA + 8 * j) = cvt_h2(o[j][0] * inv0, o[j][1] * inv0);
        *(uint32_t*)(rowB + 8 * j) = cvt_h2(o[j][2] * inv1, o[j][3] * inv1);
    }
}

// ---------------------------------------------------------------------------
// Launch
// ---------------------------------------------------------------------------
extern "C" void kernel_launch(void* const* d_in, const int* in_sizes, int n_in,
                              void* d_out, int out_size)
{
    const float* xq  = (const float*)d_in[0];
    const float* xkv = (const float*)d_in[1];
    const float* Wq  = (const float*)d_in[2];
    const float* Wk  = (const float*)d_in[3];
    const float* Wv  = (const float*)d_in[4];
    const float* Wo  = (const float*)d_in[5];
    float* out = (float*)d_out;

    init_invf_kernel<<<1, 32>>>();
    conv_in_kernel<<<dim3(512, 1, 2), 256>>>(xq, xkv);
    conv_w_kernel<<<dim3(32, 32, 4), dim3(32, 32)>>>(Wq, Wk, Wv, Wo);

    const int gemm_smem = NSTAGE * STG;   // 61440
    cudaFuncSetAttribute(mma_gemm, cudaFuncAttributeMaxDynamicSharedMemorySize,
                         gemm_smem);

    // Q, K, V projections fused into one launch (z = 0,1,2)
    mma_gemm<<<dim3(EMB / 128, MTOT / 128, 3), 128, gemm_smem>>>(nullptr, -1);

    cudaFuncSetAttribute(attn_mma, cudaFuncAttributeMaxDynamicSharedMemorySize,
                         SM_ATT);
    attn_mma<<<dim3(T_SEQ / 64, NHEADS, BATCH), 128, SM_ATT>>>();

    // O-projection
    mma_gemm<<<dim3(EMB / 128, MTOT / 128, 1), 128, gemm_smem>>>(out, 3);
}

// round 9
// speedup vs baseline: 5.4295x; 1.1438x over previous
#include <cuda_runtime.h>
#include <cuda_fp16.h>
#include <math.h>
#include <stdint.h>

#define BATCH   4
#define T_SEQ   2048
#define EMB     1024
#define NHEADS  16
#define HDIM    64
#define WHALF   256
#define MTOT    (BATCH * T_SEQ)      // 8192
#define BK      32
#define AROWB   80                   // padded row: 32 fp16 (64B) + 16B pad
#define ASTG    (128 * AROWB)        // 10240 B per operand per stage
#define STG     (2 * ASTG)           // 20480 B per stage
#define NSTAGE  3

// ---------------------------------------------------------------------------
// Scratch (static device globals; cudaMalloc forbidden)
// ---------------------------------------------------------------------------
__device__ __half a_q [(size_t)MTOT * EMB];   // Xh
__device__ __half a_kv[(size_t)MTOT * EMB];
__device__ __half a_at[(size_t)MTOT * EMB];   // attn out Oh
__device__ __half w_q[EMB * EMB];             // Wh, [N][K] K-major
__device__ __half w_k[EMB * EMB];
__device__ __half w_v[EMB * EMB];
__device__ __half w_o[EMB * EMB];
// attention operands (single fp16)
__device__ __half q2[(size_t)MTOT * NHEADS * 64];   // [m][h][Qh] (x 1/8)
__device__ __half k2[(size_t)MTOT * NHEADS * 64];   // [m][h][Kh]
__device__ __half v2[(size_t)MTOT * EMB];           // [m][h*64+d] Vh
__device__ float g_invf[32];

// ---------------------------------------------------------------------------
// PTX helpers (sm_103 base ISA only)
// ---------------------------------------------------------------------------
__device__ __forceinline__ uint32_t smem_u32(const void* p) {
    uint32_t a;
    asm("{ .reg .u64 t; cvta.to.shared.u64 t, %1; cvt.u32.u64 %0, t; }"
        : "=r"(a) : "l"(p));
    return a;
}
__device__ __forceinline__ void cp16(uint32_t dst, const void* src) {
    asm volatile("cp.async.cg.shared.global [%0], [%1], 16;"
                 :: "r"(dst), "l"(src) : "memory");
}
__device__ __forceinline__ void cp_commit() {
    asm volatile("cp.async.commit_group;" ::: "memory");
}
__device__ __forceinline__ void ldsm4(uint32_t& r0, uint32_t& r1,
                                      uint32_t& r2, uint32_t& r3, uint32_t addr) {
    asm volatile("ldmatrix.sync.aligned.m8n8.x4.shared.b16 {%0,%1,%2,%3}, [%4];"
                 : "=r"(r0), "=r"(r1), "=r"(r2), "=r"(r3) : "r"(addr));
}
__device__ __forceinline__ void ldsm4t(uint32_t& r0, uint32_t& r1,
                                       uint32_t& r2, uint32_t& r3, uint32_t addr) {
    asm volatile("ldmatrix.sync.aligned.m8n8.x4.trans.shared.b16 {%0,%1,%2,%3}, [%4];"
                 : "=r"(r0), "=r"(r1), "=r"(r2), "=r"(r3) : "r"(addr));
}
__device__ __forceinline__ void mma16816(float* c, uint32_t a0, uint32_t a1,
                                         uint32_t a2, uint32_t a3,
                                         uint32_t b0, uint32_t b1) {
    asm volatile(
        "mma.sync.aligned.m16n8k16.row.col.f32.f16.f16.f32 "
        "{%0,%1,%2,%3}, {%4,%5,%6,%7}, {%8,%9}, {%0,%1,%2,%3};"
        : "+f"(c[0]), "+f"(c[1]), "+f"(c[2]), "+f"(c[3])
        : "r"(a0), "r"(a1), "r"(a2), "r"(a3), "r"(b0), "r"(b1));
}
__device__ __forceinline__ uint32_t pk_h2(__half a, __half b) {
    return (uint32_t)__half_as_ushort(a) |
           ((uint32_t)__half_as_ushort(b) << 16);
}
__device__ __forceinline__ uint32_t cvt_h2(float x0, float x1) {
    return pk_h2(__float2half_rn(x0), __float2half_rn(x1));
}

// ---------------------------------------------------------------------------
// Conversion kernels (fused across operands via blockIdx.z)
// ---------------------------------------------------------------------------
__global__ void init_invf_kernel() {
    int p = threadIdx.x;
    if (p < 32) g_invf[p] = (float)pow(10000.0, -(double)p / 32.0);
}

__global__ __launch_bounds__(256) void conv_in_kernel(
    const float* __restrict__ Xq, const float* __restrict__ Xkv) {
    const float* X = blockIdx.z ? Xkv : Xq;
    __half* A = blockIdx.z ? a_kv : a_q;
    const size_t n4 = (size_t)MTOT * EMB / 4;
    for (size_t i = (size_t)blockIdx.x * blockDim.x + threadIdx.x;
         i < n4; i += (size_t)gridDim.x * blockDim.x) {
        float4 v = ((const float4*)X)[i];
        uint2 o;
        o.x = cvt_h2(v.x, v.y);
        o.y = cvt_h2(v.z, v.w);
        ((uint2*)A)[i] = o;
    }
}

__global__ void conv_w_kernel(const float* __restrict__ Wq,
                              const float* __restrict__ Wk,
                              const float* __restrict__ Wv,
                              const float* __restrict__ Wo) {
    const int z = blockIdx.z;
    const float* W = (z == 0) ? Wq : (z == 1) ? Wk : (z == 2) ? Wv : Wo;
    __half* O = (z == 0) ? w_q : (z == 1) ? w_k : (z == 2) ? w_v : w_o;
    __shared__ float tile[32][33];
    int tx = threadIdx.x, ty = threadIdx.y;
    tile[ty][tx] = W[(size_t)(blockIdx.y * 32 + ty) * EMB + blockIdx.x * 32 + tx];
    __syncthreads();
    int n = blockIdx.x * 32 + ty;
    int k = blockIdx.y * 32 + tx;
    O[(size_t)n * EMB + k] = __float2half_rn(tile[tx][ty]);
}

// ---------------------------------------------------------------------------
// mma.sync fp16 GEMM, 128x128 CTA tile, 8 warps (2x4 -> 64x32 warp tiles),
// BK=32, 3-stage cp.async, single barrier per chunk.
// csel: <0 -> use blockIdx.z (merged QKV projections); else explicit.
//   0 -> q2 (x1/8, rotary), 1 -> k2 (rotary), 2 -> v2, 3 -> fp32 Cexp (A=a_at)
// ---------------------------------------------------------------------------
__global__ __launch_bounds__(256) void mma_gemm(float* __restrict__ Cexp,
                                                int csel_in) {
    const int csel = (csel_in < 0) ? (int)blockIdx.z : csel_in;
    const int rotary = (csel <= 1);
    const __half* Ag = (csel == 0) ? a_q : (csel == 3) ? a_at : a_kv;
    const __half* Bg = (csel == 0) ? w_q : (csel == 1) ? w_k
                       : (csel == 2) ? w_v : w_o;
    const int nch = 32;

    extern __shared__ char smraw[];
    const uint32_t sb = smem_u32(smraw);
    const int t = threadIdx.x;
    const int wid = t >> 5, lane = t & 31;
    const int m0 = blockIdx.y * 128, n0 = blockIdx.x * 128;
    const int wm0 = (wid & 1) * 64;
    const int wn0 = (wid >> 1) * 32;

    const char* Ab = (const char*)(Ag + (size_t)m0 * EMB);
    const char* Bb = (const char*)(Bg + (size_t)n0 * EMB);

    const int r0i = (2 * t) >> 2, s0i = (2 * t) & 3;
    const int r1i = (2 * t + 1) >> 2, s1i = (2 * t + 1) & 3;

#define LOAD_CHUNK(c)                                                          \
    do {                                                                       \
        uint32_t _sa = sb + ((c) % NSTAGE) * STG;                              \
        uint32_t _sb2 = _sa + ASTG;                                            \
        size_t _ga0 = (size_t)r0i * (EMB * 2) + (size_t)(c) * 64 + s0i * 16;   \
        size_t _ga1 = (size_t)r1i * (EMB * 2) + (size_t)(c) * 64 + s1i * 16;   \
        cp16(_sa + r0i * AROWB + s0i * 16, Ab + _ga0);                         \
        cp16(_sa + r1i * AROWB + s1i * 16, Ab + _ga1);                         \
        cp16(_sb2 + r0i * AROWB + s0i * 16, Bb + _ga0);                        \
        cp16(_sb2 + r1i * AROWB + s1i * 16, Bb + _ga1);                        \
        cp_commit();                                                           \
    } while (0)

    float acc[4][4][4];
#pragma unroll
    for (int i = 0; i < 4; i++)
#pragma unroll
        for (int j = 0; j < 4; j++)
#pragma unroll
            for (int u = 0; u < 4; u++) acc[i][j][u] = 0.0f;

    LOAD_CHUNK(0);
    LOAD_CHUNK(1);

    const int lq = lane >> 3, lr = lane & 7;
    const int a_row = (lq & 1) * 8 + lr;
    const int a_cb  = (lq >> 1) * 16;
    const int b_row = (lq >> 1) * 8 + lr;
    const int b_cb  = (lq & 1) * 16;

    for (int c = 0; c < nch; c++) {
        if (c >= nch - 1) asm volatile("cp.async.wait_group 0;" ::: "memory");
        else              asm volatile("cp.async.wait_group 1;" ::: "memory");
        __syncthreads();
        if (c + 2 < nch) LOAD_CHUNK(c + 2);

        const uint32_t sa  = sb + (c % NSTAGE) * STG;
        const uint32_t sb2 = sa + ASTG;

#pragma unroll
        for (int ks = 0; ks < 2; ks++) {
            uint32_t af[4][4], bf[2][4];
#pragma unroll
            for (int i = 0; i < 4; i++)
                ldsm4(af[i][0], af[i][1], af[i][2], af[i][3],
                      sa + (uint32_t)((wm0 + i * 16 + a_row) * AROWB
                                      + ks * 32 + a_cb));
#pragma unroll
            for (int jp = 0; jp < 2; jp++)
                ldsm4(bf[jp][0], bf[jp][1], bf[jp][2], bf[jp][3],
                      sb2 + (uint32_t)((wn0 + jp * 16 + b_row) * AROWB
                                       + ks * 32 + b_cb));
#pragma unroll
            for (int i = 0; i < 4; i++)
#pragma unroll
                for (int j = 0; j < 4; j++)
                    mma16816(acc[i][j], af[i][0], af[i][1], af[i][2], af[i][3],
                             bf[j >> 1][(j & 1) * 2], bf[j >> 1][(j & 1) * 2 + 1]);
        }
    }

    // ---- epilogue ----
    const int mrow = lane >> 2;
    const int ncol = (lane & 3) * 2;
#pragma unroll
    for (int i = 0; i < 4; i++) {
        const int gmA = m0 + wm0 + i * 16 + mrow;
        const int gmB = gmA + 8;
        const float tpA = (float)(gmA & (T_SEQ - 1));
        const float tpB = (float)(gmB & (T_SEQ - 1));
#pragma unroll
        for (int j = 0; j < 4; j++) {
            const int gc = n0 + wn0 + j * 8 + ncol;
            float x0 = acc[i][j][0], x1 = acc[i][j][1];
            float y0 = acc[i][j][2], y1 = acc[i][j][3];
            if (rotary) {
                const int p = (gc & 63) >> 1;
                const float f = g_invf[p];
                float angA = __fmul_rn(tpA, f);
                float angB = __fmul_rn(tpB, f);
                double dA = (double)angA;
                double rA = dA - floor(dA * 0.15915494309189535) * 6.283185307179586;
                double dB = (double)angB;
                double rB = dB - floor(dB * 0.15915494309189535) * 6.283185307179586;
                float sA = sinf((float)rA), cA = cosf((float)rA);
                float sB = sinf((float)rB), cB = cosf((float)rB);
                float t0 = x0 * cA - x1 * sA;
                float t1 = x1 * cA + x0 * sA;
                float u0 = y0 * cB - y1 * sB;
                float u1 = y1 * cB + y0 * sB;
                x0 = t0; x1 = t1; y0 = u0; y1 = u1;
            }
            const int hh = gc >> 6, d = gc & 63;
            if (csel == 0 || csel == 1) {   // Q or K -> single fp16
                if (csel == 0) { x0 *= 0.125f; x1 *= 0.125f;
                                 y0 *= 0.125f; y1 *= 0.125f; }
                __half* dst = (csel == 0) ? q2 : k2;
                *(uint32_t*)(dst + ((size_t)gmA * NHEADS + hh) * 64 + d) =
                    cvt_h2(x0, x1);
                *(uint32_t*)(dst + ((size_t)gmB * NHEADS + hh) * 64 + d) =
                    cvt_h2(y0, y1);
            } else if (csel == 2) {         // V -> single fp16
                *(uint32_t*)(v2 + (size_t)gmA * EMB + gc) = cvt_h2(x0, x1);
                *(uint32_t*)(v2 + (size_t)gmB * EMB + gc) = cvt_h2(y0, y1);
            } else {                        // final fp32 output
                *(float2*)(Cexp + (size_t)gmA * EMB + gc) = make_float2(x0, x1);
                *(float2*)(Cexp + (size_t)gmB * EMB + gc) = make_float2(y0, y1);
            }
        }
    }
#undef LOAD_CHUNK
}

// ---------------------------------------------------------------------------
// Banded flash attention, fp16 mma. Block = (64 queries, head, batch), 4 warps.
// QK^T: Qh.Kh (k=64). PV: Ph x Vh. Output -> Oh fp16 rows of a_at.
// ---------------------------------------------------------------------------
#define KPITCH 144   // 64 fp16 (128B) + 16B pad
#define SM_Q   0
#define SM_K   (64 * KPITCH)             // 9216
#define SM_V   (SM_K + 64 * KPITCH)      // 18432
#define SM_ATT (SM_V + 64 * KPITCH)      // 27648 bytes

__global__ __launch_bounds__(128) void attn_mma() {
    const int qt = blockIdx.x, h = blockIdx.y, b = blockIdx.z;
    const int t = threadIdx.x;
    const int wid = t >> 5, lane = t & 31;
    const int qbase = qt * 64;

    extern __shared__ char smraw[];
    char* smp = smraw;
    const uint32_t sb = smem_u32(smraw);

    // ---- load Qh tile (64 x 64 fp16) once ----
    for (int i = t; i < 64 * 8; i += 128) {
        int r = i >> 3, c = i & 7;
        const uint4* src = (const uint4*)(q2 +
            ((size_t)(b * T_SEQ + qbase + r) * NHEADS + h) * 64);
        *(uint4*)(smp + SM_Q + r * KPITCH + c * 16) = src[c];
    }

    float m0r = -3.0e38f, m1r = -3.0e38f, l0r = 0.0f, l1r = 0.0f;
    float o[8][4];
#pragma unroll
    for (int j = 0; j < 8; j++)
#pragma unroll
        for (int u = 0; u < 4; u++) o[j][u] = 0.0f;

    const int kt_lo = (qt - 4 > 0) ? (qt - 4) : 0;
    const int kt_hi = (qt + 4 < 31) ? (qt + 4) : 31;

    const int r0g = qbase + 16 * wid + (lane >> 2);
    const int coff = 2 * (lane & 3);

    for (int kt = kt_lo; kt <= kt_hi; kt++) {
        const int kbase = kt * 64;
        __syncthreads();
        // ---- load Kh (64x64) and Vh (64x64) ----
        for (int i = t; i < 64 * 8; i += 128) {
            int r = i >> 3, c = i & 7;
            const uint4* srck = (const uint4*)(k2 +
                ((size_t)(b * T_SEQ + kbase + r) * NHEADS + h) * 64);
            *(uint4*)(smp + SM_K + r * KPITCH + c * 16) = srck[c];
            size_t g = (size_t)(b * T_SEQ + kbase + r) * EMB + h * 64;
            *(uint4*)(smp + SM_V + r * KPITCH + c * 16) =
                ((const uint4*)(v2 + g))[c];
        }
        __syncthreads();

        // ---- S = Qh Kh^T (k = 64) ----
        float s[8][4];
#pragma unroll
        for (int j = 0; j < 8; j++)
#pragma unroll
            for (int u = 0; u < 4; u++) s[j][u] = 0.0f;

        const uint32_t aAddrBase = sb + SM_Q
            + (uint32_t)((16 * wid + (lane & 15)) * KPITCH + (lane >> 4) * 16);
        const int bRow = (lane & 7) + ((lane >> 4) << 3);
        const uint32_t bAddrBase = sb + SM_K
            + (uint32_t)(bRow * KPITCH + (((lane >> 3) & 1) << 4));

#pragma unroll
        for (int ks = 0; ks < 4; ks++) {
            uint32_t a0, a1, a2, a3;
            ldsm4(a0, a1, a2, a3, aAddrBase + ks * 32);
#pragma unroll
            for (int g = 0; g < 4; g++) {
                uint32_t b0, b1, b2, b3;
                ldsm4(b0, b1, b2, b3,
                      bAddrBase + (uint32_t)(g * 16 * KPITCH + ks * 32));
                mma16816(s[2 * g],     a0, a1, a2, a3, b0, b1);
                mma16816(s[2 * g + 1], a0, a1, a2, a3, b2, b3);
            }
        }

        // ---- band mask ----
#pragma unroll
        for (int j = 0; j < 8; j++) {
            int c0 = kbase + 8 * j + coff;
            int d00 = r0g - c0, d01 = r0g - (c0 + 1);
            if (d00 > WHALF || d00 < -WHALF) s[j][0] = -1.0e30f;
            if (d01 > WHALF || d01 < -WHALF) s[j][1] = -1.0e30f;
            int d10 = d00 + 8, d11 = d01 + 8;
            if (d10 > WHALF || d10 < -WHALF) s[j][2] = -1.0e30f;
            if (d11 > WHALF || d11 < -WHALF) s[j][3] = -1.0e30f;
        }

        // ---- online softmax ----
        float mx0 = -1.0e30f, mx1 = -1.0e30f;
#pragma unroll
        for (int j = 0; j < 8; j++) {
            mx0 = fmaxf(mx0, fmaxf(s[j][0], s[j][1]));
            mx1 = fmaxf(mx1, fmaxf(s[j][2], s[j][3]));
        }
        mx0 = fmaxf(mx0, __shfl_xor_sync(0xffffffffu, mx0, 1));
        mx0 = fmaxf(mx0, __shfl_xor_sync(0xffffffffu, mx0, 2));
        mx1 = fmaxf(mx1, __shfl_xor_sync(0xffffffffu, mx1, 1));
        mx1 = fmaxf(mx1, __shfl_xor_sync(0xffffffffu, mx1, 2));
        float mn0 = fmaxf(m0r, mx0), mn1 = fmaxf(m1r, mx1);
        float cor0 = __expf(m0r - mn0), cor1 = __expf(m1r - mn1);
        m0r = mn0; m1r = mn1;

        float rs0 = 0.0f, rs1 = 0.0f;
#pragma unroll
        for (int j = 0; j < 8; j++) {
            s[j][0] = __expf(s[j][0] - mn0);
            s[j][1] = __expf(s[j][1] - mn0);
            s[j][2] = __expf(s[j][2] - mn1);
            s[j][3] = __expf(s[j][3] - mn1);
            rs0 += s[j][0] + s[j][1];
            rs1 += s[j][2] + s[j][3];
        }
        rs0 += __shfl_xor_sync(0xffffffffu, rs0, 1);
        rs0 += __shfl_xor_sync(0xffffffffu, rs0, 2);
        rs1 += __shfl_xor_sync(0xffffffffu, rs1, 1);
        rs1 += __shfl_xor_sync(0xffffffffu, rs1, 2);
        l0r = l0r * cor0 + rs0;
        l1r = l1r * cor1 + rs1;

#pragma unroll
        for (int j = 0; j < 8; j++) {
            o[j][0] *= cor0; o[j][1] *= cor0;
            o[j][2] *= cor1; o[j][3] *= cor1;
        }

        // ---- P -> fp16 A-fragments ----
        uint32_t ph[4][4];
#pragma unroll
        for (int ks2 = 0; ks2 < 4; ks2++) {
            int j0 = 2 * ks2, j1 = j0 + 1;
            ph[ks2][0] = cvt_h2(s[j0][0], s[j0][1]);
            ph[ks2][1] = cvt_h2(s[j0][2], s[j0][3]);
            ph[ks2][2] = cvt_h2(s[j1][0], s[j1][1]);
            ph[ks2][3] = cvt_h2(s[j1][2], s[j1][3]);
        }

        // ---- PV: out += Ph*Vh ----
        const uint32_t vAddrBase =
            (uint32_t)((lane & 15) * KPITCH + (lane >> 4) * 16);
#pragma unroll
        for (int ks2 = 0; ks2 < 4; ks2++) {
            uint32_t voff = vAddrBase + (uint32_t)(ks2 * 16 * KPITCH);
#pragma unroll
            for (int g = 0; g < 4; g++) {
                uint32_t v0, v1, v2r, v3;
                ldsm4t(v0, v1, v2r, v3, sb + SM_V + voff + g * 32);
                mma16816(o[2 * g],     ph[ks2][0], ph[ks2][1], ph[ks2][2],
                         ph[ks2][3], v0, v1);
                mma16816(o[2 * g + 1], ph[ks2][0], ph[ks2][1], ph[ks2][2],
                         ph[ks2][3], v2r, v3);
            }
        }
    }

    // ---- finalize: write Oh rows of a_at ----
    const float inv0 = 1.0f / l0r, inv1 = 1.0f / l1r;
    const size_t mA = (size_t)(b * T_SEQ) + qbase + 16 * wid + (lane >> 2);
    const size_t mB = mA + 8;
    __half* rowA = a_at + mA * EMB + h * 64 + coff;
    __half* rowB = a_at + mB * EMB + h * 64 + coff;
#pragma unroll
    for (int j = 0; j < 8; j++) {
        *(uint32_t*)(rowA + 8 * j) = cvt_h2(o[j][0] * inv0, o[j][1] * inv0);
        *(uint32_t*)(rowB + 8 * j) = cvt_h2(o[j][2] * inv1, o[j][3] * inv1);
    }
}

// ---------------------------------------------------------------------------
// Launch
// ---------------------------------------------------------------------------
extern "C" void kernel_launch(void* const* d_in, const int* in_sizes, int n_in,
                              void* d_out, int out_size)
{
    const float* xq  = (const float*)d_in[0];
    const float* xkv = (const float*)d_in[1];
    const float* Wq  = (const float*)d_in[2];
    const float* Wk  = (const float*)d_in[3];
    const float* Wv  = (const float*)d_in[4];
    const float* Wo  = (const float*)d_in[5];
    float* out = (float*)d_out;

    init_invf_kernel<<<1, 32>>>();
    conv_in_kernel<<<dim3(512, 1, 2), 256>>>(xq, xkv);
    conv_w_kernel<<<dim3(32, 32, 4), dim3(32, 32)>>>(Wq, Wk, Wv, Wo);

    const int gemm_smem = NSTAGE * STG;   // 61440
    cudaFuncSetAttribute(mma_gemm, cudaFuncAttributeMaxDynamicSharedMemorySize,
                         gemm_smem);

    // Q, K, V projections fused into one launch (z = 0,1,2)
    mma_gemm<<<dim3(EMB / 128, MTOT / 128, 3), 256, gemm_smem>>>(nullptr, -1);

    cudaFuncSetAttribute(attn_mma, cudaFuncAttributeMaxDynamicSharedMemorySize,
                         SM_ATT);
    attn_mma<<<dim3(T_SEQ / 64, NHEADS, BATCH), 128, SM_ATT>>>();

    // O-projection
    mma_gemm<<<dim3(EMB / 128, MTOT / 128, 1), 256, gemm_smem>>>(out, 3);
}

// round 10
// speedup vs baseline: 6.0849x; 1.1207x over previous
#include <cuda_runtime.h>
#include <cuda_fp16.h>
#include <math.h>
#include <stdint.h>

#define BATCH   4
#define T_SEQ   2048
#define EMB     1024
#define NHEADS  16
#define HDIM    64
#define WHALF   256
#define MTOT    (BATCH * T_SEQ)      // 8192
#define BK      32
#define AROWB   80                   // padded row: 32 fp16 (64B) + 16B pad
#define ASTG    (128 * AROWB)        // A: 128 rows  -> 10240 B
#define BSTG    (64 * AROWB)         // B:  64 rows  ->  5120 B
#define STG     (ASTG + BSTG)        // 15360 B per stage
#define NSTAGE  3                    // 46080 B total

// ---------------------------------------------------------------------------
// Scratch (static device globals; cudaMalloc forbidden)
// ---------------------------------------------------------------------------
__device__ __half a_q [(size_t)MTOT * EMB];   // Xh
__device__ __half a_kv[(size_t)MTOT * EMB];
__device__ __half a_at[(size_t)MTOT * EMB];   // attn out Oh
__device__ __half w_q[EMB * EMB];             // Wh, [N][K] K-major
__device__ __half w_k[EMB * EMB];
__device__ __half w_v[EMB * EMB];
__device__ __half w_o[EMB * EMB];
// attention operands (single fp16)
__device__ __half q2[(size_t)MTOT * NHEADS * 64];   // [m][h][Qh] (x 1/8)
__device__ __half k2[(size_t)MTOT * NHEADS * 64];   // [m][h][Kh]
__device__ __half v2[(size_t)MTOT * EMB];           // [m][h*64+d] Vh
__device__ float g_invf[32];

// ---------------------------------------------------------------------------
// PTX helpers (sm_103 base ISA only)
// ---------------------------------------------------------------------------
__device__ __forceinline__ uint32_t smem_u32(const void* p) {
    uint32_t a;
    asm("{ .reg .u64 t; cvta.to.shared.u64 t, %1; cvt.u32.u64 %0, t; }"
        : "=r"(a) : "l"(p));
    return a;
}
__device__ __forceinline__ void cp16(uint32_t dst, const void* src) {
    asm volatile("cp.async.cg.shared.global [%0], [%1], 16;"
                 :: "r"(dst), "l"(src) : "memory");
}
__device__ __forceinline__ void cp_commit() {
    asm volatile("cp.async.commit_group;" ::: "memory");
}
__device__ __forceinline__ void ldsm4(uint32_t& r0, uint32_t& r1,
                                      uint32_t& r2, uint32_t& r3, uint32_t addr) {
    asm volatile("ldmatrix.sync.aligned.m8n8.x4.shared.b16 {%0,%1,%2,%3}, [%4];"
                 : "=r"(r0), "=r"(r1), "=r"(r2), "=r"(r3) : "r"(addr));
}
__device__ __forceinline__ void ldsm4t(uint32_t& r0, uint32_t& r1,
                                       uint32_t& r2, uint32_t& r3, uint32_t addr) {
    asm volatile("ldmatrix.sync.aligned.m8n8.x4.trans.shared.b16 {%0,%1,%2,%3}, [%4];"
                 : "=r"(r0), "=r"(r1), "=r"(r2), "=r"(r3) : "r"(addr));
}
__device__ __forceinline__ void mma16816(float* c, uint32_t a0, uint32_t a1,
                                         uint32_t a2, uint32_t a3,
                                         uint32_t b0, uint32_t b1) {
    asm volatile(
        "mma.sync.aligned.m16n8k16.row.col.f32.f16.f16.f32 "
        "{%0,%1,%2,%3}, {%4,%5,%6,%7}, {%8,%9}, {%0,%1,%2,%3};"
        : "+f"(c[0]), "+f"(c[1]), "+f"(c[2]), "+f"(c[3])
        : "r"(a0), "r"(a1), "r"(a2), "r"(a3), "r"(b0), "r"(b1));
}
__device__ __forceinline__ uint32_t pk_h2(__half a, __half b) {
    return (uint32_t)__half_as_ushort(a) |
           ((uint32_t)__half_as_ushort(b) << 16);
}
__device__ __forceinline__ uint32_t cvt_h2(float x0, float x1) {
    return pk_h2(__float2half_rn(x0), __float2half_rn(x1));
}

// ---------------------------------------------------------------------------
// Conversion kernels (fused across operands via blockIdx.z)
// ---------------------------------------------------------------------------
__global__ void init_invf_kernel() {
    int p = threadIdx.x;
    if (p < 32) g_invf[p] = (float)pow(10000.0, -(double)p / 32.0);
}

__global__ __launch_bounds__(256) void conv_in_kernel(
    const float* __restrict__ Xq, const float* __restrict__ Xkv) {
    const float* X = blockIdx.z ? Xkv : Xq;
    __half* A = blockIdx.z ? a_kv : a_q;
    const size_t n4 = (size_t)MTOT * EMB / 4;
    for (size_t i = (size_t)blockIdx.x * blockDim.x + threadIdx.x;
         i < n4; i += (size_t)gridDim.x * blockDim.x) {
        float4 v = ((const float4*)X)[i];
        uint2 o;
        o.x = cvt_h2(v.x, v.y);
        o.y = cvt_h2(v.z, v.w);
        ((uint2*)A)[i] = o;
    }
}

__global__ void conv_w_kernel(const float* __restrict__ Wq,
                              const float* __restrict__ Wk,
                              const float* __restrict__ Wv,
                              const float* __restrict__ Wo) {
    const int z = blockIdx.z;
    const float* W = (z == 0) ? Wq : (z == 1) ? Wk : (z == 2) ? Wv : Wo;
    __half* O = (z == 0) ? w_q : (z == 1) ? w_k : (z == 2) ? w_v : w_o;
    __shared__ float tile[32][33];
    int tx = threadIdx.x, ty = threadIdx.y;
    tile[ty][tx] = W[(size_t)(blockIdx.y * 32 + ty) * EMB + blockIdx.x * 32 + tx];
    __syncthreads();
    int n = blockIdx.x * 32 + ty;
    int k = blockIdx.y * 32 + tx;
    O[(size_t)n * EMB + k] = __float2half_rn(tile[tx][ty]);
}

// ---------------------------------------------------------------------------
// mma.sync fp16 GEMM, 128x64 CTA tile, 4 warps (2x2 -> 64x32 warp tiles),
// BK=32, 3-stage cp.async, single barrier per chunk. 4 CTAs/SM for latency
// hiding via independent pipeline domains.
// csel: <0 -> use blockIdx.z (merged QKV projections); else explicit.
//   0 -> q2 (x1/8, rotary), 1 -> k2 (rotary), 2 -> v2, 3 -> fp32 Cexp (A=a_at)
// ---------------------------------------------------------------------------
__global__ __launch_bounds__(128) void mma_gemm(float* __restrict__ Cexp,
                                                int csel_in) {
    const int csel = (csel_in < 0) ? (int)blockIdx.z : csel_in;
    const int rotary = (csel <= 1);
    const __half* Ag = (csel == 0) ? a_q : (csel == 3) ? a_at : a_kv;
    const __half* Bg = (csel == 0) ? w_q : (csel == 1) ? w_k
                       : (csel == 2) ? w_v : w_o;
    const int nch = 32;

    extern __shared__ char smraw[];
    const uint32_t sb = smem_u32(smraw);
    const int t = threadIdx.x;
    const int wid = t >> 5, lane = t & 31;
    const int m0 = blockIdx.y * 128, n0 = blockIdx.x * 64;
    const int wm0 = (wid & 1) * 64;
    const int wn0 = (wid >> 1) * 32;

    const char* Ab = (const char*)(Ag + (size_t)m0 * EMB);
    const char* Bb = (const char*)(Bg + (size_t)n0 * EMB);

    // A: 512 slots (128 rows x 4 segs) -> 4 per thread
    // B: 256 slots (64 rows x 4 segs)  -> 2 per thread
#define LOAD_CHUNK(c)                                                          \
    do {                                                                       \
        uint32_t _sa = sb + ((c) % NSTAGE) * STG;                              \
        uint32_t _sb2 = _sa + ASTG;                                            \
        _Pragma("unroll")                                                      \
        for (int _i = 0; _i < 4; _i++) {                                       \
            int _idx = t + _i * 128;                                           \
            int _row = _idx >> 2, _seg = _idx & 3;                             \
            size_t _g = (size_t)_row * (EMB * 2) + (size_t)(c) * 64            \
                        + _seg * 16;                                           \
            cp16(_sa + (uint32_t)(_row * AROWB + _seg * 16), Ab + _g);         \
        }                                                                      \
        _Pragma("unroll")                                                      \
        for (int _i = 0; _i < 2; _i++) {                                       \
            int _idx = t + _i * 128;                                           \
            int _row = _idx >> 2, _seg = _idx & 3;                             \
            size_t _g = (size_t)_row * (EMB * 2) + (size_t)(c) * 64            \
                        + _seg * 16;                                           \
            cp16(_sb2 + (uint32_t)(_row * AROWB + _seg * 16), Bb + _g);        \
        }                                                                      \
        cp_commit();                                                           \
    } while (0)

    float acc[4][4][4];
#pragma unroll
    for (int i = 0; i < 4; i++)
#pragma unroll
        for (int j = 0; j < 4; j++)
#pragma unroll
            for (int u = 0; u < 4; u++) acc[i][j][u] = 0.0f;

    LOAD_CHUNK(0);
    LOAD_CHUNK(1);

    const int lq = lane >> 3, lr = lane & 7;
    const int a_row = (lq & 1) * 8 + lr;
    const int a_cb  = (lq >> 1) * 16;
    const int b_row = (lq >> 1) * 8 + lr;
    const int b_cb  = (lq & 1) * 16;

    for (int c = 0; c < nch; c++) {
        if (c >= nch - 1) asm volatile("cp.async.wait_group 0;" ::: "memory");
        else              asm volatile("cp.async.wait_group 1;" ::: "memory");
        __syncthreads();
        if (c + 2 < nch) LOAD_CHUNK(c + 2);

        const uint32_t sa  = sb + (c % NSTAGE) * STG;
        const uint32_t sb2 = sa + ASTG;

#pragma unroll
        for (int ks = 0; ks < 2; ks++) {
            uint32_t af[4][4], bf[2][4];
#pragma unroll
            for (int i = 0; i < 4; i++)
                ldsm4(af[i][0], af[i][1], af[i][2], af[i][3],
                      sa + (uint32_t)((wm0 + i * 16 + a_row) * AROWB
                                      + ks * 32 + a_cb));
#pragma unroll
            for (int jp = 0; jp < 2; jp++)
                ldsm4(bf[jp][0], bf[jp][1], bf[jp][2], bf[jp][3],
                      sb2 + (uint32_t)((wn0 + jp * 16 + b_row) * AROWB
                                       + ks * 32 + b_cb));
#pragma unroll
            for (int i = 0; i < 4; i++)
#pragma unroll
                for (int j = 0; j < 4; j++)
                    mma16816(acc[i][j], af[i][0], af[i][1], af[i][2], af[i][3],
                             bf[j >> 1][(j & 1) * 2], bf[j >> 1][(j & 1) * 2 + 1]);
        }
    }

    // ---- epilogue ----
    const int mrow = lane >> 2;
    const int ncol = (lane & 3) * 2;
#pragma unroll
    for (int i = 0; i < 4; i++) {
        const int gmA = m0 + wm0 + i * 16 + mrow;
        const int gmB = gmA + 8;
        const float tpA = (float)(gmA & (T_SEQ - 1));
        const float tpB = (float)(gmB & (T_SEQ - 1));
#pragma unroll
        for (int j = 0; j < 4; j++) {
            const int gc = n0 + wn0 + j * 8 + ncol;
            float x0 = acc[i][j][0], x1 = acc[i][j][1];
            float y0 = acc[i][j][2], y1 = acc[i][j][3];
            if (rotary) {
                const int p = (gc & 63) >> 1;
                const float f = g_invf[p];
                float angA = __fmul_rn(tpA, f);
                float angB = __fmul_rn(tpB, f);
                double dA = (double)angA;
                double rA = dA - floor(dA * 0.15915494309189535) * 6.283185307179586;
                double dB = (double)angB;
                double rB = dB - floor(dB * 0.15915494309189535) * 6.283185307179586;
                float sA = sinf((float)rA), cA = cosf((float)rA);
                float sB = sinf((float)rB), cB = cosf((float)rB);
                float t0 = x0 * cA - x1 * sA;
                float t1 = x1 * cA + x0 * sA;
                float u0 = y0 * cB - y1 * sB;
                float u1 = y1 * cB + y0 * sB;
                x0 = t0; x1 = t1; y0 = u0; y1 = u1;
            }
            const int hh = gc >> 6, d = gc & 63;
            if (csel == 0 || csel == 1) {   // Q or K -> single fp16
                if (csel == 0) { x0 *= 0.125f; x1 *= 0.125f;
                                 y0 *= 0.125f; y1 *= 0.125f; }
                __half* dst = (csel == 0) ? q2 : k2;
                *(uint32_t*)(dst + ((size_t)gmA * NHEADS + hh) * 64 + d) =
                    cvt_h2(x0, x1);
                *(uint32_t*)(dst + ((size_t)gmB * NHEADS + hh) * 64 + d) =
                    cvt_h2(y0, y1);
            } else if (csel == 2) {         // V -> single fp16
                *(uint32_t*)(v2 + (size_t)gmA * EMB + gc) = cvt_h2(x0, x1);
                *(uint32_t*)(v2 + (size_t)gmB * EMB + gc) = cvt_h2(y0, y1);
            } else {                        // final fp32 output
                *(float2*)(Cexp + (size_t)gmA * EMB + gc) = make_float2(x0, x1);
                *(float2*)(Cexp + (size_t)gmB * EMB + gc) = make_float2(y0, y1);
            }
        }
    }
#undef LOAD_CHUNK
}

// ---------------------------------------------------------------------------
// Banded flash attention, fp16 mma. Block = (64 queries, head, batch), 4 warps.
// QK^T: Qh.Kh (k=64). PV: Ph x Vh. Output -> Oh fp16 rows of a_at.
// ---------------------------------------------------------------------------
#define KPITCH 144   // 64 fp16 (128B) + 16B pad
#define SM_Q   0
#define SM_K   (64 * KPITCH)             // 9216
#define SM_V   (SM_K + 64 * KPITCH)      // 18432
#define SM_ATT (SM_V + 64 * KPITCH)      // 27648 bytes

__global__ __launch_bounds__(128) void attn_mma() {
    const int qt = blockIdx.x, h = blockIdx.y, b = blockIdx.z;
    const int t = threadIdx.x;
    const int wid = t >> 5, lane = t & 31;
    const int qbase = qt * 64;

    extern __shared__ char smraw[];
    char* smp = smraw;
    const uint32_t sb = smem_u32(smraw);

    // ---- load Qh tile (64 x 64 fp16) once ----
    for (int i = t; i < 64 * 8; i += 128) {
        int r = i >> 3, c = i & 7;
        const uint4* src = (const uint4*)(q2 +
            ((size_t)(b * T_SEQ + qbase + r) * NHEADS + h) * 64);
        *(uint4*)(smp + SM_Q + r * KPITCH + c * 16) = src[c];
    }

    float m0r = -3.0e38f, m1r = -3.0e38f, l0r = 0.0f, l1r = 0.0f;
    float o[8][4];
#pragma unroll
    for (int j = 0; j < 8; j++)
#pragma unroll
        for (int u = 0; u < 4; u++) o[j][u] = 0.0f;

    const int kt_lo = (qt - 4 > 0) ? (qt - 4) : 0;
    const int kt_hi = (qt + 4 < 31) ? (qt + 4) : 31;

    const int r0g = qbase + 16 * wid + (lane >> 2);
    const int coff = 2 * (lane & 3);

    for (int kt = kt_lo; kt <= kt_hi; kt++) {
        const int kbase = kt * 64;
        __syncthreads();
        // ---- load Kh (64x64) and Vh (64x64) ----
        for (int i = t; i < 64 * 8; i += 128) {
            int r = i >> 3, c = i & 7;
            const uint4* srck = (const uint4*)(k2 +
                ((size_t)(b * T_SEQ + kbase + r) * NHEADS + h) * 64);
            *(uint4*)(smp + SM_K + r * KPITCH + c * 16) = srck[c];
            size_t g = (size_t)(b * T_SEQ + kbase + r) * EMB + h * 64;
            *(uint4*)(smp + SM_V + r * KPITCH + c * 16) =
                ((const uint4*)(v2 + g))[c];
        }
        __syncthreads();

        // ---- S = Qh Kh^T (k = 64) ----
        float s[8][4];
#pragma unroll
        for (int j = 0; j < 8; j++)
#pragma unroll
            for (int u = 0; u < 4; u++) s[j][u] = 0.0f;

        const uint32_t aAddrBase = sb + SM_Q
            + (uint32_t)((16 * wid + (lane & 15)) * KPITCH + (lane >> 4) * 16);
        const int bRow = (lane & 7) + ((lane >> 4) << 3);
        const uint32_t bAddrBase = sb + SM_K
            + (uint32_t)(bRow * KPITCH + (((lane >> 3) & 1) << 4));

#pragma unroll
        for (int ks = 0; ks < 4; ks++) {
            uint32_t a0, a1, a2, a3;
            ldsm4(a0, a1, a2, a3, aAddrBase + ks * 32);
#pragma unroll
            for (int g = 0; g < 4; g++) {
                uint32_t b0, b1, b2, b3;
                ldsm4(b0, b1, b2, b3,
                      bAddrBase + (uint32_t)(g * 16 * KPITCH + ks * 32));
                mma16816(s[2 * g],     a0, a1, a2, a3, b0, b1);
                mma16816(s[2 * g + 1], a0, a1, a2, a3, b2, b3);
            }
        }

        // ---- band mask ----
#pragma unroll
        for (int j = 0; j < 8; j++) {
            int c0 = kbase + 8 * j + coff;
            int d00 = r0g - c0, d01 = r0g - (c0 + 1);
            if (d00 > WHALF || d00 < -WHALF) s[j][0] = -1.0e30f;
            if (d01 > WHALF || d01 < -WHALF) s[j][1] = -1.0e30f;
            int d10 = d00 + 8, d11 = d01 + 8;
            if (d10 > WHALF || d10 < -WHALF) s[j][2] = -1.0e30f;
            if (d11 > WHALF || d11 < -WHALF) s[j][3] = -1.0e30f;
        }

        // ---- online softmax ----
        float mx0 = -1.0e30f, mx1 = -1.0e30f;
#pragma unroll
        for (int j = 0; j < 8; j++) {
            mx0 = fmaxf(mx0, fmaxf(s[j][0], s[j][1]));
            mx1 = fmaxf(mx1, fmaxf(s[j][2], s[j][3]));
        }
        mx0 = fmaxf(mx0, __shfl_xor_sync(0xffffffffu, mx0, 1));
        mx0 = fmaxf(mx0, __shfl_xor_sync(0xffffffffu, mx0, 2));
        mx1 = fmaxf(mx1, __shfl_xor_sync(0xffffffffu, mx1, 1));
        mx1 = fmaxf(mx1, __shfl_xor_sync(0xffffffffu, mx1, 2));
        float mn0 = fmaxf(m0r, mx0), mn1 = fmaxf(m1r, mx1);
        float cor0 = __expf(m0r - mn0), cor1 = __expf(m1r - mn1);
        m0r = mn0; m1r = mn1;

        float rs0 = 0.0f, rs1 = 0.0f;
#pragma unroll
        for (int j = 0; j < 8; j++) {
            s[j][0] = __expf(s[j][0] - mn0);
            s[j][1] = __expf(s[j][1] - mn0);
            s[j][2] = __expf(s[j][2] - mn1);
            s[j][3] = __expf(s[j][3] - mn1);
            rs0 += s[j][0] + s[j][1];
            rs1 += s[j][2] + s[j][3];
        }
        rs0 += __shfl_xor_sync(0xffffffffu, rs0, 1);
        rs0 += __shfl_xor_sync(0xffffffffu, rs0, 2);
        rs1 += __shfl_xor_sync(0xffffffffu, rs1, 1);
        rs1 += __shfl_xor_sync(0xffffffffu, rs1, 2);
        l0r = l0r * cor0 + rs0;
        l1r = l1r * cor1 + rs1;

#pragma unroll
        for (int j = 0; j < 8; j++) {
            o[j][0] *= cor0; o[j][1] *= cor0;
            o[j][2] *= cor1; o[j][3] *= cor1;
        }

        // ---- P -> fp16 A-fragments ----
        uint32_t ph[4][4];
#pragma unroll
        for (int ks2 = 0; ks2 < 4; ks2++) {
            int j0 = 2 * ks2, j1 = j0 + 1;
            ph[ks2][0] = cvt_h2(s[j0][0], s[j0][1]);
            ph[ks2][1] = cvt_h2(s[j0][2], s[j0][3]);
            ph[ks2][2] = cvt_h2(s[j1][0], s[j1][1]);
            ph[ks2][3] = cvt_h2(s[j1][2], s[j1][3]);
        }

        // ---- PV: out += Ph*Vh ----
        const uint32_t vAddrBase =
            (uint32_t)((lane & 15) * KPITCH + (lane >> 4) * 16);
#pragma unroll
        for (int ks2 = 0; ks2 < 4; ks2++) {
            uint32_t voff = vAddrBase + (uint32_t)(ks2 * 16 * KPITCH);
#pragma unroll
            for (int g = 0; g < 4; g++) {
                uint32_t v0, v1, v2r, v3;
                ldsm4t(v0, v1, v2r, v3, sb + SM_V + voff + g * 32);
                mma16816(o[2 * g],     ph[ks2][0], ph[ks2][1], ph[ks2][2],
                         ph[ks2][3], v0, v1);
                mma16816(o[2 * g + 1], ph[ks2][0], ph[ks2][1], ph[ks2][2],
                         ph[ks2][3], v2r, v3);
            }
        }
    }

    // ---- finalize: write Oh rows of a_at ----
    const float inv0 = 1.0f / l0r, inv1 = 1.0f / l1r;
    const size_t mA = (size_t)(b * T_SEQ) + qbase + 16 * wid + (lane >> 2);
    const size_t mB = mA + 8;
    __half* rowA = a_at + mA * EMB + h * 64 + coff;
    __half* rowB = a_at + mB * EMB + h * 64 + coff;
#pragma unroll
    for (int j = 0; j < 8; j++) {
        *(uint32_t*)(rowA + 8 * j) = cvt_h2(o[j][0] * inv0, o[j][1] * inv0);
        *(uint32_t*)(rowB + 8 * j) = cvt_h2(o[j][2] * inv1, o[j][3] * inv1);
    }
}

// ---------------------------------------------------------------------------
// Launch
// ---------------------------------------------------------------------------
extern "C" void kernel_launch(void* const* d_in, const int* in_sizes, int n_in,
                              void* d_out, int out_size)
{
    const float* xq  = (const float*)d_in[0];
    const float* xkv = (const float*)d_in[1];
    const float* Wq  = (const float*)d_in[2];
    const float* Wk  = (const float*)d_in[3];
    const float* Wv  = (const float*)d_in[4];
    const float* Wo  = (const float*)d_in[5];
    float* out = (float*)d_out;

    init_invf_kernel<<<1, 32>>>();
    conv_in_kernel<<<dim3(512, 1, 2), 256>>>(xq, xkv);
    conv_w_kernel<<<dim3(32, 32, 4), dim3(32, 32)>>>(Wq, Wk, Wv, Wo);

    const int gemm_smem = NSTAGE * STG;   // 46080
    cudaFuncSetAttribute(mma_gemm, cudaFuncAttributeMaxDynamicSharedMemorySize,
                         gemm_smem);

    // Q, K, V projections fused into one launch (z = 0,1,2)
    mma_gemm<<<dim3(EMB / 64, MTOT / 128, 3), 128, gemm_smem>>>(nullptr, -1);

    cudaFuncSetAttribute(attn_mma, cudaFuncAttributeMaxDynamicSharedMemorySize,
                         SM_ATT);
    attn_mma<<<dim3(T_SEQ / 64, NHEADS, BATCH), 128, SM_ATT>>>();

    // O-projection
    mma_gemm<<<dim3(EMB / 64, MTOT / 128, 1), 128, gemm_smem>>>(out, 3);
}

// round 11
// speedup vs baseline: 6.4300x; 1.0567x over previous
#include <cuda_runtime.h>
#include <cuda_fp16.h>
#include <math.h>
#include <stdint.h>

#define BATCH   4
#define T_SEQ   2048
#define EMB     1024
#define NHEADS  16
#define HDIM    64
#define WHALF   256
#define MTOT    (BATCH * T_SEQ)      // 8192
#define BK      32
#define AROWB   80                   // padded row: 32 fp16 (64B) + 16B pad
#define ASTG    (128 * AROWB)        // A: 128 rows  -> 10240 B
#define BSTG    (64 * AROWB)         // B:  64 rows  ->  5120 B
#define STG     (ASTG + BSTG)        // 15360 B per stage
#define NSTAGE  3                    // 46080 B total

// ---------------------------------------------------------------------------
// Scratch (static device globals; cudaMalloc forbidden)
// ---------------------------------------------------------------------------
__device__ __half a_q [(size_t)MTOT * EMB];   // Xh
__device__ __half a_kv[(size_t)MTOT * EMB];
__device__ __half a_at[(size_t)MTOT * EMB];   // attn out Oh
__device__ __half w_q[EMB * EMB];             // Wh, [N][K] K-major
__device__ __half w_k[EMB * EMB];
__device__ __half w_v[EMB * EMB];
__device__ __half w_o[EMB * EMB];
// attention operands (single fp16)
__device__ __half q2[(size_t)MTOT * NHEADS * 64];   // [m][h][Qh] (x 1/8)
__device__ __half k2[(size_t)MTOT * NHEADS * 64];   // [m][h][Kh]
__device__ __half v2[(size_t)MTOT * EMB];           // [m][h*64+d] Vh
__device__ float g_invf[32];

// ---------------------------------------------------------------------------
// PTX helpers (sm_103 base ISA only)
// ---------------------------------------------------------------------------
__device__ __forceinline__ uint32_t smem_u32(const void* p) {
    uint32_t a;
    asm("{ .reg .u64 t; cvta.to.shared.u64 t, %1; cvt.u32.u64 %0, t; }"
        : "=r"(a) : "l"(p));
    return a;
}
__device__ __forceinline__ void cp16(uint32_t dst, const void* src) {
    asm volatile("cp.async.cg.shared.global [%0], [%1], 16;"
                 :: "r"(dst), "l"(src) : "memory");
}
__device__ __forceinline__ void cp_commit() {
    asm volatile("cp.async.commit_group;" ::: "memory");
}
__device__ __forceinline__ void ldsm4(uint32_t& r0, uint32_t& r1,
                                      uint32_t& r2, uint32_t& r3, uint32_t addr) {
    asm volatile("ldmatrix.sync.aligned.m8n8.x4.shared.b16 {%0,%1,%2,%3}, [%4];"
                 : "=r"(r0), "=r"(r1), "=r"(r2), "=r"(r3) : "r"(addr));
}
__device__ __forceinline__ void ldsm4t(uint32_t& r0, uint32_t& r1,
                                       uint32_t& r2, uint32_t& r3, uint32_t addr) {
    asm volatile("ldmatrix.sync.aligned.m8n8.x4.trans.shared.b16 {%0,%1,%2,%3}, [%4];"
                 : "=r"(r0), "=r"(r1), "=r"(r2), "=r"(r3) : "r"(addr));
}
__device__ __forceinline__ void mma16816(float* c, uint32_t a0, uint32_t a1,
                                         uint32_t a2, uint32_t a3,
                                         uint32_t b0, uint32_t b1) {
    asm volatile(
        "mma.sync.aligned.m16n8k16.row.col.f32.f16.f16.f32 "
        "{%0,%1,%2,%3}, {%4,%5,%6,%7}, {%8,%9}, {%0,%1,%2,%3};"
        : "+f"(c[0]), "+f"(c[1]), "+f"(c[2]), "+f"(c[3])
        : "r"(a0), "r"(a1), "r"(a2), "r"(a3), "r"(b0), "r"(b1));
}
__device__ __forceinline__ uint32_t pk_h2(__half a, __half b) {
    return (uint32_t)__half_as_ushort(a) |
           ((uint32_t)__half_as_ushort(b) << 16);
}
__device__ __forceinline__ uint32_t cvt_h2(float x0, float x1) {
    return pk_h2(__float2half_rn(x0), __float2half_rn(x1));
}

// ---------------------------------------------------------------------------
// Fused conversion kernel: grid (32, 32, 6), 256 threads.
//   z 0/1: inputs Xq/Xkv fp32 -> a_q/a_kv fp16 (vectorized)
//   z 2-5: weights Wq/Wk/Wv/Wo fp32 [K,N] -> w_* fp16 [N][K] (transposed)
//   z==2, block(0,0): also fills g_invf (consumed by the NEXT launch)
// ---------------------------------------------------------------------------
__global__ __launch_bounds__(256) void conv_all(
    const float* __restrict__ Xq, const float* __restrict__ Xkv,
    const float* __restrict__ Wq, const float* __restrict__ Wk,
    const float* __restrict__ Wv, const float* __restrict__ Wo)
{
    const int z = blockIdx.z;
    const int t = threadIdx.x;

    if (z < 2) {
        const float* X = z ? Xkv : Xq;
        __half* A = z ? a_kv : a_q;
        const size_t n4 = (size_t)MTOT * EMB / 4;           // 2,097,152
        const size_t stride = (size_t)32 * 32 * 256;        // 262,144
        for (size_t i = (size_t)(blockIdx.y * 32 + blockIdx.x) * 256 + t;
             i < n4; i += stride) {
            float4 v = ((const float4*)X)[i];
            uint2 o;
            o.x = cvt_h2(v.x, v.y);
            o.y = cvt_h2(v.z, v.w);
            ((uint2*)A)[i] = o;
        }
        return;
    }

    const int w = z - 2;
    const float* W = (w == 0) ? Wq : (w == 1) ? Wk : (w == 2) ? Wv : Wo;
    __half* O = (w == 0) ? w_q : (w == 1) ? w_k : (w == 2) ? w_v : w_o;

    if (w == 0 && blockIdx.x == 0 && blockIdx.y == 0 && t < 32)
        g_invf[t] = (float)pow(10000.0, -(double)t / 32.0);

    __shared__ float tile[32][33];
    const int tx = t & 31, ty = t >> 5;   // ty 0..7
#pragma unroll
    for (int r = ty; r < 32; r += 8)
        tile[r][tx] = W[(size_t)(blockIdx.y * 32 + r) * EMB + blockIdx.x * 32 + tx];
    __syncthreads();
#pragma unroll
    for (int r = ty; r < 32; r += 8) {
        // O[n][k] with n = bx*32 + r, k = by*32 + tx  (coalesced in k)
        O[(size_t)(blockIdx.x * 32 + r) * EMB + blockIdx.y * 32 + tx] =
            __float2half_rn(tile[tx][r]);
    }
}

// ---------------------------------------------------------------------------
// mma.sync fp16 GEMM, 128x64 CTA tile, 4 warps (2x2 -> 64x32 warp tiles),
// BK=32, 3-stage cp.async, single barrier per chunk, 4 CTAs/SM.
// csel: <0 -> use blockIdx.z (merged QKV projections); else explicit.
//   0 -> q2 (x1/8, rotary), 1 -> k2 (rotary), 2 -> v2, 3 -> fp32 Cexp (A=a_at)
// ---------------------------------------------------------------------------
__global__ __launch_bounds__(128) void mma_gemm(float* __restrict__ Cexp,
                                                int csel_in) {
    const int csel = (csel_in < 0) ? (int)blockIdx.z : csel_in;
    const int rotary = (csel <= 1);
    const __half* Ag = (csel == 0) ? a_q : (csel == 3) ? a_at : a_kv;
    const __half* Bg = (csel == 0) ? w_q : (csel == 1) ? w_k
                       : (csel == 2) ? w_v : w_o;
    const int nch = 32;

    extern __shared__ char smraw[];
    const uint32_t sb = smem_u32(smraw);
    const int t = threadIdx.x;
    const int wid = t >> 5, lane = t & 31;
    const int m0 = blockIdx.y * 128, n0 = blockIdx.x * 64;
    const int wm0 = (wid & 1) * 64;
    const int wn0 = (wid >> 1) * 32;

    const char* Ab = (const char*)(Ag + (size_t)m0 * EMB);
    const char* Bb = (const char*)(Bg + (size_t)n0 * EMB);

#define LOAD_CHUNK(c)                                                          \
    do {                                                                       \
        uint32_t _sa = sb + ((c) % NSTAGE) * STG;                              \
        uint32_t _sb2 = _sa + ASTG;                                            \
        _Pragma("unroll")                                                      \
        for (int _i = 0; _i < 4; _i++) {                                       \
            int _idx = t + _i * 128;                                           \
            int _row = _idx >> 2, _seg = _idx & 3;                             \
            size_t _g = (size_t)_row * (EMB * 2) + (size_t)(c) * 64            \
                        + _seg * 16;                                           \
            cp16(_sa + (uint32_t)(_row * AROWB + _seg * 16), Ab + _g);         \
        }                                                                      \
        _Pragma("unroll")                                                      \
        for (int _i = 0; _i < 2; _i++) {                                       \
            int _idx = t + _i * 128;                                           \
            int _row = _idx >> 2, _seg = _idx & 3;                             \
            size_t _g = (size_t)_row * (EMB * 2) + (size_t)(c) * 64            \
                        + _seg * 16;                                           \
            cp16(_sb2 + (uint32_t)(_row * AROWB + _seg * 16), Bb + _g);        \
        }                                                                      \
        cp_commit();                                                           \
    } while (0)

    float acc[4][4][4];
#pragma unroll
    for (int i = 0; i < 4; i++)
#pragma unroll
        for (int j = 0; j < 4; j++)
#pragma unroll
            for (int u = 0; u < 4; u++) acc[i][j][u] = 0.0f;

    LOAD_CHUNK(0);
    LOAD_CHUNK(1);

    const int lq = lane >> 3, lr = lane & 7;
    const int a_row = (lq & 1) * 8 + lr;
    const int a_cb  = (lq >> 1) * 16;
    const int b_row = (lq >> 1) * 8 + lr;
    const int b_cb  = (lq & 1) * 16;

    for (int c = 0; c < nch; c++) {
        if (c >= nch - 1) asm volatile("cp.async.wait_group 0;" ::: "memory");
        else              asm volatile("cp.async.wait_group 1;" ::: "memory");
        __syncthreads();
        if (c + 2 < nch) LOAD_CHUNK(c + 2);

        const uint32_t sa  = sb + (c % NSTAGE) * STG;
        const uint32_t sb2 = sa + ASTG;

#pragma unroll
        for (int ks = 0; ks < 2; ks++) {
            uint32_t af[4][4], bf[2][4];
#pragma unroll
            for (int i = 0; i < 4; i++)
                ldsm4(af[i][0], af[i][1], af[i][2], af[i][3],
                      sa + (uint32_t)((wm0 + i * 16 + a_row) * AROWB
                                      + ks * 32 + a_cb));
#pragma unroll
            for (int jp = 0; jp < 2; jp++)
                ldsm4(bf[jp][0], bf[jp][1], bf[jp][2], bf[jp][3],
                      sb2 + (uint32_t)((wn0 + jp * 16 + b_row) * AROWB
                                       + ks * 32 + b_cb));
#pragma unroll
            for (int i = 0; i < 4; i++)
#pragma unroll
                for (int j = 0; j < 4; j++)
                    mma16816(acc[i][j], af[i][0], af[i][1], af[i][2], af[i][3],
                             bf[j >> 1][(j & 1) * 2], bf[j >> 1][(j & 1) * 2 + 1]);
        }
    }

    // ---- epilogue ----
    const int mrow = lane >> 2;
    const int ncol = (lane & 3) * 2;
#pragma unroll
    for (int i = 0; i < 4; i++) {
        const int gmA = m0 + wm0 + i * 16 + mrow;
        const int gmB = gmA + 8;
        const float tpA = (float)(gmA & (T_SEQ - 1));
        const float tpB = (float)(gmB & (T_SEQ - 1));
#pragma unroll
        for (int j = 0; j < 4; j++) {
            const int gc = n0 + wn0 + j * 8 + ncol;
            float x0 = acc[i][j][0], x1 = acc[i][j][1];
            float y0 = acc[i][j][2], y1 = acc[i][j][3];
            if (rotary) {
                const int p = (gc & 63) >> 1;
                const float f = g_invf[p];
                float angA = __fmul_rn(tpA, f);
                float angB = __fmul_rn(tpB, f);
                double dA = (double)angA;
                double rA = dA - floor(dA * 0.15915494309189535) * 6.283185307179586;
                double dB = (double)angB;
                double rB = dB - floor(dB * 0.15915494309189535) * 6.283185307179586;
                float sA = sinf((float)rA), cA = cosf((float)rA);
                float sB = sinf((float)rB), cB = cosf((float)rB);
                float t0 = x0 * cA - x1 * sA;
                float t1 = x1 * cA + x0 * sA;
                float u0 = y0 * cB - y1 * sB;
                float u1 = y1 * cB + y0 * sB;
                x0 = t0; x1 = t1; y0 = u0; y1 = u1;
            }
            const int hh = gc >> 6, d = gc & 63;
            if (csel == 0 || csel == 1) {   // Q or K -> single fp16
                if (csel == 0) { x0 *= 0.125f; x1 *= 0.125f;
                                 y0 *= 0.125f; y1 *= 0.125f; }
                __half* dst = (csel == 0) ? q2 : k2;
                *(uint32_t*)(dst + ((size_t)gmA * NHEADS + hh) * 64 + d) =
                    cvt_h2(x0, x1);
                *(uint32_t*)(dst + ((size_t)gmB * NHEADS + hh) * 64 + d) =
                    cvt_h2(y0, y1);
            } else if (csel == 2) {         // V -> single fp16
                *(uint32_t*)(v2 + (size_t)gmA * EMB + gc) = cvt_h2(x0, x1);
                *(uint32_t*)(v2 + (size_t)gmB * EMB + gc) = cvt_h2(y0, y1);
            } else {                        // final fp32 output
                *(float2*)(Cexp + (size_t)gmA * EMB + gc) = make_float2(x0, x1);
                *(float2*)(Cexp + (size_t)gmB * EMB + gc) = make_float2(y0, y1);
            }
        }
    }
#undef LOAD_CHUNK
}

// ---------------------------------------------------------------------------
// Banded flash attention, fp16 mma. Block = (64 queries, head, batch), 4 warps.
// QK^T: Qh.Kh (k=64). PV: Ph x Vh. Output -> Oh fp16 rows of a_at.
// ---------------------------------------------------------------------------
#define KPITCH 144   // 64 fp16 (128B) + 16B pad
#define SM_Q   0
#define SM_K   (64 * KPITCH)             // 9216
#define SM_V   (SM_K + 64 * KPITCH)      // 18432
#define SM_ATT (SM_V + 64 * KPITCH)      // 27648 bytes

__global__ __launch_bounds__(128) void attn_mma() {
    const int qt = blockIdx.x, h = blockIdx.y, b = blockIdx.z;
    const int t = threadIdx.x;
    const int wid = t >> 5, lane = t & 31;
    const int qbase = qt * 64;

    extern __shared__ char smraw[];
    char* smp = smraw;
    const uint32_t sb = smem_u32(smraw);

    // ---- load Qh tile (64 x 64 fp16) once ----
    for (int i = t; i < 64 * 8; i += 128) {
        int r = i >> 3, c = i & 7;
        const uint4* src = (const uint4*)(q2 +
            ((size_t)(b * T_SEQ + qbase + r) * NHEADS + h) * 64);
        *(uint4*)(smp + SM_Q + r * KPITCH + c * 16) = src[c];
    }

    float m0r = -3.0e38f, m1r = -3.0e38f, l0r = 0.0f, l1r = 0.0f;
    float o[8][4];
#pragma unroll
    for (int j = 0; j < 8; j++)
#pragma unroll
        for (int u = 0; u < 4; u++) o[j][u] = 0.0f;

    const int kt_lo = (qt - 4 > 0) ? (qt - 4) : 0;
    const int kt_hi = (qt + 4 < 31) ? (qt + 4) : 31;

    const int r0g = qbase + 16 * wid + (lane >> 2);
    const int coff = 2 * (lane & 3);

    for (int kt = kt_lo; kt <= kt_hi; kt++) {
        const int kbase = kt * 64;
        __syncthreads();
        for (int i = t; i < 64 * 8; i += 128) {
            int r = i >> 3, c = i & 7;
            const uint4* srck = (const uint4*)(k2 +
                ((size_t)(b * T_SEQ + kbase + r) * NHEADS + h) * 64);
            *(uint4*)(smp + SM_K + r * KPITCH + c * 16) = srck[c];
            size_t g = (size_t)(b * T_SEQ + kbase + r) * EMB + h * 64;
            *(uint4*)(smp + SM_V + r * KPITCH + c * 16) =
                ((const uint4*)(v2 + g))[c];
        }
        __syncthreads();

        float s[8][4];
#pragma unroll
        for (int j = 0; j < 8; j++)
#pragma unroll
            for (int u = 0; u < 4; u++) s[j][u] = 0.0f;

        const uint32_t aAddrBase = sb + SM_Q
            + (uint32_t)((16 * wid + (lane & 15)) * KPITCH + (lane >> 4) * 16);
        const int bRow = (lane & 7) + ((lane >> 4) << 3);
        const uint32_t bAddrBase = sb + SM_K
            + (uint32_t)(bRow * KPITCH + (((lane >> 3) & 1) << 4));

#pragma unroll
        for (int ks = 0; ks < 4; ks++) {
            uint32_t a0, a1, a2, a3;
            ldsm4(a0, a1, a2, a3, aAddrBase + ks * 32);
#pragma unroll
            for (int g = 0; g < 4; g++) {
                uint32_t b0, b1, b2, b3;
                ldsm4(b0, b1, b2, b3,
                      bAddrBase + (uint32_t)(g * 16 * KPITCH + ks * 32));
                mma16816(s[2 * g],     a0, a1, a2, a3, b0, b1);
                mma16816(s[2 * g + 1], a0, a1, a2, a3, b2, b3);
            }
        }

#pragma unroll
        for (int j = 0; j < 8; j++) {
            int c0 = kbase + 8 * j + coff;
            int d00 = r0g - c0, d01 = r0g - (c0 + 1);
            if (d00 > WHALF || d00 < -WHALF) s[j][0] = -1.0e30f;
            if (d01 > WHALF || d01 < -WHALF) s[j][1] = -1.0e30f;
            int d10 = d00 + 8, d11 = d01 + 8;
            if (d10 > WHALF || d10 < -WHALF) s[j][2] = -1.0e30f;
            if (d11 > WHALF || d11 < -WHALF) s[j][3] = -1.0e30f;
        }

        float mx0 = -1.0e30f, mx1 = -1.0e30f;
#pragma unroll
        for (int j = 0; j < 8; j++) {
            mx0 = fmaxf(mx0, fmaxf(s[j][0], s[j][1]));
            mx1 = fmaxf(mx1, fmaxf(s[j][2], s[j][3]));
        }
        mx0 = fmaxf(mx0, __shfl_xor_sync(0xffffffffu, mx0, 1));
        mx0 = fmaxf(mx0, __shfl_xor_sync(0xffffffffu, mx0, 2));
        mx1 = fmaxf(mx1, __shfl_xor_sync(0xffffffffu, mx1, 1));
        mx1 = fmaxf(mx1, __shfl_xor_sync(0xffffffffu, mx1, 2));
        float mn0 = fmaxf(m0r, mx0), mn1 = fmaxf(m1r, mx1);
        float cor0 = __expf(m0r - mn0), cor1 = __expf(m1r - mn1);
        m0r = mn0; m1r = mn1;

        float rs0 = 0.0f, rs1 = 0.0f;
#pragma unroll
        for (int j = 0; j < 8; j++) {
            s[j][0] = __expf(s[j][0] - mn0);
            s[j][1] = __expf(s[j][1] - mn0);
            s[j][2] = __expf(s[j][2] - mn1);
            s[j][3] = __expf(s[j][3] - mn1);
            rs0 += s[j][0] + s[j][1];
            rs1 += s[j][2] + s[j][3];
        }
        rs0 += __shfl_xor_sync(0xffffffffu, rs0, 1);
        rs0 += __shfl_xor_sync(0xffffffffu, rs0, 2);
        rs1 += __shfl_xor_sync(0xffffffffu, rs1, 1);
        rs1 += __shfl_xor_sync(0xffffffffu, rs1, 2);
        l0r = l0r * cor0 + rs0;
        l1r = l1r * cor1 + rs1;

#pragma unroll
        for (int j = 0; j < 8; j++) {
            o[j][0] *= cor0; o[j][1] *= cor0;
            o[j][2] *= cor1; o[j][3] *= cor1;
        }

        uint32_t ph[4][4];
#pragma unroll
        for (int ks2 = 0; ks2 < 4; ks2++) {
            int j0 = 2 * ks2, j1 = j0 + 1;
            ph[ks2][0] = cvt_h2(s[j0][0], s[j0][1]);
            ph[ks2][1] = cvt_h2(s[j0][2], s[j0][3]);
            ph[ks2][2] = cvt_h2(s[j1][0], s[j1][1]);
            ph[ks2][3] = cvt_h2(s[j1][2], s[j1][3]);
        }

        const uint32_t vAddrBase =
            (uint32_t)((lane & 15) * KPITCH + (lane >> 4) * 16);
#pragma unroll
        for (int ks2 = 0; ks2 < 4; ks2++) {
            uint32_t voff = vAddrBase + (uint32_t)(ks2 * 16 * KPITCH);
#pragma unroll
            for (int g = 0; g < 4; g++) {
                uint32_t v0, v1, v2r, v3;
                ldsm4t(v0, v1, v2r, v3, sb + SM_V + voff + g * 32);
                mma16816(o[2 * g],     ph[ks2][0], ph[ks2][1], ph[ks2][2],
                         ph[ks2][3], v0, v1);
                mma16816(o[2 * g + 1], ph[ks2][0], ph[ks2][1], ph[ks2][2],
                         ph[ks2][3], v2r, v3);
            }
        }
    }

    const float inv0 = 1.0f / l0r, inv1 = 1.0f / l1r;
    const size_t mA = (size_t)(b * T_SEQ) + qbase + 16 * wid + (lane >> 2);
    const size_t mB = mA + 8;
    __half* rowA = a_at + mA * EMB + h * 64 + coff;
    __half* rowB = a_at + mB * EMB + h * 64 + coff;
#pragma unroll
    for (int j = 0; j < 8; j++) {
        *(uint32_t*)(rowA + 8 * j) = cvt_h2(o[j][0] * inv0, o[j][1] * inv0);
        *(uint32_t*)(rowB + 8 * j) = cvt_h2(o[j][2] * inv1, o[j][3] * inv1);
    }
}

// ---------------------------------------------------------------------------
// Launch — 4 launches total
// ---------------------------------------------------------------------------
extern "C" void kernel_launch(void* const* d_in, const int* in_sizes, int n_in,
                              void* d_out, int out_size)
{
    const float* xq  = (const float*)d_in[0];
    const float* xkv = (const float*)d_in[1];
    const float* Wq  = (const float*)d_in[2];
    const float* Wk  = (const float*)d_in[3];
    const float* Wv  = (const float*)d_in[4];
    const float* Wo  = (const float*)d_in[5];
    float* out = (float*)d_out;

    // all conversions + invf table in one launch
    conv_all<<<dim3(32, 32, 6), 256>>>(xq, xkv, Wq, Wk, Wv, Wo);

    const int gemm_smem = NSTAGE * STG;   // 46080
    cudaFuncSetAttribute(mma_gemm, cudaFuncAttributeMaxDynamicSharedMemorySize,
                         gemm_smem);

    // Q, K, V projections fused into one launch (z = 0,1,2)
    mma_gemm<<<dim3(EMB / 64, MTOT / 128, 3), 128, gemm_smem>>>(nullptr, -1);

    cudaFuncSetAttribute(attn_mma, cudaFuncAttributeMaxDynamicSharedMemorySize,
                         SM_ATT);
    attn_mma<<<dim3(T_SEQ / 64, NHEADS, BATCH), 128, SM_ATT>>>();

    // O-projection
    mma_gemm<<<dim3(EMB / 64, MTOT / 128, 1), 128, gemm_smem>>>(out, 3);
}

// round 12
// speedup vs baseline: 6.6371x; 1.0322x over previous
#include <cuda_runtime.h>
#include <cuda_fp16.h>
#include <math.h>
#include <stdint.h>

#define BATCH   4
#define T_SEQ   2048
#define EMB     1024
#define NHEADS  16
#define HDIM    64
#define WHALF   256
#define MTOT    (BATCH * T_SEQ)      // 8192
#define BK      32
#define AROWB   80                   // padded row: 32 fp16 (64B) + 16B pad
#define ASTG    (128 * AROWB)        // A: 128 rows  -> 10240 B
#define BSTG    (64 * AROWB)         // B:  64 rows  ->  5120 B
#define STG     (ASTG + BSTG)        // 15360 B per stage
#define NSTAGE  3                    // 46080 B total

// ---------------------------------------------------------------------------
// Scratch (static device globals; cudaMalloc forbidden)
// ---------------------------------------------------------------------------
__device__ __half a_q [(size_t)MTOT * EMB];   // Xh
__device__ __half a_kv[(size_t)MTOT * EMB];
__device__ __half a_at[(size_t)MTOT * EMB];   // attn out Oh
__device__ __half w_q[EMB * EMB];             // Wh, [N][K] K-major
__device__ __half w_k[EMB * EMB];
__device__ __half w_v[EMB * EMB];
__device__ __half w_o[EMB * EMB];
// attention operands (single fp16)
__device__ __half q2[(size_t)MTOT * NHEADS * 64];   // [m][h][Qh] (x 1/8)
__device__ __half k2[(size_t)MTOT * NHEADS * 64];   // [m][h][Kh]
__device__ __half v2[(size_t)MTOT * EMB];           // [m][h*64+d] Vh
__device__ float g_invf[32];

// ---------------------------------------------------------------------------
// PTX helpers (sm_103 base ISA only)
// ---------------------------------------------------------------------------
__device__ __forceinline__ uint32_t smem_u32(const void* p) {
    uint32_t a;
    asm("{ .reg .u64 t; cvta.to.shared.u64 t, %1; cvt.u32.u64 %0, t; }"
        : "=r"(a) : "l"(p));
    return a;
}
__device__ __forceinline__ void cp16(uint32_t dst, const void* src) {
    asm volatile("cp.async.cg.shared.global [%0], [%1], 16;"
                 :: "r"(dst), "l"(src) : "memory");
}
__device__ __forceinline__ void cp_commit() {
    asm volatile("cp.async.commit_group;" ::: "memory");
}
__device__ __forceinline__ void ldsm4(uint32_t& r0, uint32_t& r1,
                                      uint32_t& r2, uint32_t& r3, uint32_t addr) {
    asm volatile("ldmatrix.sync.aligned.m8n8.x4.shared.b16 {%0,%1,%2,%3}, [%4];"
                 : "=r"(r0), "=r"(r1), "=r"(r2), "=r"(r3) : "r"(addr));
}
__device__ __forceinline__ void ldsm4t(uint32_t& r0, uint32_t& r1,
                                       uint32_t& r2, uint32_t& r3, uint32_t addr) {
    asm volatile("ldmatrix.sync.aligned.m8n8.x4.trans.shared.b16 {%0,%1,%2,%3}, [%4];"
                 : "=r"(r0), "=r"(r1), "=r"(r2), "=r"(r3) : "r"(addr));
}
__device__ __forceinline__ void mma16816(float* c, uint32_t a0, uint32_t a1,
                                         uint32_t a2, uint32_t a3,
                                         uint32_t b0, uint32_t b1) {
    asm volatile(
        "mma.sync.aligned.m16n8k16.row.col.f32.f16.f16.f32 "
        "{%0,%1,%2,%3}, {%4,%5,%6,%7}, {%8,%9}, {%0,%1,%2,%3};"
        : "+f"(c[0]), "+f"(c[1]), "+f"(c[2]), "+f"(c[3])
        : "r"(a0), "r"(a1), "r"(a2), "r"(a3), "r"(b0), "r"(b1));
}
__device__ __forceinline__ uint32_t pk_h2(__half a, __half b) {
    return (uint32_t)__half_as_ushort(a) |
           ((uint32_t)__half_as_ushort(b) << 16);
}
__device__ __forceinline__ uint32_t cvt_h2(float x0, float x1) {
    return pk_h2(__float2half_rn(x0), __float2half_rn(x1));
}

// ---------------------------------------------------------------------------
// Fused conversion kernel: grid (32, 32, 6), 256 threads.
// ---------------------------------------------------------------------------
__global__ __launch_bounds__(256) void conv_all(
    const float* __restrict__ Xq, const float* __restrict__ Xkv,
    const float* __restrict__ Wq, const float* __restrict__ Wk,
    const float* __restrict__ Wv, const float* __restrict__ Wo)
{
    const int z = blockIdx.z;
    const int t = threadIdx.x;

    if (z < 2) {
        const float* X = z ? Xkv : Xq;
        __half* A = z ? a_kv : a_q;
        const size_t n4 = (size_t)MTOT * EMB / 4;
        const size_t stride = (size_t)32 * 32 * 256;
        for (size_t i = (size_t)(blockIdx.y * 32 + blockIdx.x) * 256 + t;
             i < n4; i += stride) {
            float4 v = ((const float4*)X)[i];
            uint2 o;
            o.x = cvt_h2(v.x, v.y);
            o.y = cvt_h2(v.z, v.w);
            ((uint2*)A)[i] = o;
        }
        return;
    }

    const int w = z - 2;
    const float* W = (w == 0) ? Wq : (w == 1) ? Wk : (w == 2) ? Wv : Wo;
    __half* O = (w == 0) ? w_q : (w == 1) ? w_k : (w == 2) ? w_v : w_o;

    if (w == 0 && blockIdx.x == 0 && blockIdx.y == 0 && t < 32)
        g_invf[t] = (float)pow(10000.0, -(double)t / 32.0);

    __shared__ float tile[32][33];
    const int tx = t & 31, ty = t >> 5;
#pragma unroll
    for (int r = ty; r < 32; r += 8)
        tile[r][tx] = W[(size_t)(blockIdx.y * 32 + r) * EMB + blockIdx.x * 32 + tx];
    __syncthreads();
#pragma unroll
    for (int r = ty; r < 32; r += 8) {
        O[(size_t)(blockIdx.x * 32 + r) * EMB + blockIdx.y * 32 + tx] =
            __float2half_rn(tile[tx][r]);
    }
}

// ---------------------------------------------------------------------------
// mma.sync fp16 GEMM, 128x64 CTA tile, 4 warps (2x2 -> 64x32 warp tiles),
// BK=32, 3-stage cp.async, single barrier per chunk, 4 CTAs/SM.
// ---------------------------------------------------------------------------
__global__ __launch_bounds__(128) void mma_gemm(float* __restrict__ Cexp,
                                                int csel_in) {
    const int csel = (csel_in < 0) ? (int)blockIdx.z : csel_in;
    const int rotary = (csel <= 1);
    const __half* Ag = (csel == 0) ? a_q : (csel == 3) ? a_at : a_kv;
    const __half* Bg = (csel == 0) ? w_q : (csel == 1) ? w_k
                       : (csel == 2) ? w_v : w_o;
    const int nch = 32;

    extern __shared__ char smraw[];
    const uint32_t sb = smem_u32(smraw);
    const int t = threadIdx.x;
    const int wid = t >> 5, lane = t & 31;
    const int m0 = blockIdx.y * 128, n0 = blockIdx.x * 64;
    const int wm0 = (wid & 1) * 64;
    const int wn0 = (wid >> 1) * 32;

    const char* Ab = (const char*)(Ag + (size_t)m0 * EMB);
    const char* Bb = (const char*)(Bg + (size_t)n0 * EMB);

#define LOAD_CHUNK(c)                                                          \
    do {                                                                       \
        uint32_t _sa = sb + ((c) % NSTAGE) * STG;                              \
        uint32_t _sb2 = _sa + ASTG;                                            \
        _Pragma("unroll")                                                      \
        for (int _i = 0; _i < 4; _i++) {                                       \
            int _idx = t + _i * 128;                                           \
            int _row = _idx >> 2, _seg = _idx & 3;                             \
            size_t _g = (size_t)_row * (EMB * 2) + (size_t)(c) * 64            \
                        + _seg * 16;                                           \
            cp16(_sa + (uint32_t)(_row * AROWB + _seg * 16), Ab + _g);         \
        }                                                                      \
        _Pragma("unroll")                                                      \
        for (int _i = 0; _i < 2; _i++) {                                       \
            int _idx = t + _i * 128;                                           \
            int _row = _idx >> 2, _seg = _idx & 3;                             \
            size_t _g = (size_t)_row * (EMB * 2) + (size_t)(c) * 64            \
                        + _seg * 16;                                           \
            cp16(_sb2 + (uint32_t)(_row * AROWB + _seg * 16), Bb + _g);        \
        }                                                                      \
        cp_commit();                                                           \
    } while (0)

    float acc[4][4][4];
#pragma unroll
    for (int i = 0; i < 4; i++)
#pragma unroll
        for (int j = 0; j < 4; j++)
#pragma unroll
            for (int u = 0; u < 4; u++) acc[i][j][u] = 0.0f;

    LOAD_CHUNK(0);
    LOAD_CHUNK(1);

    const int lq = lane >> 3, lr = lane & 7;
    const int a_row = (lq & 1) * 8 + lr;
    const int a_cb  = (lq >> 1) * 16;
    const int b_row = (lq >> 1) * 8 + lr;
    const int b_cb  = (lq & 1) * 16;

    for (int c = 0; c < nch; c++) {
        if (c >= nch - 1) asm volatile("cp.async.wait_group 0;" ::: "memory");
        else              asm volatile("cp.async.wait_group 1;" ::: "memory");
        __syncthreads();
        if (c + 2 < nch) LOAD_CHUNK(c + 2);

        const uint32_t sa  = sb + (c % NSTAGE) * STG;
        const uint32_t sb2 = sa + ASTG;

#pragma unroll
        for (int ks = 0; ks < 2; ks++) {
            uint32_t af[4][4], bf[2][4];
#pragma unroll
            for (int i = 0; i < 4; i++)
                ldsm4(af[i][0], af[i][1], af[i][2], af[i][3],
                      sa + (uint32_t)((wm0 + i * 16 + a_row) * AROWB
                                      + ks * 32 + a_cb));
#pragma unroll
            for (int jp = 0; jp < 2; jp++)
                ldsm4(bf[jp][0], bf[jp][1], bf[jp][2], bf[jp][3],
                      sb2 + (uint32_t)((wn0 + jp * 16 + b_row) * AROWB
                                       + ks * 32 + b_cb));
#pragma unroll
            for (int i = 0; i < 4; i++)
#pragma unroll
                for (int j = 0; j < 4; j++)
                    mma16816(acc[i][j], af[i][0], af[i][1], af[i][2], af[i][3],
                             bf[j >> 1][(j & 1) * 2], bf[j >> 1][(j & 1) * 2 + 1]);
        }
    }

    // ---- epilogue ----
    const int mrow = lane >> 2;
    const int ncol = (lane & 3) * 2;
#pragma unroll
    for (int i = 0; i < 4; i++) {
        const int gmA = m0 + wm0 + i * 16 + mrow;
        const int gmB = gmA + 8;
        const float tpA = (float)(gmA & (T_SEQ - 1));
        const float tpB = (float)(gmB & (T_SEQ - 1));
#pragma unroll
        for (int j = 0; j < 4; j++) {
            const int gc = n0 + wn0 + j * 8 + ncol;
            float x0 = acc[i][j][0], x1 = acc[i][j][1];
            float y0 = acc[i][j][2], y1 = acc[i][j][3];
            if (rotary) {
                const int p = (gc & 63) >> 1;
                const float f = g_invf[p];
                float angA = __fmul_rn(tpA, f);
                float angB = __fmul_rn(tpB, f);
                double dA = (double)angA;
                double rA = dA - floor(dA * 0.15915494309189535) * 6.283185307179586;
                double dB = (double)angB;
                double rB = dB - floor(dB * 0.15915494309189535) * 6.283185307179586;
                float sA = sinf((float)rA), cA = cosf((float)rA);
                float sB = sinf((float)rB), cB = cosf((float)rB);
                float t0 = x0 * cA - x1 * sA;
                float t1 = x1 * cA + x0 * sA;
                float u0 = y0 * cB - y1 * sB;
                float u1 = y1 * cB + y0 * sB;
                x0 = t0; x1 = t1; y0 = u0; y1 = u1;
            }
            const int hh = gc >> 6, d = gc & 63;
            if (csel == 0 || csel == 1) {
                if (csel == 0) { x0 *= 0.125f; x1 *= 0.125f;
                                 y0 *= 0.125f; y1 *= 0.125f; }
                __half* dst = (csel == 0) ? q2 : k2;
                *(uint32_t*)(dst + ((size_t)gmA * NHEADS + hh) * 64 + d) =
                    cvt_h2(x0, x1);
                *(uint32_t*)(dst + ((size_t)gmB * NHEADS + hh) * 64 + d) =
                    cvt_h2(y0, y1);
            } else if (csel == 2) {
                *(uint32_t*)(v2 + (size_t)gmA * EMB + gc) = cvt_h2(x0, x1);
                *(uint32_t*)(v2 + (size_t)gmB * EMB + gc) = cvt_h2(y0, y1);
            } else {
                *(float2*)(Cexp + (size_t)gmA * EMB + gc) = make_float2(x0, x1);
                *(float2*)(Cexp + (size_t)gmB * EMB + gc) = make_float2(y0, y1);
            }
        }
    }
#undef LOAD_CHUNK
}

// ---------------------------------------------------------------------------
// Banded flash attention, fp16 mma, cp.async double-buffered K/V prefetch.
// Block = (64 queries, head, batch), 4 warps. One barrier per k-tile.
// ---------------------------------------------------------------------------
#define KPITCH 144                       // 64 fp16 (128B) + 16B pad
#define SM_Q    0                        // 64*144 = 9216
#define SM_KV0  9216                     // stage s at 9216 + s*18432
#define KVSTG   18432                    // K (9216) + V (9216)
#define SM_ATT  (9216 + 2 * KVSTG)       // 46080 bytes

__device__ __forceinline__ void attn_load_kv(uint32_t sb, int stage,
                                             int b, int kbase, int h, int t) {
    const uint32_t base = sb + SM_KV0 + stage * KVSTG;
#pragma unroll
    for (int i = 0; i < 4; i++) {
        int idx = t + i * 128;
        int r = idx >> 3, c = idx & 7;
        const char* ks = (const char*)(k2 +
            ((size_t)(b * T_SEQ + kbase + r) * NHEADS + h) * 64) + c * 16;
        const char* vs = (const char*)(v2 +
            (size_t)(b * T_SEQ + kbase + r) * EMB + h * 64) + c * 16;
        cp16(base + (uint32_t)(r * KPITCH + c * 16), ks);
        cp16(base + 9216u + (uint32_t)(r * KPITCH + c * 16), vs);
    }
    cp_commit();
}

__global__ __launch_bounds__(128) void attn_mma() {
    const int qt = blockIdx.x, h = blockIdx.y, b = blockIdx.z;
    const int t = threadIdx.x;
    const int wid = t >> 5, lane = t & 31;
    const int qbase = qt * 64;

    extern __shared__ char smraw[];
    const uint32_t sb = smem_u32(smraw);

    // ---- Q tile via cp.async (one group) ----
#pragma unroll
    for (int i = 0; i < 4; i++) {
        int idx = t + i * 128;
        int r = idx >> 3, c = idx & 7;
        const char* qs = (const char*)(q2 +
            ((size_t)(b * T_SEQ + qbase + r) * NHEADS + h) * 64) + c * 16;
        cp16(sb + SM_Q + (uint32_t)(r * KPITCH + c * 16), qs);
    }
    cp_commit();

    const int kt_lo = (qt - 4 > 0) ? (qt - 4) : 0;
    const int kt_hi = (qt + 4 < 31) ? (qt + 4) : 31;

    // prefetch first K/V tile
    attn_load_kv(sb, 0, b, kt_lo * 64, h, t);

    float m0r = -3.0e38f, m1r = -3.0e38f, l0r = 0.0f, l1r = 0.0f;
    float o[8][4];
#pragma unroll
    for (int j = 0; j < 8; j++)
#pragma unroll
        for (int u = 0; u < 4; u++) o[j][u] = 0.0f;

    const int r0g = qbase + 16 * wid + (lane >> 2);
    const int coff = 2 * (lane & 3);

    int stage = 0;
    for (int kt = kt_lo; kt <= kt_hi; kt++) {
        const int kbase = kt * 64;
        asm volatile("cp.async.wait_group 0;" ::: "memory");
        __syncthreads();   // tile (and Q on first iter) resident; prior reads done
        if (kt < kt_hi)
            attn_load_kv(sb, stage ^ 1, b, kbase + 64, h, t);

        const uint32_t smK = sb + SM_KV0 + stage * KVSTG;
        const uint32_t smV = smK + 9216u;

        // ---- S = Qh Kh^T (k = 64) ----
        float s[8][4];
#pragma unroll
        for (int j = 0; j < 8; j++)
#pragma unroll
            for (int u = 0; u < 4; u++) s[j][u] = 0.0f;

        const uint32_t aAddrBase = sb + SM_Q
            + (uint32_t)((16 * wid + (lane & 15)) * KPITCH + (lane >> 4) * 16);
        const int bRow = (lane & 7) + ((lane >> 4) << 3);
        const uint32_t bAddrBase = smK
            + (uint32_t)(bRow * KPITCH + (((lane >> 3) & 1) << 4));

#pragma unroll
        for (int ks = 0; ks < 4; ks++) {
            uint32_t a0, a1, a2, a3;
            ldsm4(a0, a1, a2, a3, aAddrBase + ks * 32);
#pragma unroll
            for (int g = 0; g < 4; g++) {
                uint32_t b0, b1, b2, b3;
                ldsm4(b0, b1, b2, b3,
                      bAddrBase + (uint32_t)(g * 16 * KPITCH + ks * 32));
                mma16816(s[2 * g],     a0, a1, a2, a3, b0, b1);
                mma16816(s[2 * g + 1], a0, a1, a2, a3, b2, b3);
            }
        }

        // ---- band mask ----
#pragma unroll
        for (int j = 0; j < 8; j++) {
            int c0 = kbase + 8 * j + coff;
            int d00 = r0g - c0, d01 = r0g - (c0 + 1);
            if (d00 > WHALF || d00 < -WHALF) s[j][0] = -1.0e30f;
            if (d01 > WHALF || d01 < -WHALF) s[j][1] = -1.0e30f;
            int d10 = d00 + 8, d11 = d01 + 8;
            if (d10 > WHALF || d10 < -WHALF) s[j][2] = -1.0e30f;
            if (d11 > WHALF || d11 < -WHALF) s[j][3] = -1.0e30f;
        }

        // ---- online softmax ----
        float mx0 = -1.0e30f, mx1 = -1.0e30f;
#pragma unroll
        for (int j = 0; j < 8; j++) {
            mx0 = fmaxf(mx0, fmaxf(s[j][0], s[j][1]));
            mx1 = fmaxf(mx1, fmaxf(s[j][2], s[j][3]));
        }
        mx0 = fmaxf(mx0, __shfl_xor_sync(0xffffffffu, mx0, 1));
        mx0 = fmaxf(mx0, __shfl_xor_sync(0xffffffffu, mx0, 2));
        mx1 = fmaxf(mx1, __shfl_xor_sync(0xffffffffu, mx1, 1));
        mx1 = fmaxf(mx1, __shfl_xor_sync(0xffffffffu, mx1, 2));
        float mn0 = fmaxf(m0r, mx0), mn1 = fmaxf(m1r, mx1);
        float cor0 = __expf(m0r - mn0), cor1 = __expf(m1r - mn1);
        m0r = mn0; m1r = mn1;

        float rs0 = 0.0f, rs1 = 0.0f;
#pragma unroll
        for (int j = 0; j < 8; j++) {
            s[j][0] = __expf(s[j][0] - mn0);
            s[j][1] = __expf(s[j][1] - mn0);
            s[j][2] = __expf(s[j][2] - mn1);
            s[j][3] = __expf(s[j][3] - mn1);
            rs0 += s[j][0] + s[j][1];
            rs1 += s[j][2] + s[j][3];
        }
        rs0 += __shfl_xor_sync(0xffffffffu, rs0, 1);
        rs0 += __shfl_xor_sync(0xffffffffu, rs0, 2);
        rs1 += __shfl_xor_sync(0xffffffffu, rs1, 1);
        rs1 += __shfl_xor_sync(0xffffffffu, rs1, 2);
        l0r = l0r * cor0 + rs0;
        l1r = l1r * cor1 + rs1;

#pragma unroll
        for (int j = 0; j < 8; j++) {
            o[j][0] *= cor0; o[j][1] *= cor0;
            o[j][2] *= cor1; o[j][3] *= cor1;
        }

        uint32_t ph[4][4];
#pragma unroll
        for (int ks2 = 0; ks2 < 4; ks2++) {
            int j0 = 2 * ks2, j1 = j0 + 1;
            ph[ks2][0] = cvt_h2(s[j0][0], s[j0][1]);
            ph[ks2][1] = cvt_h2(s[j0][2], s[j0][3]);
            ph[ks2][2] = cvt_h2(s[j1][0], s[j1][1]);
            ph[ks2][3] = cvt_h2(s[j1][2], s[j1][3]);
        }

        const uint32_t vAddrBase = smV
            + (uint32_t)((lane & 15) * KPITCH + (lane >> 4) * 16);
#pragma unroll
        for (int ks2 = 0; ks2 < 4; ks2++) {
            uint32_t voff = vAddrBase + (uint32_t)(ks2 * 16 * KPITCH);
#pragma unroll
            for (int g = 0; g < 4; g++) {
                uint32_t v0, v1, v2r, v3;
                ldsm4t(v0, v1, v2r, v3, voff + g * 32);
                mma16816(o[2 * g],     ph[ks2][0], ph[ks2][1], ph[ks2][2],
                         ph[ks2][3], v0, v1);
                mma16816(o[2 * g + 1], ph[ks2][0], ph[ks2][1], ph[ks2][2],
                         ph[ks2][3], v2r, v3);
            }
        }
        stage ^= 1;
    }

    const float inv0 = 1.0f / l0r, inv1 = 1.0f / l1r;
    const size_t mA = (size_t)(b * T_SEQ) + qbase + 16 * wid + (lane >> 2);
    const size_t mB = mA + 8;
    __half* rowA = a_at + mA * EMB + h * 64 + coff;
    __half* rowB = a_at + mB * EMB + h * 64 + coff;
#pragma unroll
    for (int j = 0; j < 8; j++) {
        *(uint32_t*)(rowA + 8 * j) = cvt_h2(o[j][0] * inv0, o[j][1] * inv0);
        *(uint32_t*)(rowB + 8 * j) = cvt_h2(o[j][2] * inv1, o[j][3] * inv1);
    }
}

// ---------------------------------------------------------------------------
// Launch — 4 launches total
// ---------------------------------------------------------------------------
extern "C" void kernel_launch(void* const* d_in, const int* in_sizes, int n_in,
                              void* d_out, int out_size)
{
    const float* xq  = (const float*)d_in[0];
    const float* xkv = (const float*)d_in[1];
    const float* Wq  = (const float*)d_in[2];
    const float* Wk  = (const float*)d_in[3];
    const float* Wv  = (const float*)d_in[4];
    const float* Wo  = (const float*)d_in[5];
    float* out = (float*)d_out;

    conv_all<<<dim3(32, 32, 6), 256>>>(xq, xkv, Wq, Wk, Wv, Wo);

    const int gemm_smem = NSTAGE * STG;   // 46080
    cudaFuncSetAttribute(mma_gemm, cudaFuncAttributeMaxDynamicSharedMemorySize,
                         gemm_smem);

    mma_gemm<<<dim3(EMB / 64, MTOT / 128, 3), 128, gemm_smem>>>(nullptr, -1);

    cudaFuncSetAttribute(attn_mma, cudaFuncAttributeMaxDynamicSharedMemorySize,
                         SM_ATT);
    attn_mma<<<dim3(T_SEQ / 64, NHEADS, BATCH), 128, SM_ATT>>>();

    mma_gemm<<<dim3(EMB / 64, MTOT / 128, 1), 128, gemm_smem>>>(out, 3);
}